// round 2
// baseline (speedup 1.0000x reference)
#include <cuda_runtime.h>
#include <math.h>

#define Bb 8
#define Ss 1024
#define Dd 1024
#define Hh 16
#define DKk 64

// Scratch: projected Q, K, V and attention output (pre-O-projection).
__device__ float g_Q[(size_t)Bb * Ss * Dd];
__device__ float g_K[(size_t)Bb * Ss * Dd];
__device__ float g_V[(size_t)Bb * Ss * Dd];
__device__ float g_AO[(size_t)Bb * Ss * Dd];

// ---------------------------------------------------------------------------
// Y[M,N] = X[M,K] @ W[N,K]^T + bias[N]     (M=8192, N=K=1024)
// 128x128 block tile, BK=16, 256 threads, 8x8 per-thread microtile.
// ---------------------------------------------------------------------------
__global__ __launch_bounds__(256) void gemm_bias(const float* __restrict__ X,
                                                 const float* __restrict__ W,
                                                 const float* __restrict__ bias,
                                                 float* __restrict__ Y) {
    const int K = 1024, N = 1024;
    __shared__ float As[16][128];
    __shared__ float Bs[16][128];

    const int tid  = threadIdx.x;
    const int tRow = tid >> 4;        // 0..15
    const int tCol = tid & 15;        // 0..15
    const int lRow = tid >> 2;        // 0..63
    const int lCol = (tid & 3) << 2;  // 0,4,8,12

    const float* Xb = X + (size_t)blockIdx.y * 128 * K;
    const float* Wb = W + (size_t)blockIdx.x * 128 * K;

    float acc[8][8];
#pragma unroll
    for (int i = 0; i < 8; i++)
#pragma unroll
        for (int j = 0; j < 8; j++) acc[i][j] = 0.0f;

    for (int k0 = 0; k0 < K; k0 += 16) {
#pragma unroll
        for (int r = 0; r < 128; r += 64) {
            float4 ta = *(const float4*)(Xb + (size_t)(lRow + r) * K + k0 + lCol);
            As[lCol + 0][lRow + r] = ta.x;
            As[lCol + 1][lRow + r] = ta.y;
            As[lCol + 2][lRow + r] = ta.z;
            As[lCol + 3][lRow + r] = ta.w;
            float4 tb = *(const float4*)(Wb + (size_t)(lRow + r) * K + k0 + lCol);
            Bs[lCol + 0][lRow + r] = tb.x;
            Bs[lCol + 1][lRow + r] = tb.y;
            Bs[lCol + 2][lRow + r] = tb.z;
            Bs[lCol + 3][lRow + r] = tb.w;
        }
        __syncthreads();

#pragma unroll
        for (int k = 0; k < 16; k++) {
            float4 a0 = *(const float4*)&As[k][tRow * 8];
            float4 a1 = *(const float4*)&As[k][tRow * 8 + 4];
            float4 b0 = *(const float4*)&Bs[k][tCol * 8];
            float4 b1 = *(const float4*)&Bs[k][tCol * 8 + 4];
            float a[8] = {a0.x, a0.y, a0.z, a0.w, a1.x, a1.y, a1.z, a1.w};
            float b[8] = {b0.x, b0.y, b0.z, b0.w, b1.x, b1.y, b1.z, b1.w};
#pragma unroll
            for (int i = 0; i < 8; i++)
#pragma unroll
                for (int j = 0; j < 8; j++) acc[i][j] += a[i] * b[j];
        }
        __syncthreads();
    }

    const int rowBase = blockIdx.y * 128 + tRow * 8;
    const int colBase = blockIdx.x * 128 + tCol * 8;
#pragma unroll
    for (int i = 0; i < 8; i++) {
#pragma unroll
        for (int j = 0; j < 8; j += 4) {
            float4 o;
            o.x = acc[i][j + 0] + bias[colBase + j + 0];
            o.y = acc[i][j + 1] + bias[colBase + j + 1];
            o.z = acc[i][j + 2] + bias[colBase + j + 2];
            o.w = acc[i][j + 3] + bias[colBase + j + 3];
            *(float4*)&Y[(size_t)(rowBase + i) * N + colBase + j] = o;
        }
    }
}

// ---------------------------------------------------------------------------
// Flash-style masked attention.
// Grid: (S/128, H, B). Block: 128 threads; thread t owns query row qt*128+t.
// q row (64 f32) and o accumulator (64 f32) live in registers. K/V tiles of
// 32 keys staged in smem (broadcast reads). Scores staged in padded smem.
// ---------------------------------------------------------------------------
__global__ __launch_bounds__(128) void attn_kernel(const float* __restrict__ Qm,
                                                   const float* __restrict__ Km,
                                                   const float* __restrict__ Vm,
                                                   const int* __restrict__ mask,
                                                   float* __restrict__ O) {
    const int qt = blockIdx.x, h = blockIdx.y, b = blockIdx.z;
    const int t = threadIdx.x;
    const int q = qt * 128 + t;

    __shared__ float Ks[32][64];
    __shared__ float Vs[32][64];
    __shared__ float Sc[128][33];  // padded: conflict-free per-row access

    float4 q4[16], o4[16];
    const float* qp = Qm + ((size_t)(b * Ss + q)) * Dd + h * DKk;
#pragma unroll
    for (int i = 0; i < 16; i++) {
        q4[i] = ((const float4*)qp)[i];
        o4[i] = make_float4(0.f, 0.f, 0.f, 0.f);
    }
    float m = -INFINITY, l = 0.0f;

    const int* mrow = mask + ((size_t)b * Ss + q) * Ss;  // mask[b][0][q][:]
    const int lr = t >> 2;          // 0..31 (key row for tile load)
    const int lc = (t & 3) * 16;    // 0,16,32,48

    for (int k0 = 0; k0 < Ss; k0 += 32) {
        // Cooperative K/V tile load: 32 keys x 64 dims.
        const float* kp = Km + ((size_t)(b * Ss + k0 + lr)) * Dd + h * DKk + lc;
        const float* vp = Vm + ((size_t)(b * Ss + k0 + lr)) * Dd + h * DKk + lc;
#pragma unroll
        for (int i = 0; i < 4; i++) {
            *(float4*)&Ks[lr][lc + 4 * i] = ((const float4*)kp)[i];
            *(float4*)&Vs[lr][lc + 4 * i] = ((const float4*)vp)[i];
        }
        __syncthreads();

        // Scores for this thread's query row against 32 keys.
        float tmax = -INFINITY;
#pragma unroll
        for (int jj = 0; jj < 8; jj++) {
            int4 mv = ((const int4*)(mrow + k0))[jj];
            float s[4];
#pragma unroll
            for (int u = 0; u < 4; u++) {
                const float4* kr = (const float4*)Ks[4 * jj + u];
                float4 a = make_float4(0.f, 0.f, 0.f, 0.f);
#pragma unroll
                for (int d = 0; d < 16; d++) {
                    float4 kv = kr[d];
                    a.x += q4[d].x * kv.x;
                    a.y += q4[d].y * kv.y;
                    a.z += q4[d].z * kv.z;
                    a.w += q4[d].w * kv.w;
                }
                s[u] = (a.x + a.y + a.z + a.w) * 0.125f;  // 1/sqrt(64)
            }
            if (mv.x == 0) s[0] = -1e9f;
            if (mv.y == 0) s[1] = -1e9f;
            if (mv.z == 0) s[2] = -1e9f;
            if (mv.w == 0) s[3] = -1e9f;
#pragma unroll
            for (int u = 0; u < 4; u++) {
                tmax = fmaxf(tmax, s[u]);
                Sc[t][4 * jj + u] = s[u];
            }
        }

        // Online softmax update.
        float mnew  = fmaxf(m, tmax);
        float alpha = __expf(m - mnew);  // m=-inf -> 0, zeroes empty state
        l *= alpha;
#pragma unroll
        for (int i = 0; i < 16; i++) {
            o4[i].x *= alpha; o4[i].y *= alpha;
            o4[i].z *= alpha; o4[i].w *= alpha;
        }

#pragma unroll 4
        for (int j = 0; j < 32; j++) {
            float p = __expf(Sc[t][j] - mnew);
            l += p;
            const float4* vr = (const float4*)Vs[j];
#pragma unroll
            for (int d = 0; d < 16; d++) {
                float4 vv = vr[d];
                o4[d].x += p * vv.x; o4[d].y += p * vv.y;
                o4[d].z += p * vv.z; o4[d].w += p * vv.w;
            }
        }
        m = mnew;
        __syncthreads();
    }

    const float inv = 1.0f / l;
    float* op = O + ((size_t)(b * Ss + q)) * Dd + h * DKk;
#pragma unroll
    for (int i = 0; i < 16; i++) {
        float4 o = o4[i];
        o.x *= inv; o.y *= inv; o.z *= inv; o.w *= inv;
        ((float4*)op)[i] = o;
    }
}

// ---------------------------------------------------------------------------
// Inputs (metadata order): q, k, v, mask, WQ_w, WQ_b, WK_w, WK_b,
//                          WV_w, WV_b, WO_w, WO_b
// ---------------------------------------------------------------------------
extern "C" void kernel_launch(void* const* d_in, const int* in_sizes, int n_in,
                              void* d_out, int out_size) {
    (void)in_sizes; (void)n_in; (void)out_size;

    const float* q    = (const float*)d_in[0];
    const float* k    = (const float*)d_in[1];
    const float* v    = (const float*)d_in[2];
    const int*   mask = (const int*)d_in[3];
    const float* WQw  = (const float*)d_in[4];
    const float* WQb  = (const float*)d_in[5];
    const float* WKw  = (const float*)d_in[6];
    const float* WKb  = (const float*)d_in[7];
    const float* WVw  = (const float*)d_in[8];
    const float* WVb  = (const float*)d_in[9];
    const float* WOw  = (const float*)d_in[10];
    const float* WOb  = (const float*)d_in[11];
    float* out = (float*)d_out;

    float *gQ, *gK, *gV, *gAO;
    cudaGetSymbolAddress((void**)&gQ, g_Q);
    cudaGetSymbolAddress((void**)&gK, g_K);
    cudaGetSymbolAddress((void**)&gV, g_V);
    cudaGetSymbolAddress((void**)&gAO, g_AO);

    dim3 gg(Dd / 128, (Bb * Ss) / 128);  // (8, 64)
    gemm_bias<<<gg, 256>>>(q, WQw, WQb, gQ);
    gemm_bias<<<gg, 256>>>(k, WKw, WKb, gK);
    gemm_bias<<<gg, 256>>>(v, WVw, WVb, gV);

    attn_kernel<<<dim3(Ss / 128, Hh, Bb), 128>>>(gQ, gK, gV, mask, gAO);

    gemm_bias<<<gg, 256>>>(gAO, WOw, WOb, out);
}

// round 4
// speedup vs baseline: 1.3752x; 1.3752x over previous
#include <cuda_runtime.h>
#include <cuda_bf16.h>
#include <math.h>
#include <cstdint>

#define Bb 8
#define Ss 1024
#define Dd 1024
#define Hh 16
#define DKk 64

// Scratch: projected Q, K, V and attention output (pre-O-projection).
__device__ float g_Q[(size_t)Bb * Ss * Dd];
__device__ float g_K[(size_t)Bb * Ss * Dd];
__device__ float g_V[(size_t)Bb * Ss * Dd];
__device__ float g_AO[(size_t)Bb * Ss * Dd];

// ---------------------------------------------------------------------------
// Tensor-core GEMM: Y[M,N] = X[M,K] @ W[N,K]^T + bias[N]  (M=8192,N=K=1024)
// bf16 split precision: X = Xh + Xl, W = Wh + Wl,
//   acc += Xh*Wh + Xh*Wl + Xl*Wh   (fp32 accum; dropped Xl*Wl ~ 2^-16)
// 128x128 block tile, BK=16, 256 threads, 8 warps of 32x64 warp tiles.
// ---------------------------------------------------------------------------

#define LDSM4(r0, r1, r2, r3, addr)                                          \
    asm volatile("ldmatrix.sync.aligned.m8n8.x4.shared.b16 {%0,%1,%2,%3}, [%4];" \
                 : "=r"(r0), "=r"(r1), "=r"(r2), "=r"(r3) : "r"(addr))

#define MMA16816(d, a0, a1, a2, a3, b0, b1)                                  \
    asm volatile(                                                            \
        "mma.sync.aligned.m16n8k16.row.col.f32.bf16.bf16.f32 "               \
        "{%0,%1,%2,%3}, {%4,%5,%6,%7}, {%8,%9}, {%0,%1,%2,%3};"              \
        : "+f"(d[0]), "+f"(d[1]), "+f"(d[2]), "+f"(d[3])                     \
        : "r"(a0), "r"(a1), "r"(a2), "r"(a3), "r"(b0), "r"(b1))

__device__ __forceinline__ void split_pack8(const float4& v0, const float4& v1,
                                            uint4& hi, uint4& lo) {
    float f[8] = {v0.x, v0.y, v0.z, v0.w, v1.x, v1.y, v1.z, v1.w};
    union { unsigned short u[8]; uint4 v; } ph, pl;
#pragma unroll
    for (int i = 0; i < 8; i++) {
        __nv_bfloat16 h = __float2bfloat16_rn(f[i]);
        __nv_bfloat16 l = __float2bfloat16_rn(f[i] - __bfloat162float(h));
        ph.u[i] = __bfloat16_as_ushort(h);
        pl.u[i] = __bfloat16_as_ushort(l);
    }
    hi = ph.v;
    lo = pl.v;
}

__global__ __launch_bounds__(256) void gemm_bias_tc(const float* __restrict__ X,
                                                    const float* __restrict__ W,
                                                    const float* __restrict__ bias,
                                                    float* __restrict__ Y) {
    const int K = 1024, N = 1024;
    // Padded row stride 24 halves (48B): conflict-free ldmatrix + 16B aligned.
    __shared__ __align__(16) __nv_bfloat16 Ah[128][24];
    __shared__ __align__(16) __nv_bfloat16 Al[128][24];
    __shared__ __align__(16) __nv_bfloat16 Bh[128][24];
    __shared__ __align__(16) __nv_bfloat16 Bl[128][24];

    const int tid  = threadIdx.x;
    const int lane = tid & 31;
    const int warp = tid >> 5;
    const int wm   = warp >> 1;  // 0..3 : m position (32 rows each)
    const int wn   = warp & 1;   // 0..1 : n position (64 cols each)

    // Global load assignment: 2 threads per row, 8 floats each.
    const int ldRow  = tid >> 1;
    const int ldHalf = tid & 1;  // k-offset 0 or 8

    const float* Xb = X + (size_t)(blockIdx.y * 128 + ldRow) * K + ldHalf * 8;
    const float* Wb = W + (size_t)(blockIdx.x * 128 + ldRow) * K + ldHalf * 8;

    // ldmatrix source addresses (constant across k-loop).
    uint32_t aAddrH[2], aAddrL[2], bAddrH[4], bAddrL[4];
#pragma unroll
    for (int mt = 0; mt < 2; mt++) {
        int r = wm * 32 + mt * 16 + (lane & 15);
        int c = (lane >> 4) * 8;
        aAddrH[mt] = (uint32_t)__cvta_generic_to_shared(&Ah[r][c]);
        aAddrL[mt] = (uint32_t)__cvta_generic_to_shared(&Al[r][c]);
    }
#pragma unroll
    for (int p = 0; p < 4; p++) {
        int r = wn * 64 + p * 16 + ((lane >> 4) << 3) + (lane & 7);
        int c = ((lane >> 3) & 1) * 8;
        bAddrH[p] = (uint32_t)__cvta_generic_to_shared(&Bh[r][c]);
        bAddrL[p] = (uint32_t)__cvta_generic_to_shared(&Bl[r][c]);
    }

    float acc[2][8][4];
#pragma unroll
    for (int mt = 0; mt < 2; mt++)
#pragma unroll
        for (int nt = 0; nt < 8; nt++)
#pragma unroll
            for (int i = 0; i < 4; i++) acc[mt][nt][i] = 0.0f;

    // Prefetch first k-tile into registers.
    float4 xr0 = ((const float4*)Xb)[0], xr1 = ((const float4*)Xb)[1];
    float4 wr0 = ((const float4*)Wb)[0], wr1 = ((const float4*)Wb)[1];

    for (int k0 = 0; k0 < K; k0 += 16) {
        // Convert + store current tile.
        uint4 hx, lx, hw, lw;
        split_pack8(xr0, xr1, hx, lx);
        split_pack8(wr0, wr1, hw, lw);
        *(uint4*)&Ah[ldRow][ldHalf * 8] = hx;
        *(uint4*)&Al[ldRow][ldHalf * 8] = lx;
        *(uint4*)&Bh[ldRow][ldHalf * 8] = hw;
        *(uint4*)&Bl[ldRow][ldHalf * 8] = lw;
        __syncthreads();

        // Prefetch next tile while doing MMAs.
        if (k0 + 16 < K) {
            xr0 = ((const float4*)(Xb + k0 + 16))[0];
            xr1 = ((const float4*)(Xb + k0 + 16))[1];
            wr0 = ((const float4*)(Wb + k0 + 16))[0];
            wr1 = ((const float4*)(Wb + k0 + 16))[1];
        }

        // Load all B fragments (hi and lo).
        uint32_t bh[4][4], bl[4][4];
#pragma unroll
        for (int p = 0; p < 4; p++) {
            LDSM4(bh[p][0], bh[p][1], bh[p][2], bh[p][3], bAddrH[p]);
            LDSM4(bl[p][0], bl[p][1], bl[p][2], bl[p][3], bAddrL[p]);
        }

#pragma unroll
        for (int mt = 0; mt < 2; mt++) {
            uint32_t ah[4], al[4];
            LDSM4(ah[0], ah[1], ah[2], ah[3], aAddrH[mt]);
            LDSM4(al[0], al[1], al[2], al[3], aAddrL[mt]);
            // hh pass
#pragma unroll
            for (int nt = 0; nt < 8; nt++)
                MMA16816(acc[mt][nt], ah[0], ah[1], ah[2], ah[3],
                         bh[nt >> 1][(nt & 1) * 2], bh[nt >> 1][(nt & 1) * 2 + 1]);
            // hl pass
#pragma unroll
            for (int nt = 0; nt < 8; nt++)
                MMA16816(acc[mt][nt], ah[0], ah[1], ah[2], ah[3],
                         bl[nt >> 1][(nt & 1) * 2], bl[nt >> 1][(nt & 1) * 2 + 1]);
            // lh pass
#pragma unroll
            for (int nt = 0; nt < 8; nt++)
                MMA16816(acc[mt][nt], al[0], al[1], al[2], al[3],
                         bh[nt >> 1][(nt & 1) * 2], bh[nt >> 1][(nt & 1) * 2 + 1]);
        }
        __syncthreads();
    }

    // Epilogue: c0,c1 -> (row, col..col+1); c2,c3 -> (row+8, ...)
    const int rowBase = blockIdx.y * 128 + wm * 32;
    const int colBase = blockIdx.x * 128 + wn * 64;
#pragma unroll
    for (int mt = 0; mt < 2; mt++) {
        int row = rowBase + mt * 16 + (lane >> 2);
#pragma unroll
        for (int nt = 0; nt < 8; nt++) {
            int col = colBase + nt * 8 + (lane & 3) * 2;
            float2 bv = *(const float2*)&bias[col];
            float2 o0 = make_float2(acc[mt][nt][0] + bv.x, acc[mt][nt][1] + bv.y);
            float2 o1 = make_float2(acc[mt][nt][2] + bv.x, acc[mt][nt][3] + bv.y);
            *(float2*)&Y[(size_t)row * N + col]       = o0;
            *(float2*)&Y[(size_t)(row + 8) * N + col] = o1;
        }
    }
}

// ---------------------------------------------------------------------------
// Flash-style masked attention (unchanged from R1).
// ---------------------------------------------------------------------------
__global__ __launch_bounds__(128) void attn_kernel(const float* __restrict__ Qm,
                                                   const float* __restrict__ Km,
                                                   const float* __restrict__ Vm,
                                                   const int* __restrict__ mask,
                                                   float* __restrict__ O) {
    const int qt = blockIdx.x, h = blockIdx.y, b = blockIdx.z;
    const int t = threadIdx.x;
    const int q = qt * 128 + t;

    __shared__ float Ks[32][64];
    __shared__ float Vs[32][64];
    __shared__ float Sc[128][33];

    float4 q4[16], o4[16];
    const float* qp = Qm + ((size_t)(b * Ss + q)) * Dd + h * DKk;
#pragma unroll
    for (int i = 0; i < 16; i++) {
        q4[i] = ((const float4*)qp)[i];
        o4[i] = make_float4(0.f, 0.f, 0.f, 0.f);
    }
    float m = -INFINITY, l = 0.0f;

    const int* mrow = mask + ((size_t)b * Ss + q) * Ss;
    const int lr = t >> 2;
    const int lc = (t & 3) * 16;

    for (int k0 = 0; k0 < Ss; k0 += 32) {
        const float* kp = Km + ((size_t)(b * Ss + k0 + lr)) * Dd + h * DKk + lc;
        const float* vp = Vm + ((size_t)(b * Ss + k0 + lr)) * Dd + h * DKk + lc;
#pragma unroll
        for (int i = 0; i < 4; i++) {
            *(float4*)&Ks[lr][lc + 4 * i] = ((const float4*)kp)[i];
            *(float4*)&Vs[lr][lc + 4 * i] = ((const float4*)vp)[i];
        }
        __syncthreads();

        float tmax = -INFINITY;
#pragma unroll
        for (int jj = 0; jj < 8; jj++) {
            int4 mv = ((const int4*)(mrow + k0))[jj];
            float s[4];
#pragma unroll
            for (int u = 0; u < 4; u++) {
                const float4* kr = (const float4*)Ks[4 * jj + u];
                float4 a = make_float4(0.f, 0.f, 0.f, 0.f);
#pragma unroll
                for (int d = 0; d < 16; d++) {
                    float4 kv = kr[d];
                    a.x += q4[d].x * kv.x;
                    a.y += q4[d].y * kv.y;
                    a.z += q4[d].z * kv.z;
                    a.w += q4[d].w * kv.w;
                }
                s[u] = (a.x + a.y + a.z + a.w) * 0.125f;
            }
            if (mv.x == 0) s[0] = -1e9f;
            if (mv.y == 0) s[1] = -1e9f;
            if (mv.z == 0) s[2] = -1e9f;
            if (mv.w == 0) s[3] = -1e9f;
#pragma unroll
            for (int u = 0; u < 4; u++) {
                tmax = fmaxf(tmax, s[u]);
                Sc[t][4 * jj + u] = s[u];
            }
        }

        float mnew  = fmaxf(m, tmax);
        float alpha = __expf(m - mnew);
        l *= alpha;
#pragma unroll
        for (int i = 0; i < 16; i++) {
            o4[i].x *= alpha; o4[i].y *= alpha;
            o4[i].z *= alpha; o4[i].w *= alpha;
        }

#pragma unroll 4
        for (int j = 0; j < 32; j++) {
            float p = __expf(Sc[t][j] - mnew);
            l += p;
            const float4* vr = (const float4*)Vs[j];
#pragma unroll
            for (int d = 0; d < 16; d++) {
                float4 vv = vr[d];
                o4[d].x += p * vv.x; o4[d].y += p * vv.y;
                o4[d].z += p * vv.z; o4[d].w += p * vv.w;
            }
        }
        m = mnew;
        __syncthreads();
    }

    const float inv = 1.0f / l;
    float* op = O + ((size_t)(b * Ss + q)) * Dd + h * DKk;
#pragma unroll
    for (int i = 0; i < 16; i++) {
        float4 o = o4[i];
        o.x *= inv; o.y *= inv; o.z *= inv; o.w *= inv;
        ((float4*)op)[i] = o;
    }
}

// ---------------------------------------------------------------------------
extern "C" void kernel_launch(void* const* d_in, const int* in_sizes, int n_in,
                              void* d_out, int out_size) {
    (void)in_sizes; (void)n_in; (void)out_size;

    const float* q    = (const float*)d_in[0];
    const float* k    = (const float*)d_in[1];
    const float* v    = (const float*)d_in[2];
    const int*   mask = (const int*)d_in[3];
    const float* WQw  = (const float*)d_in[4];
    const float* WQb  = (const float*)d_in[5];
    const float* WKw  = (const float*)d_in[6];
    const float* WKb  = (const float*)d_in[7];
    const float* WVw  = (const float*)d_in[8];
    const float* WVb  = (const float*)d_in[9];
    const float* WOw  = (const float*)d_in[10];
    const float* WOb  = (const float*)d_in[11];
    float* out = (float*)d_out;

    float *gQ, *gK, *gV, *gAO;
    cudaGetSymbolAddress((void**)&gQ, g_Q);
    cudaGetSymbolAddress((void**)&gK, g_K);
    cudaGetSymbolAddress((void**)&gV, g_V);
    cudaGetSymbolAddress((void**)&gAO, g_AO);

    dim3 gg(Dd / 128, (Bb * Ss) / 128);  // (8, 64)
    gemm_bias_tc<<<gg, 256>>>(q, WQw, WQb, gQ);
    gemm_bias_tc<<<gg, 256>>>(k, WKw, WKb, gK);
    gemm_bias_tc<<<gg, 256>>>(v, WVw, WVb, gV);

    attn_kernel<<<dim3(Ss / 128, Hh, Bb), 128>>>(gQ, gK, gV, mask, gAO);

    gemm_bias_tc<<<gg, 256>>>(gAO, WOw, WOb, out);
}

// round 5
// speedup vs baseline: 2.6228x; 1.9072x over previous
#include <cuda_runtime.h>
#include <cuda_bf16.h>
#include <math.h>
#include <cstdint>

#define Bb 8
#define Ss 1024
#define Dd 1024
#define Hh 16
#define DKk 64

// Scratch: split-bf16 projected Q/K/V, fp32 attention output, packed mask bits.
__device__ __nv_bfloat16 g_Qh[(size_t)Bb * Ss * Dd];
__device__ __nv_bfloat16 g_Ql[(size_t)Bb * Ss * Dd];
__device__ __nv_bfloat16 g_Kh[(size_t)Bb * Ss * Dd];
__device__ __nv_bfloat16 g_Kl[(size_t)Bb * Ss * Dd];
__device__ __nv_bfloat16 g_Vh[(size_t)Bb * Ss * Dd];
__device__ __nv_bfloat16 g_Vl[(size_t)Bb * Ss * Dd];
__device__ float g_AO[(size_t)Bb * Ss * Dd];
__device__ uint32_t g_mbits[(size_t)Bb * Ss * (Ss / 32)];

#define LDSM4(r0, r1, r2, r3, addr)                                          \
    asm volatile("ldmatrix.sync.aligned.m8n8.x4.shared.b16 {%0,%1,%2,%3}, [%4];" \
                 : "=r"(r0), "=r"(r1), "=r"(r2), "=r"(r3) : "r"(addr))

#define MMA16816(d, a0, a1, a2, a3, b0, b1)                                  \
    asm volatile(                                                            \
        "mma.sync.aligned.m16n8k16.row.col.f32.bf16.bf16.f32 "               \
        "{%0,%1,%2,%3}, {%4,%5,%6,%7}, {%8,%9}, {%0,%1,%2,%3};"              \
        : "+f"(d[0]), "+f"(d[1]), "+f"(d[2]), "+f"(d[3])                     \
        : "r"(a0), "r"(a1), "r"(a2), "r"(a3), "r"(b0), "r"(b1))

__device__ __forceinline__ void split_pack8(const float4& v0, const float4& v1,
                                            uint4& hi, uint4& lo) {
    float f[8] = {v0.x, v0.y, v0.z, v0.w, v1.x, v1.y, v1.z, v1.w};
    union { unsigned short u[8]; uint4 v; } ph, pl;
#pragma unroll
    for (int i = 0; i < 8; i++) {
        __nv_bfloat16 h = __float2bfloat16_rn(f[i]);
        __nv_bfloat16 l = __float2bfloat16_rn(f[i] - __bfloat162float(h));
        ph.u[i] = __bfloat16_as_ushort(h);
        pl.u[i] = __bfloat16_as_ushort(l);
    }
    hi = ph.v;
    lo = pl.v;
}

__device__ __forceinline__ uint32_t pack_bf2(float a, float b) {
    __nv_bfloat162 t = __floats2bfloat162_rn(a, b);  // .x = a (low half)
    return *(uint32_t*)&t;
}

// ---------------------------------------------------------------------------
// Shared GEMM mainloop body (macro-free duplication kept minimal via helper).
// Y = X[M,K] @ W[N,K]^T + bias. Split-bf16 3-pass MMA. Two epilogues:
// fp32 out (O projection) or split-bf16 out (Q/K/V projections).
// ---------------------------------------------------------------------------
template <int SPLIT_OUT>
__global__ __launch_bounds__(256) void gemm_bias_tc(const float* __restrict__ X,
                                                    const float* __restrict__ W,
                                                    const float* __restrict__ bias,
                                                    float* __restrict__ Y,
                                                    __nv_bfloat16* __restrict__ Yh,
                                                    __nv_bfloat16* __restrict__ Yl) {
    const int K = 1024, N = 1024;
    __shared__ __align__(16) __nv_bfloat16 Ah[128][24];
    __shared__ __align__(16) __nv_bfloat16 Al[128][24];
    __shared__ __align__(16) __nv_bfloat16 Bh[128][24];
    __shared__ __align__(16) __nv_bfloat16 Bl[128][24];

    const int tid  = threadIdx.x;
    const int lane = tid & 31;
    const int warp = tid >> 5;
    const int wm   = warp >> 1;
    const int wn   = warp & 1;

    const int ldRow  = tid >> 1;
    const int ldHalf = tid & 1;

    const float* Xb = X + (size_t)(blockIdx.y * 128 + ldRow) * K + ldHalf * 8;
    const float* Wb = W + (size_t)(blockIdx.x * 128 + ldRow) * K + ldHalf * 8;

    uint32_t aAddrH[2], aAddrL[2], bAddrH[4], bAddrL[4];
#pragma unroll
    for (int mt = 0; mt < 2; mt++) {
        int r = wm * 32 + mt * 16 + (lane & 15);
        int c = (lane >> 4) * 8;
        aAddrH[mt] = (uint32_t)__cvta_generic_to_shared(&Ah[r][c]);
        aAddrL[mt] = (uint32_t)__cvta_generic_to_shared(&Al[r][c]);
    }
#pragma unroll
    for (int p = 0; p < 4; p++) {
        int r = wn * 64 + p * 16 + ((lane >> 4) << 3) + (lane & 7);
        int c = ((lane >> 3) & 1) * 8;
        bAddrH[p] = (uint32_t)__cvta_generic_to_shared(&Bh[r][c]);
        bAddrL[p] = (uint32_t)__cvta_generic_to_shared(&Bl[r][c]);
    }

    float acc[2][8][4];
#pragma unroll
    for (int mt = 0; mt < 2; mt++)
#pragma unroll
        for (int nt = 0; nt < 8; nt++)
#pragma unroll
            for (int i = 0; i < 4; i++) acc[mt][nt][i] = 0.0f;

    float4 xr0 = ((const float4*)Xb)[0], xr1 = ((const float4*)Xb)[1];
    float4 wr0 = ((const float4*)Wb)[0], wr1 = ((const float4*)Wb)[1];

    for (int k0 = 0; k0 < K; k0 += 16) {
        uint4 hx, lx, hw, lw;
        split_pack8(xr0, xr1, hx, lx);
        split_pack8(wr0, wr1, hw, lw);
        *(uint4*)&Ah[ldRow][ldHalf * 8] = hx;
        *(uint4*)&Al[ldRow][ldHalf * 8] = lx;
        *(uint4*)&Bh[ldRow][ldHalf * 8] = hw;
        *(uint4*)&Bl[ldRow][ldHalf * 8] = lw;
        __syncthreads();

        if (k0 + 16 < K) {
            xr0 = ((const float4*)(Xb + k0 + 16))[0];
            xr1 = ((const float4*)(Xb + k0 + 16))[1];
            wr0 = ((const float4*)(Wb + k0 + 16))[0];
            wr1 = ((const float4*)(Wb + k0 + 16))[1];
        }

        uint32_t bh[4][4], bl[4][4];
#pragma unroll
        for (int p = 0; p < 4; p++) {
            LDSM4(bh[p][0], bh[p][1], bh[p][2], bh[p][3], bAddrH[p]);
            LDSM4(bl[p][0], bl[p][1], bl[p][2], bl[p][3], bAddrL[p]);
        }

#pragma unroll
        for (int mt = 0; mt < 2; mt++) {
            uint32_t ah[4], al[4];
            LDSM4(ah[0], ah[1], ah[2], ah[3], aAddrH[mt]);
            LDSM4(al[0], al[1], al[2], al[3], aAddrL[mt]);
#pragma unroll
            for (int nt = 0; nt < 8; nt++)
                MMA16816(acc[mt][nt], ah[0], ah[1], ah[2], ah[3],
                         bh[nt >> 1][(nt & 1) * 2], bh[nt >> 1][(nt & 1) * 2 + 1]);
#pragma unroll
            for (int nt = 0; nt < 8; nt++)
                MMA16816(acc[mt][nt], ah[0], ah[1], ah[2], ah[3],
                         bl[nt >> 1][(nt & 1) * 2], bl[nt >> 1][(nt & 1) * 2 + 1]);
#pragma unroll
            for (int nt = 0; nt < 8; nt++)
                MMA16816(acc[mt][nt], al[0], al[1], al[2], al[3],
                         bh[nt >> 1][(nt & 1) * 2], bh[nt >> 1][(nt & 1) * 2 + 1]);
        }
        __syncthreads();
    }

    const int rowBase = blockIdx.y * 128 + wm * 32;
    const int colBase = blockIdx.x * 128 + wn * 64;
#pragma unroll
    for (int mt = 0; mt < 2; mt++) {
        int row = rowBase + mt * 16 + (lane >> 2);
#pragma unroll
        for (int nt = 0; nt < 8; nt++) {
            int col = colBase + nt * 8 + (lane & 3) * 2;
            float2 bv = *(const float2*)&bias[col];
            float o00 = acc[mt][nt][0] + bv.x, o01 = acc[mt][nt][1] + bv.y;
            float o10 = acc[mt][nt][2] + bv.x, o11 = acc[mt][nt][3] + bv.y;
            if (SPLIT_OUT) {
                __nv_bfloat16 h00 = __float2bfloat16_rn(o00);
                __nv_bfloat16 h01 = __float2bfloat16_rn(o01);
                __nv_bfloat16 h10 = __float2bfloat16_rn(o10);
                __nv_bfloat16 h11 = __float2bfloat16_rn(o11);
                uint32_t ph0 = pack_bf2(o00, o01), ph1 = pack_bf2(o10, o11);
                uint32_t pl0 = pack_bf2(o00 - __bfloat162float(h00),
                                        o01 - __bfloat162float(h01));
                uint32_t pl1 = pack_bf2(o10 - __bfloat162float(h10),
                                        o11 - __bfloat162float(h11));
                // NB: pack_bf2 re-rounds; recompute hi exactly:
                *(uint32_t*)&Yh[(size_t)row * N + col]       = ph0;
                *(uint32_t*)&Yh[(size_t)(row + 8) * N + col] = ph1;
                *(uint32_t*)&Yl[(size_t)row * N + col]       = pl0;
                *(uint32_t*)&Yl[(size_t)(row + 8) * N + col] = pl1;
            } else {
                *(float2*)&Y[(size_t)row * N + col]       = make_float2(o00, o01);
                *(float2*)&Y[(size_t)(row + 8) * N + col] = make_float2(o10, o11);
            }
        }
    }
}

// ---------------------------------------------------------------------------
// Pack mask ints to bits: g_mbits[b][q][w] bit i = (mask[b][0][q][w*32+i] != 0)
// ---------------------------------------------------------------------------
__global__ void pack_mask(const int* __restrict__ mask, uint32_t* __restrict__ bits) {
    size_t w = (size_t)blockIdx.x * 256 + threadIdx.x;  // 262144 words
    const int* p = mask + w * 32;
    uint32_t v = 0;
#pragma unroll
    for (int i = 0; i < 32; i += 4) {
        int4 t = *(const int4*)(p + i);
        v |= (uint32_t)(t.x != 0) << i;
        v |= (uint32_t)(t.y != 0) << (i + 1);
        v |= (uint32_t)(t.z != 0) << (i + 2);
        v |= (uint32_t)(t.w != 0) << (i + 3);
    }
    bits[w] = v;
}

// ---------------------------------------------------------------------------
// Tensor-core flash attention.
// Block = 128 q-rows x one (b,h). 8 warps, each m16. KV tiles of 64 keys.
// QK^T and P.V both split-bf16 (3 MMA passes). Online softmax in registers,
// exp2f with scale folded, mask via packed bits.
// ---------------------------------------------------------------------------
struct QStage { __nv_bfloat16 h[128][72], l[128][72]; };
struct KVStage {
    __nv_bfloat16 kh[64][72], kl[64][72];
    __nv_bfloat16 vth[64][72], vtl[64][72];  // transposed: [dim][key]
    uint32_t mw[128][2];
};

__global__ __launch_bounds__(256, 1) void attn_tc(
    const __nv_bfloat16* __restrict__ Qh, const __nv_bfloat16* __restrict__ Ql,
    const __nv_bfloat16* __restrict__ Kh, const __nv_bfloat16* __restrict__ Kl,
    const __nv_bfloat16* __restrict__ Vh, const __nv_bfloat16* __restrict__ Vl,
    const uint32_t* __restrict__ mbits, float* __restrict__ O) {
    const int qt = blockIdx.x, h = blockIdx.y, b = blockIdx.z;
    const int tid = threadIdx.x, lane = tid & 31, warp = tid >> 5;
    const float SC = 0.125f * 1.44269504f;  // 1/sqrt(64) * log2(e)

    __shared__ union { QStage q; KVStage kv; } sm;

    const size_t qrow0 = (size_t)b * Ss + qt * 128;

    // ---- Stage Q tile, ldmatrix Q fragments to registers.
    {
        int r = tid >> 1, half = tid & 1;  // 2 threads/row, 32 halves each
        const uint4* gh = (const uint4*)(Qh + (qrow0 + r) * Dd + h * 64 + half * 32);
        const uint4* gl = (const uint4*)(Ql + (qrow0 + r) * Dd + h * 64 + half * 32);
        uint4* sh = (uint4*)&sm.q.h[r][half * 32];
        uint4* sl = (uint4*)&sm.q.l[r][half * 32];
#pragma unroll
        for (int i = 0; i < 4; i++) { sh[i] = gh[i]; sl[i] = gl[i]; }
    }
    __syncthreads();

    uint32_t qfh[4][4], qfl[4][4];
    {
        uint32_t bqh = (uint32_t)__cvta_generic_to_shared(&sm.q.h[0][0]);
        uint32_t bql = (uint32_t)__cvta_generic_to_shared(&sm.q.l[0][0]);
        int r = warp * 16 + (lane & 15);
#pragma unroll
        for (int s = 0; s < 4; s++) {
            uint32_t off = (uint32_t)((r * 72 + s * 16 + (lane >> 4) * 8) * 2);
            LDSM4(qfh[s][0], qfh[s][1], qfh[s][2], qfh[s][3], bqh + off);
            LDSM4(qfl[s][0], qfl[s][1], qfl[s][2], qfl[s][3], bql + off);
        }
    }
    __syncthreads();

    float oacc[8][4];
#pragma unroll
    for (int nt = 0; nt < 8; nt++)
#pragma unroll
        for (int i = 0; i < 4; i++) oacc[nt][i] = 0.0f;
    float m1 = -1e30f, m2 = -1e30f, l1 = 0.0f, l2 = 0.0f;

    const int rb = ((lane >> 4) << 3) + (lane & 7);   // ldsm B row part
    const int cb = ((lane >> 3) & 1) * 8;             // ldsm B col part
    const int r1 = lane >> 2;                          // fragment row in warp tile

    for (int kt = 0; kt < 16; kt++) {
        // ---- Load K (straight) and V (transposed) tiles + mask words.
        {
            int r = tid >> 2, qtr = tid & 3;  // 4 threads/row, 16 halves each
            size_t g = ((size_t)b * Ss + kt * 64 + r) * Dd + h * 64 + qtr * 16;
            *(uint4*)&sm.kv.kh[r][qtr * 16]     = *(const uint4*)(Kh + g);
            *(uint4*)&sm.kv.kh[r][qtr * 16 + 8] = *(const uint4*)(Kh + g + 8);
            *(uint4*)&sm.kv.kl[r][qtr * 16]     = *(const uint4*)(Kl + g);
            *(uint4*)&sm.kv.kl[r][qtr * 16 + 8] = *(const uint4*)(Kl + g + 8);
            union { uint4 v[2]; __nv_bfloat16 e[16]; } th, tl;
            th.v[0] = *(const uint4*)(Vh + g); th.v[1] = *(const uint4*)(Vh + g + 8);
            tl.v[0] = *(const uint4*)(Vl + g); tl.v[1] = *(const uint4*)(Vl + g + 8);
#pragma unroll
            for (int i = 0; i < 16; i++) {
                sm.kv.vth[qtr * 16 + i][r] = th.e[i];
                sm.kv.vtl[qtr * 16 + i][r] = tl.e[i];
            }
            int mr = tid >> 1, mwsel = tid & 1;
            sm.kv.mw[mr][mwsel] = mbits[(qrow0 + mr) * 32 + kt * 2 + mwsel];
        }
        __syncthreads();

        // ---- S = Q K^T (split, 3 passes), fp32 accum.
        float sacc[8][4];
#pragma unroll
        for (int nt = 0; nt < 8; nt++)
#pragma unroll
            for (int i = 0; i < 4; i++) sacc[nt][i] = 0.0f;
        {
            uint32_t kbh = (uint32_t)__cvta_generic_to_shared(&sm.kv.kh[0][0]);
            uint32_t kbl = (uint32_t)__cvta_generic_to_shared(&sm.kv.kl[0][0]);
#pragma unroll
            for (int s = 0; s < 4; s++) {
                uint32_t bh[8][2], bl[8][2];
#pragma unroll
                for (int p = 0; p < 4; p++) {
                    uint32_t off = (uint32_t)(((p * 16 + rb) * 72 + s * 16 + cb) * 2);
                    LDSM4(bh[2 * p][0], bh[2 * p][1], bh[2 * p + 1][0], bh[2 * p + 1][1], kbh + off);
                    LDSM4(bl[2 * p][0], bl[2 * p][1], bl[2 * p + 1][0], bl[2 * p + 1][1], kbl + off);
                }
#pragma unroll
                for (int nt = 0; nt < 8; nt++) {
                    MMA16816(sacc[nt], qfh[s][0], qfh[s][1], qfh[s][2], qfh[s][3], bh[nt][0], bh[nt][1]);
                    MMA16816(sacc[nt], qfh[s][0], qfh[s][1], qfh[s][2], qfh[s][3], bl[nt][0], bl[nt][1]);
                    MMA16816(sacc[nt], qfl[s][0], qfl[s][1], qfl[s][2], qfl[s][3], bh[nt][0], bh[nt][1]);
                }
            }
        }

        // ---- Scale, mask, row max.
        uint32_t w10 = sm.kv.mw[warp * 16 + r1][0];
        uint32_t w11 = sm.kv.mw[warp * 16 + r1][1];
        uint32_t w20 = sm.kv.mw[warp * 16 + r1 + 8][0];
        uint32_t w21 = sm.kv.mw[warp * 16 + r1 + 8][1];
        float tm1 = -1e30f, tm2 = -1e30f;
#pragma unroll
        for (int nt = 0; nt < 8; nt++) {
            int cbase = nt * 8 + (lane & 3) * 2;
            uint32_t wA = (nt < 4) ? w10 : w11;
            uint32_t wB = (nt < 4) ? w20 : w21;
            int shf = cbase & 31;
            float s0 = sacc[nt][0] * SC, s1 = sacc[nt][1] * SC;
            float s2 = sacc[nt][2] * SC, s3 = sacc[nt][3] * SC;
            if (!((wA >> shf) & 1))       s0 = -1e9f;
            if (!((wA >> (shf + 1)) & 1)) s1 = -1e9f;
            if (!((wB >> shf) & 1))       s2 = -1e9f;
            if (!((wB >> (shf + 1)) & 1)) s3 = -1e9f;
            sacc[nt][0] = s0; sacc[nt][1] = s1; sacc[nt][2] = s2; sacc[nt][3] = s3;
            tm1 = fmaxf(tm1, fmaxf(s0, s1));
            tm2 = fmaxf(tm2, fmaxf(s2, s3));
        }
        tm1 = fmaxf(tm1, __shfl_xor_sync(0xffffffff, tm1, 1));
        tm1 = fmaxf(tm1, __shfl_xor_sync(0xffffffff, tm1, 2));
        tm2 = fmaxf(tm2, __shfl_xor_sync(0xffffffff, tm2, 1));
        tm2 = fmaxf(tm2, __shfl_xor_sync(0xffffffff, tm2, 2));

        float mn1 = fmaxf(m1, tm1), mn2 = fmaxf(m2, tm2);
        float a1 = exp2f(m1 - mn1), a2 = exp2f(m2 - mn2);
        m1 = mn1; m2 = mn2;
        l1 *= a1; l2 *= a2;
#pragma unroll
        for (int nt = 0; nt < 8; nt++) {
            oacc[nt][0] *= a1; oacc[nt][1] *= a1;
            oacc[nt][2] *= a2; oacc[nt][3] *= a2;
        }

        // ---- p = exp2(s - m); split to hi/lo; pack as A fragments.
        uint32_t pah[4][4], pal[4][4];
#pragma unroll
        for (int nt = 0; nt < 8; nt++) {
            float p0 = exp2f(sacc[nt][0] - m1), p1 = exp2f(sacc[nt][1] - m1);
            float p2 = exp2f(sacc[nt][2] - m2), p3 = exp2f(sacc[nt][3] - m2);
            l1 += p0 + p1; l2 += p2 + p3;
            __nv_bfloat16 h0 = __float2bfloat16_rn(p0), h1 = __float2bfloat16_rn(p1);
            __nv_bfloat16 h2 = __float2bfloat16_rn(p2), h3 = __float2bfloat16_rn(p3);
            int s = nt >> 1, base = (nt & 1) * 2;
            pah[s][base]     = pack_bf2(p0, p1);
            pah[s][base + 1] = pack_bf2(p2, p3);
            pal[s][base]     = pack_bf2(p0 - __bfloat162float(h0), p1 - __bfloat162float(h1));
            pal[s][base + 1] = pack_bf2(p2 - __bfloat162float(h2), p3 - __bfloat162float(h3));
        }

        // ---- O += P V (split, 3 passes).
        {
            uint32_t vbh = (uint32_t)__cvta_generic_to_shared(&sm.kv.vth[0][0]);
            uint32_t vbl = (uint32_t)__cvta_generic_to_shared(&sm.kv.vtl[0][0]);
#pragma unroll
            for (int s = 0; s < 4; s++) {
                uint32_t bh[8][2], bl[8][2];
#pragma unroll
                for (int p = 0; p < 4; p++) {
                    uint32_t off = (uint32_t)(((p * 16 + rb) * 72 + s * 16 + cb) * 2);
                    LDSM4(bh[2 * p][0], bh[2 * p][1], bh[2 * p + 1][0], bh[2 * p + 1][1], vbh + off);
                    LDSM4(bl[2 * p][0], bl[2 * p][1], bl[2 * p + 1][0], bl[2 * p + 1][1], vbl + off);
                }
#pragma unroll
                for (int dt = 0; dt < 8; dt++) {
                    MMA16816(oacc[dt], pah[s][0], pah[s][1], pah[s][2], pah[s][3], bh[dt][0], bh[dt][1]);
                    MMA16816(oacc[dt], pah[s][0], pah[s][1], pah[s][2], pah[s][3], bl[dt][0], bl[dt][1]);
                    MMA16816(oacc[dt], pal[s][0], pal[s][1], pal[s][2], pal[s][3], bh[dt][0], bh[dt][1]);
                }
            }
        }
        __syncthreads();
    }

    // ---- Finalize: full row sums, normalize, store.
    l1 += __shfl_xor_sync(0xffffffff, l1, 1);
    l1 += __shfl_xor_sync(0xffffffff, l1, 2);
    l2 += __shfl_xor_sync(0xffffffff, l2, 1);
    l2 += __shfl_xor_sync(0xffffffff, l2, 2);
    float inv1 = 1.0f / l1, inv2 = 1.0f / l2;

    size_t row1 = qrow0 + warp * 16 + r1;
#pragma unroll
    for (int nt = 0; nt < 8; nt++) {
        int col = h * 64 + nt * 8 + (lane & 3) * 2;
        *(float2*)&O[row1 * Dd + col] =
            make_float2(oacc[nt][0] * inv1, oacc[nt][1] * inv1);
        *(float2*)&O[(row1 + 8) * Dd + col] =
            make_float2(oacc[nt][2] * inv2, oacc[nt][3] * inv2);
    }
}

// ---------------------------------------------------------------------------
extern "C" void kernel_launch(void* const* d_in, const int* in_sizes, int n_in,
                              void* d_out, int out_size) {
    (void)in_sizes; (void)n_in; (void)out_size;

    const float* q    = (const float*)d_in[0];
    const float* k    = (const float*)d_in[1];
    const float* v    = (const float*)d_in[2];
    const int*   mask = (const int*)d_in[3];
    const float* WQw  = (const float*)d_in[4];
    const float* WQb  = (const float*)d_in[5];
    const float* WKw  = (const float*)d_in[6];
    const float* WKb  = (const float*)d_in[7];
    const float* WVw  = (const float*)d_in[8];
    const float* WVb  = (const float*)d_in[9];
    const float* WOw  = (const float*)d_in[10];
    const float* WOb  = (const float*)d_in[11];
    float* out = (float*)d_out;

    __nv_bfloat16 *gQh, *gQl, *gKh, *gKl, *gVh, *gVl;
    float* gAO; uint32_t* gMb;
    cudaGetSymbolAddress((void**)&gQh, g_Qh);
    cudaGetSymbolAddress((void**)&gQl, g_Ql);
    cudaGetSymbolAddress((void**)&gKh, g_Kh);
    cudaGetSymbolAddress((void**)&gKl, g_Kl);
    cudaGetSymbolAddress((void**)&gVh, g_Vh);
    cudaGetSymbolAddress((void**)&gVl, g_Vl);
    cudaGetSymbolAddress((void**)&gAO, g_AO);
    cudaGetSymbolAddress((void**)&gMb, g_mbits);

    pack_mask<<<(Bb * Ss * (Ss / 32)) / 256, 256>>>(mask, gMb);

    dim3 gg(Dd / 128, (Bb * Ss) / 128);  // (8, 64)
    gemm_bias_tc<1><<<gg, 256>>>(q, WQw, WQb, nullptr, gQh, gQl);
    gemm_bias_tc<1><<<gg, 256>>>(k, WKw, WKb, nullptr, gKh, gKl);
    gemm_bias_tc<1><<<gg, 256>>>(v, WVw, WVb, nullptr, gVh, gVl);

    attn_tc<<<dim3(Ss / 128, Hh, Bb), 256>>>(gQh, gQl, gKh, gKl, gVh, gVl, gMb, gAO);

    gemm_bias_tc<0><<<gg, 256>>>(gAO, WOw, WOb, out, nullptr, nullptr);
}

// round 6
// speedup vs baseline: 2.6332x; 1.0040x over previous
#include <cuda_runtime.h>
#include <cuda_bf16.h>
#include <math.h>
#include <cstdint>

#define Bb 8
#define Ss 1024
#define Dd 1024
#define Hh 16
#define DKk 64

// ---- Scratch (all split bf16 hi/lo) ----
__device__ __nv_bfloat16 g_qh[(size_t)Bb * Ss * Dd], g_ql[(size_t)Bb * Ss * Dd];
__device__ __nv_bfloat16 g_kh[(size_t)Bb * Ss * Dd], g_kl[(size_t)Bb * Ss * Dd];
__device__ __nv_bfloat16 g_vh[(size_t)Bb * Ss * Dd], g_vl[(size_t)Bb * Ss * Dd];
__device__ __nv_bfloat16 g_Qh[(size_t)Bb * Ss * Dd], g_Ql[(size_t)Bb * Ss * Dd];
__device__ __nv_bfloat16 g_Kh[(size_t)Bb * Ss * Dd], g_Kl[(size_t)Bb * Ss * Dd];
__device__ __nv_bfloat16 g_Vh[(size_t)Bb * Ss * Dd], g_Vl[(size_t)Bb * Ss * Dd];
__device__ __nv_bfloat16 g_AOh[(size_t)Bb * Ss * Dd], g_AOl[(size_t)Bb * Ss * Dd];
__device__ __nv_bfloat16 g_WQh[Dd * Dd], g_WQl[Dd * Dd];
__device__ __nv_bfloat16 g_WKh[Dd * Dd], g_WKl[Dd * Dd];
__device__ __nv_bfloat16 g_WVh[Dd * Dd], g_WVl[Dd * Dd];
__device__ __nv_bfloat16 g_WOh[Dd * Dd], g_WOl[Dd * Dd];
__device__ uint32_t g_mbits[(size_t)Bb * Ss * (Ss / 32)];

#define LDSM4(r0, r1, r2, r3, addr)                                          \
    asm volatile("ldmatrix.sync.aligned.m8n8.x4.shared.b16 {%0,%1,%2,%3}, [%4];" \
                 : "=r"(r0), "=r"(r1), "=r"(r2), "=r"(r3) : "r"(addr))

#define MMA16816(d, a0, a1, a2, a3, b0, b1)                                  \
    asm volatile(                                                            \
        "mma.sync.aligned.m16n8k16.row.col.f32.bf16.bf16.f32 "               \
        "{%0,%1,%2,%3}, {%4,%5,%6,%7}, {%8,%9}, {%0,%1,%2,%3};"              \
        : "+f"(d[0]), "+f"(d[1]), "+f"(d[2]), "+f"(d[3])                     \
        : "r"(a0), "r"(a1), "r"(a2), "r"(a3), "r"(b0), "r"(b1))

#define CP16(dst, src)                                                       \
    asm volatile("cp.async.cg.shared.global [%0], [%1], 16;" ::"r"(dst), "l"(src))
#define CP_COMMIT asm volatile("cp.async.commit_group;")
#define CP_WAIT1  asm volatile("cp.async.wait_group 1;")

__device__ __forceinline__ uint32_t pack_bf2(float a, float b) {
    __nv_bfloat162 t = __floats2bfloat162_rn(a, b);
    return *(uint32_t*)&t;
}

// ---------------------------------------------------------------------------
// Elementwise fp32 -> split bf16 (hi = rn(x), lo = rn(x - hi)).
// ---------------------------------------------------------------------------
__global__ void split_f32(const float* __restrict__ in,
                          __nv_bfloat16* __restrict__ hi,
                          __nv_bfloat16* __restrict__ lo) {
    size_t i = ((size_t)blockIdx.x * 256 + threadIdx.x) * 4;
    float4 v = *(const float4*)(in + i);
    float r0 = v.x - __bfloat162float(__float2bfloat16_rn(v.x));
    float r1 = v.y - __bfloat162float(__float2bfloat16_rn(v.y));
    float r2 = v.z - __bfloat162float(__float2bfloat16_rn(v.z));
    float r3 = v.w - __bfloat162float(__float2bfloat16_rn(v.w));
    uint2 ph = make_uint2(pack_bf2(v.x, v.y), pack_bf2(v.z, v.w));
    uint2 pl = make_uint2(pack_bf2(r0, r1), pack_bf2(r2, r3));
    *(uint2*)(hi + i) = ph;
    *(uint2*)(lo + i) = pl;
}

// ---------------------------------------------------------------------------
// Mask ints -> bit words.
// ---------------------------------------------------------------------------
__global__ void pack_mask(const int* __restrict__ mask, uint32_t* __restrict__ bits) {
    size_t w = (size_t)blockIdx.x * 256 + threadIdx.x;
    const int* p = mask + w * 32;
    uint32_t v = 0;
#pragma unroll
    for (int i = 0; i < 32; i += 4) {
        int4 t = *(const int4*)(p + i);
        v |= (uint32_t)(t.x != 0) << i;
        v |= (uint32_t)(t.y != 0) << (i + 1);
        v |= (uint32_t)(t.z != 0) << (i + 2);
        v |= (uint32_t)(t.w != 0) << (i + 3);
    }
    bits[w] = v;
}

// ---------------------------------------------------------------------------
// Pipelined split-bf16 GEMM: Y = A[M,K] @ B[N,K]^T + bias.
// A,B pre-split (hi/lo bf16). 3-stage cp.async, BK=32, 128x128 tile, 256 thr.
// ---------------------------------------------------------------------------
struct GStage {
    __nv_bfloat16 ah[128][40];
    __nv_bfloat16 al[128][40];
    __nv_bfloat16 bh[128][40];
    __nv_bfloat16 bl[128][40];
};
#define NSTAGE 3
#define AH_OFF 0
#define AL_OFF 10240
#define BH_OFF 20480
#define BL_OFF 30720

template <int SPLIT_OUT>
__global__ __launch_bounds__(256) void gemm_sp(
    const __nv_bfloat16* __restrict__ Ahg, const __nv_bfloat16* __restrict__ Alg,
    const __nv_bfloat16* __restrict__ Bhg, const __nv_bfloat16* __restrict__ Blg,
    const float* __restrict__ bias, float* __restrict__ Y,
    __nv_bfloat16* __restrict__ Yh, __nv_bfloat16* __restrict__ Yl) {
    const int K = 1024, N = 1024;
    extern __shared__ char smem_raw[];
    const uint32_t smem_base = (uint32_t)__cvta_generic_to_shared(smem_raw);

    const int tid  = threadIdx.x;
    const int lane = tid & 31;
    const int warp = tid >> 5;
    const int wm   = warp >> 1;
    const int wn   = warp & 1;

    // cp.async assignment: 2 threads per row, each 2x16B per buffer.
    const int ldRow = tid >> 1;
    const int ldCE  = (tid & 1) * 16;  // element offset (bf16)
    const size_t gA = (size_t)(blockIdx.y * 128 + ldRow) * K + ldCE;
    const size_t gB = (size_t)(blockIdx.x * 128 + ldRow) * K + ldCE;
    const uint32_t dRow = ldRow * 80 + ldCE * 2;

    // ldmatrix offsets (stage-relative).
    const int rb = ((lane >> 4) << 3) + (lane & 7);
    const int cb = ((lane >> 3) & 1) * 8;
    uint32_t aoff[2][2], boff[4][2];
#pragma unroll
    for (int mt = 0; mt < 2; mt++)
#pragma unroll
        for (int kk = 0; kk < 2; kk++)
            aoff[mt][kk] = (uint32_t)((wm * 32 + mt * 16 + (lane & 15)) * 80 +
                                      (lane >> 4) * 16 + kk * 32);
#pragma unroll
    for (int p = 0; p < 4; p++)
#pragma unroll
        for (int kk = 0; kk < 2; kk++)
            boff[p][kk] = (uint32_t)((wn * 64 + p * 16 + rb) * 80 + cb * 2 + kk * 32);

    float acc[2][8][4];
#pragma unroll
    for (int mt = 0; mt < 2; mt++)
#pragma unroll
        for (int nt = 0; nt < 8; nt++)
#pragma unroll
            for (int i = 0; i < 4; i++) acc[mt][nt][i] = 0.0f;

    auto load_stage = [&](int s, int k0) {
        uint32_t b = smem_base + (uint32_t)s * sizeof(GStage) + dRow;
        CP16(b + AH_OFF,      Ahg + gA + k0);
        CP16(b + AH_OFF + 16, Ahg + gA + k0 + 8);
        CP16(b + AL_OFF,      Alg + gA + k0);
        CP16(b + AL_OFF + 16, Alg + gA + k0 + 8);
        CP16(b + BH_OFF,      Bhg + gB + k0);
        CP16(b + BH_OFF + 16, Bhg + gB + k0 + 8);
        CP16(b + BL_OFF,      Blg + gB + k0);
        CP16(b + BL_OFF + 16, Blg + gB + k0 + 8);
    };

    load_stage(0, 0);  CP_COMMIT;
    load_stage(1, 32); CP_COMMIT;

    const int NK = K / 32;  // 32
    for (int i = 0; i < NK; i++) {
        CP_WAIT1;
        __syncthreads();
        if (i + 2 < NK) load_stage((i + 2) % NSTAGE, (i + 2) * 32);
        CP_COMMIT;

        const uint32_t sb = smem_base + (uint32_t)(i % NSTAGE) * sizeof(GStage);
#pragma unroll
        for (int kk = 0; kk < 2; kk++) {
            uint32_t bh[8][2], bl[8][2];
#pragma unroll
            for (int p = 0; p < 4; p++) {
                LDSM4(bh[2 * p][0], bh[2 * p][1], bh[2 * p + 1][0], bh[2 * p + 1][1],
                      sb + BH_OFF + boff[p][kk]);
                LDSM4(bl[2 * p][0], bl[2 * p][1], bl[2 * p + 1][0], bl[2 * p + 1][1],
                      sb + BL_OFF + boff[p][kk]);
            }
#pragma unroll
            for (int mt = 0; mt < 2; mt++) {
                uint32_t ah[4], al[4];
                LDSM4(ah[0], ah[1], ah[2], ah[3], sb + AH_OFF + aoff[mt][kk]);
                LDSM4(al[0], al[1], al[2], al[3], sb + AL_OFF + aoff[mt][kk]);
#pragma unroll
                for (int nt = 0; nt < 8; nt++)
                    MMA16816(acc[mt][nt], ah[0], ah[1], ah[2], ah[3], bh[nt][0], bh[nt][1]);
#pragma unroll
                for (int nt = 0; nt < 8; nt++)
                    MMA16816(acc[mt][nt], ah[0], ah[1], ah[2], ah[3], bl[nt][0], bl[nt][1]);
#pragma unroll
                for (int nt = 0; nt < 8; nt++)
                    MMA16816(acc[mt][nt], al[0], al[1], al[2], al[3], bh[nt][0], bh[nt][1]);
            }
        }
    }

    const int rowBase = blockIdx.y * 128 + wm * 32;
    const int colBase = blockIdx.x * 128 + wn * 64;
#pragma unroll
    for (int mt = 0; mt < 2; mt++) {
        int row = rowBase + mt * 16 + (lane >> 2);
#pragma unroll
        for (int nt = 0; nt < 8; nt++) {
            int col = colBase + nt * 8 + (lane & 3) * 2;
            float2 bv = *(const float2*)&bias[col];
            float o00 = acc[mt][nt][0] + bv.x, o01 = acc[mt][nt][1] + bv.y;
            float o10 = acc[mt][nt][2] + bv.x, o11 = acc[mt][nt][3] + bv.y;
            if (SPLIT_OUT) {
                float r00 = o00 - __bfloat162float(__float2bfloat16_rn(o00));
                float r01 = o01 - __bfloat162float(__float2bfloat16_rn(o01));
                float r10 = o10 - __bfloat162float(__float2bfloat16_rn(o10));
                float r11 = o11 - __bfloat162float(__float2bfloat16_rn(o11));
                *(uint32_t*)&Yh[(size_t)row * N + col]       = pack_bf2(o00, o01);
                *(uint32_t*)&Yh[(size_t)(row + 8) * N + col] = pack_bf2(o10, o11);
                *(uint32_t*)&Yl[(size_t)row * N + col]       = pack_bf2(r00, r01);
                *(uint32_t*)&Yl[(size_t)(row + 8) * N + col] = pack_bf2(r10, r11);
            } else {
                *(float2*)&Y[(size_t)row * N + col]       = make_float2(o00, o01);
                *(float2*)&Y[(size_t)(row + 8) * N + col] = make_float2(o10, o11);
            }
        }
    }
}

// ---------------------------------------------------------------------------
// Tensor-core flash attention (R5), epilogue now writes split bf16.
// ---------------------------------------------------------------------------
struct QStage { __nv_bfloat16 h[128][72], l[128][72]; };
struct KVStage {
    __nv_bfloat16 kh[64][72], kl[64][72];
    __nv_bfloat16 vth[64][72], vtl[64][72];
    uint32_t mw[128][2];
};

__global__ __launch_bounds__(256, 1) void attn_tc(
    const __nv_bfloat16* __restrict__ Qh, const __nv_bfloat16* __restrict__ Ql,
    const __nv_bfloat16* __restrict__ Kh, const __nv_bfloat16* __restrict__ Kl,
    const __nv_bfloat16* __restrict__ Vh, const __nv_bfloat16* __restrict__ Vl,
    const uint32_t* __restrict__ mbits,
    __nv_bfloat16* __restrict__ Oh, __nv_bfloat16* __restrict__ Ol) {
    const int qt = blockIdx.x, h = blockIdx.y, b = blockIdx.z;
    const int tid = threadIdx.x, lane = tid & 31, warp = tid >> 5;
    const float SC = 0.125f * 1.44269504f;

    __shared__ union { QStage q; KVStage kv; } sm;

    const size_t qrow0 = (size_t)b * Ss + qt * 128;

    {
        int r = tid >> 1, half = tid & 1;
        const uint4* gh = (const uint4*)(Qh + (qrow0 + r) * Dd + h * 64 + half * 32);
        const uint4* gl = (const uint4*)(Ql + (qrow0 + r) * Dd + h * 64 + half * 32);
        uint4* sh = (uint4*)&sm.q.h[r][half * 32];
        uint4* sl = (uint4*)&sm.q.l[r][half * 32];
#pragma unroll
        for (int i = 0; i < 4; i++) { sh[i] = gh[i]; sl[i] = gl[i]; }
    }
    __syncthreads();

    uint32_t qfh[4][4], qfl[4][4];
    {
        uint32_t bqh = (uint32_t)__cvta_generic_to_shared(&sm.q.h[0][0]);
        uint32_t bql = (uint32_t)__cvta_generic_to_shared(&sm.q.l[0][0]);
        int r = warp * 16 + (lane & 15);
#pragma unroll
        for (int s = 0; s < 4; s++) {
            uint32_t off = (uint32_t)((r * 72 + s * 16 + (lane >> 4) * 8) * 2);
            LDSM4(qfh[s][0], qfh[s][1], qfh[s][2], qfh[s][3], bqh + off);
            LDSM4(qfl[s][0], qfl[s][1], qfl[s][2], qfl[s][3], bql + off);
        }
    }
    __syncthreads();

    float oacc[8][4];
#pragma unroll
    for (int nt = 0; nt < 8; nt++)
#pragma unroll
        for (int i = 0; i < 4; i++) oacc[nt][i] = 0.0f;
    float m1 = -1e30f, m2 = -1e30f, l1 = 0.0f, l2 = 0.0f;

    const int rb = ((lane >> 4) << 3) + (lane & 7);
    const int cb = ((lane >> 3) & 1) * 8;
    const int r1 = lane >> 2;

    for (int kt = 0; kt < 16; kt++) {
        {
            int r = tid >> 2, qtr = tid & 3;
            size_t g = ((size_t)b * Ss + kt * 64 + r) * Dd + h * 64 + qtr * 16;
            *(uint4*)&sm.kv.kh[r][qtr * 16]     = *(const uint4*)(Kh + g);
            *(uint4*)&sm.kv.kh[r][qtr * 16 + 8] = *(const uint4*)(Kh + g + 8);
            *(uint4*)&sm.kv.kl[r][qtr * 16]     = *(const uint4*)(Kl + g);
            *(uint4*)&sm.kv.kl[r][qtr * 16 + 8] = *(const uint4*)(Kl + g + 8);
            union { uint4 v[2]; __nv_bfloat16 e[16]; } th, tl;
            th.v[0] = *(const uint4*)(Vh + g); th.v[1] = *(const uint4*)(Vh + g + 8);
            tl.v[0] = *(const uint4*)(Vl + g); tl.v[1] = *(const uint4*)(Vl + g + 8);
#pragma unroll
            for (int i = 0; i < 16; i++) {
                sm.kv.vth[qtr * 16 + i][r] = th.e[i];
                sm.kv.vtl[qtr * 16 + i][r] = tl.e[i];
            }
            int mr = tid >> 1, mwsel = tid & 1;
            sm.kv.mw[mr][mwsel] = mbits[(qrow0 + mr) * 32 + kt * 2 + mwsel];
        }
        __syncthreads();

        float sacc[8][4];
#pragma unroll
        for (int nt = 0; nt < 8; nt++)
#pragma unroll
            for (int i = 0; i < 4; i++) sacc[nt][i] = 0.0f;
        {
            uint32_t kbh = (uint32_t)__cvta_generic_to_shared(&sm.kv.kh[0][0]);
            uint32_t kbl = (uint32_t)__cvta_generic_to_shared(&sm.kv.kl[0][0]);
#pragma unroll
            for (int s = 0; s < 4; s++) {
                uint32_t bh[8][2], bl[8][2];
#pragma unroll
                for (int p = 0; p < 4; p++) {
                    uint32_t off = (uint32_t)(((p * 16 + rb) * 72 + s * 16 + cb) * 2);
                    LDSM4(bh[2 * p][0], bh[2 * p][1], bh[2 * p + 1][0], bh[2 * p + 1][1], kbh + off);
                    LDSM4(bl[2 * p][0], bl[2 * p][1], bl[2 * p + 1][0], bl[2 * p + 1][1], kbl + off);
                }
#pragma unroll
                for (int nt = 0; nt < 8; nt++) {
                    MMA16816(sacc[nt], qfh[s][0], qfh[s][1], qfh[s][2], qfh[s][3], bh[nt][0], bh[nt][1]);
                    MMA16816(sacc[nt], qfh[s][0], qfh[s][1], qfh[s][2], qfh[s][3], bl[nt][0], bl[nt][1]);
                    MMA16816(sacc[nt], qfl[s][0], qfl[s][1], qfl[s][2], qfl[s][3], bh[nt][0], bh[nt][1]);
                }
            }
        }

        uint32_t w10 = sm.kv.mw[warp * 16 + r1][0];
        uint32_t w11 = sm.kv.mw[warp * 16 + r1][1];
        uint32_t w20 = sm.kv.mw[warp * 16 + r1 + 8][0];
        uint32_t w21 = sm.kv.mw[warp * 16 + r1 + 8][1];
        float tm1 = -1e30f, tm2 = -1e30f;
#pragma unroll
        for (int nt = 0; nt < 8; nt++) {
            int cbase = nt * 8 + (lane & 3) * 2;
            uint32_t wA = (nt < 4) ? w10 : w11;
            uint32_t wB = (nt < 4) ? w20 : w21;
            int shf = cbase & 31;
            float s0 = sacc[nt][0] * SC, s1 = sacc[nt][1] * SC;
            float s2 = sacc[nt][2] * SC, s3 = sacc[nt][3] * SC;
            if (!((wA >> shf) & 1))       s0 = -1e9f;
            if (!((wA >> (shf + 1)) & 1)) s1 = -1e9f;
            if (!((wB >> shf) & 1))       s2 = -1e9f;
            if (!((wB >> (shf + 1)) & 1)) s3 = -1e9f;
            sacc[nt][0] = s0; sacc[nt][1] = s1; sacc[nt][2] = s2; sacc[nt][3] = s3;
            tm1 = fmaxf(tm1, fmaxf(s0, s1));
            tm2 = fmaxf(tm2, fmaxf(s2, s3));
        }
        tm1 = fmaxf(tm1, __shfl_xor_sync(0xffffffff, tm1, 1));
        tm1 = fmaxf(tm1, __shfl_xor_sync(0xffffffff, tm1, 2));
        tm2 = fmaxf(tm2, __shfl_xor_sync(0xffffffff, tm2, 1));
        tm2 = fmaxf(tm2, __shfl_xor_sync(0xffffffff, tm2, 2));

        float mn1 = fmaxf(m1, tm1), mn2 = fmaxf(m2, tm2);
        float a1 = exp2f(m1 - mn1), a2 = exp2f(m2 - mn2);
        m1 = mn1; m2 = mn2;
        l1 *= a1; l2 *= a2;
#pragma unroll
        for (int nt = 0; nt < 8; nt++) {
            oacc[nt][0] *= a1; oacc[nt][1] *= a1;
            oacc[nt][2] *= a2; oacc[nt][3] *= a2;
        }

        uint32_t pah[4][4], pal[4][4];
#pragma unroll
        for (int nt = 0; nt < 8; nt++) {
            float p0 = exp2f(sacc[nt][0] - m1), p1 = exp2f(sacc[nt][1] - m1);
            float p2 = exp2f(sacc[nt][2] - m2), p3 = exp2f(sacc[nt][3] - m2);
            l1 += p0 + p1; l2 += p2 + p3;
            __nv_bfloat16 h0 = __float2bfloat16_rn(p0), h1 = __float2bfloat16_rn(p1);
            __nv_bfloat16 h2 = __float2bfloat16_rn(p2), h3 = __float2bfloat16_rn(p3);
            int s = nt >> 1, base = (nt & 1) * 2;
            pah[s][base]     = pack_bf2(p0, p1);
            pah[s][base + 1] = pack_bf2(p2, p3);
            pal[s][base]     = pack_bf2(p0 - __bfloat162float(h0), p1 - __bfloat162float(h1));
            pal[s][base + 1] = pack_bf2(p2 - __bfloat162float(h2), p3 - __bfloat162float(h3));
        }

        {
            uint32_t vbh = (uint32_t)__cvta_generic_to_shared(&sm.kv.vth[0][0]);
            uint32_t vbl = (uint32_t)__cvta_generic_to_shared(&sm.kv.vtl[0][0]);
#pragma unroll
            for (int s = 0; s < 4; s++) {
                uint32_t bh[8][2], bl[8][2];
#pragma unroll
                for (int p = 0; p < 4; p++) {
                    uint32_t off = (uint32_t)(((p * 16 + rb) * 72 + s * 16 + cb) * 2);
                    LDSM4(bh[2 * p][0], bh[2 * p][1], bh[2 * p + 1][0], bh[2 * p + 1][1], vbh + off);
                    LDSM4(bl[2 * p][0], bl[2 * p][1], bl[2 * p + 1][0], bl[2 * p + 1][1], vbl + off);
                }
#pragma unroll
                for (int dt = 0; dt < 8; dt++) {
                    MMA16816(oacc[dt], pah[s][0], pah[s][1], pah[s][2], pah[s][3], bh[dt][0], bh[dt][1]);
                    MMA16816(oacc[dt], pah[s][0], pah[s][1], pah[s][2], pah[s][3], bl[dt][0], bl[dt][1]);
                    MMA16816(oacc[dt], pal[s][0], pal[s][1], pal[s][2], pal[s][3], bh[dt][0], bh[dt][1]);
                }
            }
        }
        __syncthreads();
    }

    l1 += __shfl_xor_sync(0xffffffff, l1, 1);
    l1 += __shfl_xor_sync(0xffffffff, l1, 2);
    l2 += __shfl_xor_sync(0xffffffff, l2, 1);
    l2 += __shfl_xor_sync(0xffffffff, l2, 2);
    float inv1 = 1.0f / l1, inv2 = 1.0f / l2;

    size_t row1 = qrow0 + warp * 16 + r1;
#pragma unroll
    for (int nt = 0; nt < 8; nt++) {
        int col = h * 64 + nt * 8 + (lane & 3) * 2;
        float o00 = oacc[nt][0] * inv1, o01 = oacc[nt][1] * inv1;
        float o10 = oacc[nt][2] * inv2, o11 = oacc[nt][3] * inv2;
        float r00 = o00 - __bfloat162float(__float2bfloat16_rn(o00));
        float r01 = o01 - __bfloat162float(__float2bfloat16_rn(o01));
        float r10 = o10 - __bfloat162float(__float2bfloat16_rn(o10));
        float r11 = o11 - __bfloat162float(__float2bfloat16_rn(o11));
        *(uint32_t*)&Oh[row1 * Dd + col]       = pack_bf2(o00, o01);
        *(uint32_t*)&Oh[(row1 + 8) * Dd + col] = pack_bf2(o10, o11);
        *(uint32_t*)&Ol[row1 * Dd + col]       = pack_bf2(r00, r01);
        *(uint32_t*)&Ol[(row1 + 8) * Dd + col] = pack_bf2(r10, r11);
    }
}

// ---------------------------------------------------------------------------
extern "C" void kernel_launch(void* const* d_in, const int* in_sizes, int n_in,
                              void* d_out, int out_size) {
    (void)in_sizes; (void)n_in; (void)out_size;

    const float* q    = (const float*)d_in[0];
    const float* k    = (const float*)d_in[1];
    const float* v    = (const float*)d_in[2];
    const int*   mask = (const int*)d_in[3];
    const float* WQw  = (const float*)d_in[4];
    const float* WQb  = (const float*)d_in[5];
    const float* WKw  = (const float*)d_in[6];
    const float* WKb  = (const float*)d_in[7];
    const float* WVw  = (const float*)d_in[8];
    const float* WVb  = (const float*)d_in[9];
    const float* WOw  = (const float*)d_in[10];
    const float* WOb  = (const float*)d_in[11];
    float* out = (float*)d_out;

    __nv_bfloat16 *qh, *ql, *kh, *kl, *vh, *vl;
    __nv_bfloat16 *Qh, *Ql, *Kh, *Kl, *Vh, *Vl, *AOh, *AOl;
    __nv_bfloat16 *WQh, *WQl, *WKh, *WKl, *WVh, *WVl, *WOh, *WOl;
    uint32_t* Mb;
    cudaGetSymbolAddress((void**)&qh, g_qh);   cudaGetSymbolAddress((void**)&ql, g_ql);
    cudaGetSymbolAddress((void**)&kh, g_kh);   cudaGetSymbolAddress((void**)&kl, g_kl);
    cudaGetSymbolAddress((void**)&vh, g_vh);   cudaGetSymbolAddress((void**)&vl, g_vl);
    cudaGetSymbolAddress((void**)&Qh, g_Qh);   cudaGetSymbolAddress((void**)&Ql, g_Ql);
    cudaGetSymbolAddress((void**)&Kh, g_Kh);   cudaGetSymbolAddress((void**)&Kl, g_Kl);
    cudaGetSymbolAddress((void**)&Vh, g_Vh);   cudaGetSymbolAddress((void**)&Vl, g_Vl);
    cudaGetSymbolAddress((void**)&AOh, g_AOh); cudaGetSymbolAddress((void**)&AOl, g_AOl);
    cudaGetSymbolAddress((void**)&WQh, g_WQh); cudaGetSymbolAddress((void**)&WQl, g_WQl);
    cudaGetSymbolAddress((void**)&WKh, g_WKh); cudaGetSymbolAddress((void**)&WKl, g_WKl);
    cudaGetSymbolAddress((void**)&WVh, g_WVh); cudaGetSymbolAddress((void**)&WVl, g_WVl);
    cudaGetSymbolAddress((void**)&WOh, g_WOh); cudaGetSymbolAddress((void**)&WOl, g_WOl);
    cudaGetSymbolAddress((void**)&Mb, g_mbits);

    const int smem = NSTAGE * (int)sizeof(GStage);  // 122880
    cudaFuncSetAttribute(gemm_sp<1>, cudaFuncAttributeMaxDynamicSharedMemorySize, smem);
    cudaFuncSetAttribute(gemm_sp<0>, cudaFuncAttributeMaxDynamicSharedMemorySize, smem);

    pack_mask<<<(Bb * Ss * (Ss / 32)) / 256, 256>>>(mask, Mb);

    const int nTok = Bb * Ss * Dd;  // 8388608
    const int nW   = Dd * Dd;       // 1048576
    split_f32<<<nTok / 1024, 256>>>(q, qh, ql);
    split_f32<<<nTok / 1024, 256>>>(k, kh, kl);
    split_f32<<<nTok / 1024, 256>>>(v, vh, vl);
    split_f32<<<nW / 1024, 256>>>(WQw, WQh, WQl);
    split_f32<<<nW / 1024, 256>>>(WKw, WKh, WKl);
    split_f32<<<nW / 1024, 256>>>(WVw, WVh, WVl);
    split_f32<<<nW / 1024, 256>>>(WOw, WOh, WOl);

    dim3 gg(Dd / 128, (Bb * Ss) / 128);  // (8, 64)
    gemm_sp<1><<<gg, 256, smem>>>(qh, ql, WQh, WQl, WQb, nullptr, Qh, Ql);
    gemm_sp<1><<<gg, 256, smem>>>(kh, kl, WKh, WKl, WKb, nullptr, Kh, Kl);
    gemm_sp<1><<<gg, 256, smem>>>(vh, vl, WVh, WVl, WVb, nullptr, Vh, Vl);

    attn_tc<<<dim3(Ss / 128, Hh, Bb), 256>>>(Qh, Ql, Kh, Kl, Vh, Vl, Mb, AOh, AOl);

    gemm_sp<0><<<gg, 256, smem>>>(AOh, AOl, WOh, WOl, WOb, out, nullptr, nullptr);
}

// round 8
// speedup vs baseline: 2.8162x; 1.0695x over previous
#include <cuda_runtime.h>
#include <cuda_bf16.h>
#include <math.h>
#include <cstdint>

#define Bb 8
#define Ss 1024
#define Dd 1024
#define Hh 16
#define DKk 64

// ---- Scratch (all split bf16 hi/lo) ----
__device__ __nv_bfloat16 g_qh[(size_t)Bb * Ss * Dd], g_ql[(size_t)Bb * Ss * Dd];
__device__ __nv_bfloat16 g_kh[(size_t)Bb * Ss * Dd], g_kl[(size_t)Bb * Ss * Dd];
__device__ __nv_bfloat16 g_vh[(size_t)Bb * Ss * Dd], g_vl[(size_t)Bb * Ss * Dd];
__device__ __nv_bfloat16 g_Qh[(size_t)Bb * Ss * Dd], g_Ql[(size_t)Bb * Ss * Dd];
__device__ __nv_bfloat16 g_Kh[(size_t)Bb * Ss * Dd], g_Kl[(size_t)Bb * Ss * Dd];
__device__ __nv_bfloat16 g_Vh[(size_t)Bb * Ss * Dd], g_Vl[(size_t)Bb * Ss * Dd];
__device__ __nv_bfloat16 g_AOh[(size_t)Bb * Ss * Dd], g_AOl[(size_t)Bb * Ss * Dd];
__device__ __nv_bfloat16 g_WQh[Dd * Dd], g_WQl[Dd * Dd];
__device__ __nv_bfloat16 g_WKh[Dd * Dd], g_WKl[Dd * Dd];
__device__ __nv_bfloat16 g_WVh[Dd * Dd], g_WVl[Dd * Dd];
__device__ __nv_bfloat16 g_WOh[Dd * Dd], g_WOl[Dd * Dd];
__device__ uint32_t g_mbits[(size_t)Bb * Ss * (Ss / 32)];

#define LDSM4(r0, r1, r2, r3, addr)                                          \
    asm volatile("ldmatrix.sync.aligned.m8n8.x4.shared.b16 {%0,%1,%2,%3}, [%4];" \
                 : "=r"(r0), "=r"(r1), "=r"(r2), "=r"(r3) : "r"(addr))

#define MMA16816(d, a0, a1, a2, a3, b0, b1)                                  \
    asm volatile(                                                            \
        "mma.sync.aligned.m16n8k16.row.col.f32.bf16.bf16.f32 "               \
        "{%0,%1,%2,%3}, {%4,%5,%6,%7}, {%8,%9}, {%0,%1,%2,%3};"              \
        : "+f"(d[0]), "+f"(d[1]), "+f"(d[2]), "+f"(d[3])                     \
        : "r"(a0), "r"(a1), "r"(a2), "r"(a3), "r"(b0), "r"(b1))

#define CP16(dst, src)                                                       \
    asm volatile("cp.async.cg.shared.global [%0], [%1], 16;" ::"r"(dst), "l"(src))
#define CP_COMMIT asm volatile("cp.async.commit_group;")
#define CP_WAIT1  asm volatile("cp.async.wait_group 1;")
#define CP_WAIT0  asm volatile("cp.async.wait_group 0;")

__device__ __forceinline__ uint32_t pack_bf2(float a, float b) {
    __nv_bfloat162 t = __floats2bfloat162_rn(a, b);
    return *(uint32_t*)&t;
}

// ---------------------------------------------------------------------------
// fp32 -> split bf16 (hi = rn(x), lo = rn(x - hi)).
// ---------------------------------------------------------------------------
__global__ void split_f32(const float* __restrict__ in,
                          __nv_bfloat16* __restrict__ hi,
                          __nv_bfloat16* __restrict__ lo) {
    size_t i = ((size_t)blockIdx.x * 256 + threadIdx.x) * 4;
    float4 v = *(const float4*)(in + i);
    float r0 = v.x - __bfloat162float(__float2bfloat16_rn(v.x));
    float r1 = v.y - __bfloat162float(__float2bfloat16_rn(v.y));
    float r2 = v.z - __bfloat162float(__float2bfloat16_rn(v.z));
    float r3 = v.w - __bfloat162float(__float2bfloat16_rn(v.w));
    *(uint2*)(hi + i) = make_uint2(pack_bf2(v.x, v.y), pack_bf2(v.z, v.w));
    *(uint2*)(lo + i) = make_uint2(pack_bf2(r0, r1), pack_bf2(r2, r3));
}

__global__ void pack_mask(const int* __restrict__ mask, uint32_t* __restrict__ bits) {
    size_t w = (size_t)blockIdx.x * 256 + threadIdx.x;
    const int* p = mask + w * 32;
    uint32_t v = 0;
#pragma unroll
    for (int i = 0; i < 32; i += 4) {
        int4 t = *(const int4*)(p + i);
        v |= (uint32_t)(t.x != 0) << i;
        v |= (uint32_t)(t.y != 0) << (i + 1);
        v |= (uint32_t)(t.z != 0) << (i + 2);
        v |= (uint32_t)(t.w != 0) << (i + 3);
    }
    bits[w] = v;
}

// ---------------------------------------------------------------------------
// Pipelined split-bf16 GEMM: Y = A[M,K] @ B[N,K]^T + bias.
// 2-stage cp.async (smem 80KB -> 2 CTAs/SM), BK=32, 128x128 tile, 256 thr,
// __launch_bounds__(256,2) to force <=124 regs for co-residency.
// ---------------------------------------------------------------------------
struct GStage {
    __nv_bfloat16 ah[128][40];
    __nv_bfloat16 al[128][40];
    __nv_bfloat16 bh[128][40];
    __nv_bfloat16 bl[128][40];
};
#define AH_OFF 0
#define AL_OFF 10240
#define BH_OFF 20480
#define BL_OFF 30720
#define GSMEM (2u * sizeof(GStage))  // 81920

template <int SPLIT_OUT>
__global__ __launch_bounds__(256, 2) void gemm_sp(
    const __nv_bfloat16* __restrict__ Ahg, const __nv_bfloat16* __restrict__ Alg,
    const __nv_bfloat16* __restrict__ Bhg, const __nv_bfloat16* __restrict__ Blg,
    const float* __restrict__ bias, float* __restrict__ Y,
    __nv_bfloat16* __restrict__ Yh, __nv_bfloat16* __restrict__ Yl) {
    const int K = 1024, N = 1024;
    extern __shared__ char smem_raw[];
    const uint32_t smem_base = (uint32_t)__cvta_generic_to_shared(smem_raw);

    const int tid  = threadIdx.x;
    const int lane = tid & 31;
    const int warp = tid >> 5;
    const int wm   = warp >> 1;
    const int wn   = warp & 1;

    const int ldRow = tid >> 1;
    const int ldCE  = (tid & 1) * 16;
    const size_t gA = (size_t)(blockIdx.y * 128 + ldRow) * K + ldCE;
    const size_t gB = (size_t)(blockIdx.x * 128 + ldRow) * K + ldCE;
    const uint32_t dRow = ldRow * 80 + ldCE * 2;

    const int rb = ((lane >> 4) << 3) + (lane & 7);
    const int cb = ((lane >> 3) & 1) * 8;
    uint32_t aoff[2][2], boff[4][2];
#pragma unroll
    for (int mt = 0; mt < 2; mt++)
#pragma unroll
        for (int kk = 0; kk < 2; kk++)
            aoff[mt][kk] = (uint32_t)((wm * 32 + mt * 16 + (lane & 15)) * 80 +
                                      (lane >> 4) * 16 + kk * 32);
#pragma unroll
    for (int p = 0; p < 4; p++)
#pragma unroll
        for (int kk = 0; kk < 2; kk++)
            boff[p][kk] = (uint32_t)((wn * 64 + p * 16 + rb) * 80 + cb * 2 + kk * 32);

    float acc[2][8][4];
#pragma unroll
    for (int mt = 0; mt < 2; mt++)
#pragma unroll
        for (int nt = 0; nt < 8; nt++)
#pragma unroll
            for (int i = 0; i < 4; i++) acc[mt][nt][i] = 0.0f;

    auto load_stage = [&](int s, int k0) {
        uint32_t b = smem_base + (uint32_t)s * sizeof(GStage) + dRow;
        CP16(b + AH_OFF,      Ahg + gA + k0);
        CP16(b + AH_OFF + 16, Ahg + gA + k0 + 8);
        CP16(b + AL_OFF,      Alg + gA + k0);
        CP16(b + AL_OFF + 16, Alg + gA + k0 + 8);
        CP16(b + BH_OFF,      Bhg + gB + k0);
        CP16(b + BH_OFF + 16, Bhg + gB + k0 + 8);
        CP16(b + BL_OFF,      Blg + gB + k0);
        CP16(b + BL_OFF + 16, Blg + gB + k0 + 8);
    };

    load_stage(0, 0); CP_COMMIT;

    const int NK = K / 32;  // 32
    for (int i = 0; i < NK; i++) {
        if (i + 1 < NK) {
            load_stage((i + 1) & 1, (i + 1) * 32);
            CP_COMMIT;
            CP_WAIT1;  // stage i complete (i+1 may be in flight)
        } else {
            CP_WAIT0;
        }
        __syncthreads();

        const uint32_t sb = smem_base + (uint32_t)(i & 1) * sizeof(GStage);
#pragma unroll
        for (int kk = 0; kk < 2; kk++) {
            uint32_t bh[8][2], bl[8][2];
#pragma unroll
            for (int p = 0; p < 4; p++) {
                LDSM4(bh[2 * p][0], bh[2 * p][1], bh[2 * p + 1][0], bh[2 * p + 1][1],
                      sb + BH_OFF + boff[p][kk]);
                LDSM4(bl[2 * p][0], bl[2 * p][1], bl[2 * p + 1][0], bl[2 * p + 1][1],
                      sb + BL_OFF + boff[p][kk]);
            }
#pragma unroll
            for (int mt = 0; mt < 2; mt++) {
                uint32_t ah[4], al[4];
                LDSM4(ah[0], ah[1], ah[2], ah[3], sb + AH_OFF + aoff[mt][kk]);
                LDSM4(al[0], al[1], al[2], al[3], sb + AL_OFF + aoff[mt][kk]);
#pragma unroll
                for (int nt = 0; nt < 8; nt++)
                    MMA16816(acc[mt][nt], ah[0], ah[1], ah[2], ah[3], bh[nt][0], bh[nt][1]);
#pragma unroll
                for (int nt = 0; nt < 8; nt++)
                    MMA16816(acc[mt][nt], ah[0], ah[1], ah[2], ah[3], bl[nt][0], bl[nt][1]);
#pragma unroll
                for (int nt = 0; nt < 8; nt++)
                    MMA16816(acc[mt][nt], al[0], al[1], al[2], al[3], bh[nt][0], bh[nt][1]);
            }
        }
        __syncthreads();  // all warps done with stage i before it is overwritten
    }

    const int rowBase = blockIdx.y * 128 + wm * 32;
    const int colBase = blockIdx.x * 128 + wn * 64;
#pragma unroll
    for (int mt = 0; mt < 2; mt++) {
        int row = rowBase + mt * 16 + (lane >> 2);
#pragma unroll
        for (int nt = 0; nt < 8; nt++) {
            int col = colBase + nt * 8 + (lane & 3) * 2;
            float2 bv = *(const float2*)&bias[col];
            float o00 = acc[mt][nt][0] + bv.x, o01 = acc[mt][nt][1] + bv.y;
            float o10 = acc[mt][nt][2] + bv.x, o11 = acc[mt][nt][3] + bv.y;
            if (SPLIT_OUT) {
                float r00 = o00 - __bfloat162float(__float2bfloat16_rn(o00));
                float r01 = o01 - __bfloat162float(__float2bfloat16_rn(o01));
                float r10 = o10 - __bfloat162float(__float2bfloat16_rn(o10));
                float r11 = o11 - __bfloat162float(__float2bfloat16_rn(o11));
                *(uint32_t*)&Yh[(size_t)row * N + col]       = pack_bf2(o00, o01);
                *(uint32_t*)&Yh[(size_t)(row + 8) * N + col] = pack_bf2(o10, o11);
                *(uint32_t*)&Yl[(size_t)row * N + col]       = pack_bf2(r00, r01);
                *(uint32_t*)&Yl[(size_t)(row + 8) * N + col] = pack_bf2(r10, r11);
            } else {
                *(float2*)&Y[(size_t)row * N + col]       = make_float2(o00, o01);
                *(float2*)&Y[(size_t)(row + 8) * N + col] = make_float2(o10, o11);
            }
        }
    }
}

// ---------------------------------------------------------------------------
// Tensor-core flash attention (unchanged from R6).
// ---------------------------------------------------------------------------
struct QStage { __nv_bfloat16 h[128][72], l[128][72]; };
struct KVStage {
    __nv_bfloat16 kh[64][72], kl[64][72];
    __nv_bfloat16 vth[64][72], vtl[64][72];
    uint32_t mw[128][2];
};

__global__ __launch_bounds__(256, 1) void attn_tc(
    const __nv_bfloat16* __restrict__ Qh, const __nv_bfloat16* __restrict__ Ql,
    const __nv_bfloat16* __restrict__ Kh, const __nv_bfloat16* __restrict__ Kl,
    const __nv_bfloat16* __restrict__ Vh, const __nv_bfloat16* __restrict__ Vl,
    const uint32_t* __restrict__ mbits,
    __nv_bfloat16* __restrict__ Oh, __nv_bfloat16* __restrict__ Ol) {
    const int qt = blockIdx.x, h = blockIdx.y, b = blockIdx.z;
    const int tid = threadIdx.x, lane = tid & 31, warp = tid >> 5;
    const float SC = 0.125f * 1.44269504f;

    __shared__ union { QStage q; KVStage kv; } sm;

    const size_t qrow0 = (size_t)b * Ss + qt * 128;

    {
        int r = tid >> 1, half = tid & 1;
        const uint4* gh = (const uint4*)(Qh + (qrow0 + r) * Dd + h * 64 + half * 32);
        const uint4* gl = (const uint4*)(Ql + (qrow0 + r) * Dd + h * 64 + half * 32);
        uint4* sh = (uint4*)&sm.q.h[r][half * 32];
        uint4* sl = (uint4*)&sm.q.l[r][half * 32];
#pragma unroll
        for (int i = 0; i < 4; i++) { sh[i] = gh[i]; sl[i] = gl[i]; }
    }
    __syncthreads();

    uint32_t qfh[4][4], qfl[4][4];
    {
        uint32_t bqh = (uint32_t)__cvta_generic_to_shared(&sm.q.h[0][0]);
        uint32_t bql = (uint32_t)__cvta_generic_to_shared(&sm.q.l[0][0]);
        int r = warp * 16 + (lane & 15);
#pragma unroll
        for (int s = 0; s < 4; s++) {
            uint32_t off = (uint32_t)((r * 72 + s * 16 + (lane >> 4) * 8) * 2);
            LDSM4(qfh[s][0], qfh[s][1], qfh[s][2], qfh[s][3], bqh + off);
            LDSM4(qfl[s][0], qfl[s][1], qfl[s][2], qfl[s][3], bql + off);
        }
    }
    __syncthreads();

    float oacc[8][4];
#pragma unroll
    for (int nt = 0; nt < 8; nt++)
#pragma unroll
        for (int i = 0; i < 4; i++) oacc[nt][i] = 0.0f;
    float m1 = -1e30f, m2 = -1e30f, l1 = 0.0f, l2 = 0.0f;

    const int rb = ((lane >> 4) << 3) + (lane & 7);
    const int cb = ((lane >> 3) & 1) * 8;
    const int r1 = lane >> 2;

    for (int kt = 0; kt < 16; kt++) {
        {
            int r = tid >> 2, qtr = tid & 3;
            size_t g = ((size_t)b * Ss + kt * 64 + r) * Dd + h * 64 + qtr * 16;
            *(uint4*)&sm.kv.kh[r][qtr * 16]     = *(const uint4*)(Kh + g);
            *(uint4*)&sm.kv.kh[r][qtr * 16 + 8] = *(const uint4*)(Kh + g + 8);
            *(uint4*)&sm.kv.kl[r][qtr * 16]     = *(const uint4*)(Kl + g);
            *(uint4*)&sm.kv.kl[r][qtr * 16 + 8] = *(const uint4*)(Kl + g + 8);
            union { uint4 v[2]; __nv_bfloat16 e[16]; } th, tl;
            th.v[0] = *(const uint4*)(Vh + g); th.v[1] = *(const uint4*)(Vh + g + 8);
            tl.v[0] = *(const uint4*)(Vl + g); tl.v[1] = *(const uint4*)(Vl + g + 8);
#pragma unroll
            for (int i = 0; i < 16; i++) {
                sm.kv.vth[qtr * 16 + i][r] = th.e[i];
                sm.kv.vtl[qtr * 16 + i][r] = tl.e[i];
            }
            int mr = tid >> 1, mwsel = tid & 1;
            sm.kv.mw[mr][mwsel] = mbits[(qrow0 + mr) * 32 + kt * 2 + mwsel];
        }
        __syncthreads();

        float sacc[8][4];
#pragma unroll
        for (int nt = 0; nt < 8; nt++)
#pragma unroll
            for (int i = 0; i < 4; i++) sacc[nt][i] = 0.0f;
        {
            uint32_t kbh = (uint32_t)__cvta_generic_to_shared(&sm.kv.kh[0][0]);
            uint32_t kbl = (uint32_t)__cvta_generic_to_shared(&sm.kv.kl[0][0]);
#pragma unroll
            for (int s = 0; s < 4; s++) {
                uint32_t bh[8][2], bl[8][2];
#pragma unroll
                for (int p = 0; p < 4; p++) {
                    uint32_t off = (uint32_t)(((p * 16 + rb) * 72 + s * 16 + cb) * 2);
                    LDSM4(bh[2 * p][0], bh[2 * p][1], bh[2 * p + 1][0], bh[2 * p + 1][1], kbh + off);
                    LDSM4(bl[2 * p][0], bl[2 * p][1], bl[2 * p + 1][0], bl[2 * p + 1][1], kbl + off);
                }
#pragma unroll
                for (int nt = 0; nt < 8; nt++) {
                    MMA16816(sacc[nt], qfh[s][0], qfh[s][1], qfh[s][2], qfh[s][3], bh[nt][0], bh[nt][1]);
                    MMA16816(sacc[nt], qfh[s][0], qfh[s][1], qfh[s][2], qfh[s][3], bl[nt][0], bl[nt][1]);
                    MMA16816(sacc[nt], qfl[s][0], qfl[s][1], qfl[s][2], qfl[s][3], bh[nt][0], bh[nt][1]);
                }
            }
        }

        uint32_t w10 = sm.kv.mw[warp * 16 + r1][0];
        uint32_t w11 = sm.kv.mw[warp * 16 + r1][1];
        uint32_t w20 = sm.kv.mw[warp * 16 + r1 + 8][0];
        uint32_t w21 = sm.kv.mw[warp * 16 + r1 + 8][1];
        float tm1 = -1e30f, tm2 = -1e30f;
#pragma unroll
        for (int nt = 0; nt < 8; nt++) {
            int cbase = nt * 8 + (lane & 3) * 2;
            uint32_t wA = (nt < 4) ? w10 : w11;
            uint32_t wB = (nt < 4) ? w20 : w21;
            int shf = cbase & 31;
            float s0 = sacc[nt][0] * SC, s1 = sacc[nt][1] * SC;
            float s2 = sacc[nt][2] * SC, s3 = sacc[nt][3] * SC;
            if (!((wA >> shf) & 1))       s0 = -1e9f;
            if (!((wA >> (shf + 1)) & 1)) s1 = -1e9f;
            if (!((wB >> shf) & 1))       s2 = -1e9f;
            if (!((wB >> (shf + 1)) & 1)) s3 = -1e9f;
            sacc[nt][0] = s0; sacc[nt][1] = s1; sacc[nt][2] = s2; sacc[nt][3] = s3;
            tm1 = fmaxf(tm1, fmaxf(s0, s1));
            tm2 = fmaxf(tm2, fmaxf(s2, s3));
        }
        tm1 = fmaxf(tm1, __shfl_xor_sync(0xffffffff, tm1, 1));
        tm1 = fmaxf(tm1, __shfl_xor_sync(0xffffffff, tm1, 2));
        tm2 = fmaxf(tm2, __shfl_xor_sync(0xffffffff, tm2, 1));
        tm2 = fmaxf(tm2, __shfl_xor_sync(0xffffffff, tm2, 2));

        float mn1 = fmaxf(m1, tm1), mn2 = fmaxf(m2, tm2);
        float a1 = exp2f(m1 - mn1), a2 = exp2f(m2 - mn2);
        m1 = mn1; m2 = mn2;
        l1 *= a1; l2 *= a2;
#pragma unroll
        for (int nt = 0; nt < 8; nt++) {
            oacc[nt][0] *= a1; oacc[nt][1] *= a1;
            oacc[nt][2] *= a2; oacc[nt][3] *= a2;
        }

        uint32_t pah[4][4], pal[4][4];
#pragma unroll
        for (int nt = 0; nt < 8; nt++) {
            float p0 = exp2f(sacc[nt][0] - m1), p1 = exp2f(sacc[nt][1] - m1);
            float p2 = exp2f(sacc[nt][2] - m2), p3 = exp2f(sacc[nt][3] - m2);
            l1 += p0 + p1; l2 += p2 + p3;
            __nv_bfloat16 h0 = __float2bfloat16_rn(p0), h1 = __float2bfloat16_rn(p1);
            __nv_bfloat16 h2 = __float2bfloat16_rn(p2), h3 = __float2bfloat16_rn(p3);
            int s = nt >> 1, base = (nt & 1) * 2;
            pah[s][base]     = pack_bf2(p0, p1);
            pah[s][base + 1] = pack_bf2(p2, p3);
            pal[s][base]     = pack_bf2(p0 - __bfloat162float(h0), p1 - __bfloat162float(h1));
            pal[s][base + 1] = pack_bf2(p2 - __bfloat162float(h2), p3 - __bfloat162float(h3));
        }

        {
            uint32_t vbh = (uint32_t)__cvta_generic_to_shared(&sm.kv.vth[0][0]);
            uint32_t vbl = (uint32_t)__cvta_generic_to_shared(&sm.kv.vtl[0][0]);
#pragma unroll
            for (int s = 0; s < 4; s++) {
                uint32_t bh[8][2], bl[8][2];
#pragma unroll
                for (int p = 0; p < 4; p++) {
                    uint32_t off = (uint32_t)(((p * 16 + rb) * 72 + s * 16 + cb) * 2);
                    LDSM4(bh[2 * p][0], bh[2 * p][1], bh[2 * p + 1][0], bh[2 * p + 1][1], vbh + off);
                    LDSM4(bl[2 * p][0], bl[2 * p][1], bl[2 * p + 1][0], bl[2 * p + 1][1], vbl + off);
                }
#pragma unroll
                for (int dt = 0; dt < 8; dt++) {
                    MMA16816(oacc[dt], pah[s][0], pah[s][1], pah[s][2], pah[s][3], bh[dt][0], bh[dt][1]);
                    MMA16816(oacc[dt], pah[s][0], pah[s][1], pah[s][2], pah[s][3], bl[dt][0], bl[dt][1]);
                    MMA16816(oacc[dt], pal[s][0], pal[s][1], pal[s][2], pal[s][3], bh[dt][0], bh[dt][1]);
                }
            }
        }
        __syncthreads();
    }

    l1 += __shfl_xor_sync(0xffffffff, l1, 1);
    l1 += __shfl_xor_sync(0xffffffff, l1, 2);
    l2 += __shfl_xor_sync(0xffffffff, l2, 1);
    l2 += __shfl_xor_sync(0xffffffff, l2, 2);
    float inv1 = 1.0f / l1, inv2 = 1.0f / l2;

    size_t row1 = qrow0 + warp * 16 + r1;
#pragma unroll
    for (int nt = 0; nt < 8; nt++) {
        int col = h * 64 + nt * 8 + (lane & 3) * 2;
        float o00 = oacc[nt][0] * inv1, o01 = oacc[nt][1] * inv1;
        float o10 = oacc[nt][2] * inv2, o11 = oacc[nt][3] * inv2;
        float r00 = o00 - __bfloat162float(__float2bfloat16_rn(o00));
        float r01 = o01 - __bfloat162float(__float2bfloat16_rn(o01));
        float r10 = o10 - __bfloat162float(__float2bfloat16_rn(o10));
        float r11 = o11 - __bfloat162float(__float2bfloat16_rn(o11));
        *(uint32_t*)&Oh[row1 * Dd + col]       = pack_bf2(o00, o01);
        *(uint32_t*)&Oh[(row1 + 8) * Dd + col] = pack_bf2(o10, o11);
        *(uint32_t*)&Ol[row1 * Dd + col]       = pack_bf2(r00, r01);
        *(uint32_t*)&Ol[(row1 + 8) * Dd + col] = pack_bf2(r10, r11);
    }
}

// ---------------------------------------------------------------------------
extern "C" void kernel_launch(void* const* d_in, const int* in_sizes, int n_in,
                              void* d_out, int out_size) {
    (void)in_sizes; (void)n_in; (void)out_size;

    const float* q    = (const float*)d_in[0];
    const float* k    = (const float*)d_in[1];
    const float* v    = (const float*)d_in[2];
    const int*   mask = (const int*)d_in[3];
    const float* WQw  = (const float*)d_in[4];
    const float* WQb  = (const float*)d_in[5];
    const float* WKw  = (const float*)d_in[6];
    const float* WKb  = (const float*)d_in[7];
    const float* WVw  = (const float*)d_in[8];
    const float* WVb  = (const float*)d_in[9];
    const float* WOw  = (const float*)d_in[10];
    const float* WOb  = (const float*)d_in[11];
    float* out = (float*)d_out;

    __nv_bfloat16 *qh, *ql, *kh, *kl, *vh, *vl;
    __nv_bfloat16 *Qh, *Ql, *Kh, *Kl, *Vh, *Vl, *AOh, *AOl;
    __nv_bfloat16 *WQh, *WQl, *WKh, *WKl, *WVh, *WVl, *WOh, *WOl;
    uint32_t* Mb;
    cudaGetSymbolAddress((void**)&qh, g_qh);   cudaGetSymbolAddress((void**)&ql, g_ql);
    cudaGetSymbolAddress((void**)&kh, g_kh);   cudaGetSymbolAddress((void**)&kl, g_kl);
    cudaGetSymbolAddress((void**)&vh, g_vh);   cudaGetSymbolAddress((void**)&vl, g_vl);
    cudaGetSymbolAddress((void**)&Qh, g_Qh);   cudaGetSymbolAddress((void**)&Ql, g_Ql);
    cudaGetSymbolAddress((void**)&Kh, g_Kh);   cudaGetSymbolAddress((void**)&Kl, g_Kl);
    cudaGetSymbolAddress((void**)&Vh, g_Vh);   cudaGetSymbolAddress((void**)&Vl, g_Vl);
    cudaGetSymbolAddress((void**)&AOh, g_AOh); cudaGetSymbolAddress((void**)&AOl, g_AOl);
    cudaGetSymbolAddress((void**)&WQh, g_WQh); cudaGetSymbolAddress((void**)&WQl, g_WQl);
    cudaGetSymbolAddress((void**)&WKh, g_WKh); cudaGetSymbolAddress((void**)&WKl, g_WKl);
    cudaGetSymbolAddress((void**)&WVh, g_WVh); cudaGetSymbolAddress((void**)&WVl, g_WVl);
    cudaGetSymbolAddress((void**)&WOh, g_WOh); cudaGetSymbolAddress((void**)&WOl, g_WOl);
    cudaGetSymbolAddress((void**)&Mb, g_mbits);

    cudaFuncSetAttribute(gemm_sp<1>, cudaFuncAttributeMaxDynamicSharedMemorySize, GSMEM);
    cudaFuncSetAttribute(gemm_sp<0>, cudaFuncAttributeMaxDynamicSharedMemorySize, GSMEM);

    pack_mask<<<(Bb * Ss * (Ss / 32)) / 256, 256>>>(mask, Mb);

    const int nTok = Bb * Ss * Dd;
    const int nW   = Dd * Dd;
    split_f32<<<nTok / 1024, 256>>>(q, qh, ql);
    split_f32<<<nTok / 1024, 256>>>(k, kh, kl);
    split_f32<<<nTok / 1024, 256>>>(v, vh, vl);
    split_f32<<<nW / 1024, 256>>>(WQw, WQh, WQl);
    split_f32<<<nW / 1024, 256>>>(WKw, WKh, WKl);
    split_f32<<<nW / 1024, 256>>>(WVw, WVh, WVl);
    split_f32<<<nW / 1024, 256>>>(WOw, WOh, WOl);

    dim3 gg(Dd / 128, (Bb * Ss) / 128);  // (8, 64)
    gemm_sp<1><<<gg, 256, GSMEM>>>(qh, ql, WQh, WQl, WQb, nullptr, Qh, Ql);
    gemm_sp<1><<<gg, 256, GSMEM>>>(kh, kl, WKh, WKl, WKb, nullptr, Kh, Kl);
    gemm_sp<1><<<gg, 256, GSMEM>>>(vh, vl, WVh, WVl, WVb, nullptr, Vh, Vl);

    attn_tc<<<dim3(Ss / 128, Hh, Bb), 256>>>(Qh, Ql, Kh, Kl, Vh, Vl, Mb, AOh, AOl);

    gemm_sp<0><<<gg, 256, GSMEM>>>(AOh, AOl, WOh, WOl, WOb, out, nullptr, nullptr);
}

// round 9
// speedup vs baseline: 2.8693x; 1.0188x over previous
#include <cuda_runtime.h>
#include <cuda_bf16.h>
#include <math.h>
#include <cstdint>

#define Bb 8
#define Ss 1024
#define Dd 1024
#define Hh 16
#define DKk 64

// ---- Scratch (all split bf16 hi/lo) ----
__device__ __nv_bfloat16 g_qh[(size_t)Bb * Ss * Dd], g_ql[(size_t)Bb * Ss * Dd];
__device__ __nv_bfloat16 g_kh[(size_t)Bb * Ss * Dd], g_kl[(size_t)Bb * Ss * Dd];
__device__ __nv_bfloat16 g_vh[(size_t)Bb * Ss * Dd], g_vl[(size_t)Bb * Ss * Dd];
__device__ __nv_bfloat16 g_Qh[(size_t)Bb * Ss * Dd], g_Ql[(size_t)Bb * Ss * Dd];
__device__ __nv_bfloat16 g_Kh[(size_t)Bb * Ss * Dd], g_Kl[(size_t)Bb * Ss * Dd];
__device__ __nv_bfloat16 g_Vh[(size_t)Bb * Ss * Dd], g_Vl[(size_t)Bb * Ss * Dd];
__device__ __nv_bfloat16 g_AOh[(size_t)Bb * Ss * Dd], g_AOl[(size_t)Bb * Ss * Dd];
__device__ __nv_bfloat16 g_WQh[Dd * Dd], g_WQl[Dd * Dd];
__device__ __nv_bfloat16 g_WKh[Dd * Dd], g_WKl[Dd * Dd];
__device__ __nv_bfloat16 g_WVh[Dd * Dd], g_WVl[Dd * Dd];
__device__ __nv_bfloat16 g_WOh[Dd * Dd], g_WOl[Dd * Dd];
__device__ uint32_t g_mbits[(size_t)Bb * Ss * (Ss / 32)];

#define LDSM4(r0, r1, r2, r3, addr)                                          \
    asm volatile("ldmatrix.sync.aligned.m8n8.x4.shared.b16 {%0,%1,%2,%3}, [%4];" \
                 : "=r"(r0), "=r"(r1), "=r"(r2), "=r"(r3) : "r"(addr))

#define MMA16816(d, a0, a1, a2, a3, b0, b1)                                  \
    asm volatile(                                                            \
        "mma.sync.aligned.m16n8k16.row.col.f32.bf16.bf16.f32 "               \
        "{%0,%1,%2,%3}, {%4,%5,%6,%7}, {%8,%9}, {%0,%1,%2,%3};"              \
        : "+f"(d[0]), "+f"(d[1]), "+f"(d[2]), "+f"(d[3])                     \
        : "r"(a0), "r"(a1), "r"(a2), "r"(a3), "r"(b0), "r"(b1))

#define CP16(dst, src)                                                       \
    asm volatile("cp.async.cg.shared.global [%0], [%1], 16;" ::"r"(dst), "l"(src))
#define CP_COMMIT asm volatile("cp.async.commit_group;")
#define CP_WAIT1  asm volatile("cp.async.wait_group 1;")
#define CP_WAIT0  asm volatile("cp.async.wait_group 0;")

__device__ __forceinline__ uint32_t pack_bf2(float a, float b) {
    __nv_bfloat162 t = __floats2bfloat162_rn(a, b);
    return *(uint32_t*)&t;
}

// ---------------------------------------------------------------------------
// fp32 -> split bf16 (hi = rn(x), lo = rn(x - hi)).
// ---------------------------------------------------------------------------
__global__ void split_f32(const float* __restrict__ in,
                          __nv_bfloat16* __restrict__ hi,
                          __nv_bfloat16* __restrict__ lo) {
    size_t i = ((size_t)blockIdx.x * 256 + threadIdx.x) * 4;
    float4 v = *(const float4*)(in + i);
    float r0 = v.x - __bfloat162float(__float2bfloat16_rn(v.x));
    float r1 = v.y - __bfloat162float(__float2bfloat16_rn(v.y));
    float r2 = v.z - __bfloat162float(__float2bfloat16_rn(v.z));
    float r3 = v.w - __bfloat162float(__float2bfloat16_rn(v.w));
    *(uint2*)(hi + i) = make_uint2(pack_bf2(v.x, v.y), pack_bf2(v.z, v.w));
    *(uint2*)(lo + i) = make_uint2(pack_bf2(r0, r1), pack_bf2(r2, r3));
}

__global__ void pack_mask(const int* __restrict__ mask, uint32_t* __restrict__ bits) {
    size_t w = (size_t)blockIdx.x * 256 + threadIdx.x;
    const int* p = mask + w * 32;
    uint32_t v = 0;
#pragma unroll
    for (int i = 0; i < 32; i += 4) {
        int4 t = *(const int4*)(p + i);
        v |= (uint32_t)(t.x != 0) << i;
        v |= (uint32_t)(t.y != 0) << (i + 1);
        v |= (uint32_t)(t.z != 0) << (i + 2);
        v |= (uint32_t)(t.w != 0) << (i + 3);
    }
    bits[w] = v;
}

// ---------------------------------------------------------------------------
// Pipelined split-bf16 GEMM (unchanged from R8: 2-stage cp.async, 2 CTAs/SM).
// ---------------------------------------------------------------------------
struct GStage {
    __nv_bfloat16 ah[128][40];
    __nv_bfloat16 al[128][40];
    __nv_bfloat16 bh[128][40];
    __nv_bfloat16 bl[128][40];
};
#define AH_OFF 0
#define AL_OFF 10240
#define BH_OFF 20480
#define BL_OFF 30720
#define GSMEM (2u * sizeof(GStage))  // 81920

template <int SPLIT_OUT>
__global__ __launch_bounds__(256, 2) void gemm_sp(
    const __nv_bfloat16* __restrict__ Ahg, const __nv_bfloat16* __restrict__ Alg,
    const __nv_bfloat16* __restrict__ Bhg, const __nv_bfloat16* __restrict__ Blg,
    const float* __restrict__ bias, float* __restrict__ Y,
    __nv_bfloat16* __restrict__ Yh, __nv_bfloat16* __restrict__ Yl) {
    const int K = 1024, N = 1024;
    extern __shared__ char smem_raw[];
    const uint32_t smem_base = (uint32_t)__cvta_generic_to_shared(smem_raw);

    const int tid  = threadIdx.x;
    const int lane = tid & 31;
    const int warp = tid >> 5;
    const int wm   = warp >> 1;
    const int wn   = warp & 1;

    const int ldRow = tid >> 1;
    const int ldCE  = (tid & 1) * 16;
    const size_t gA = (size_t)(blockIdx.y * 128 + ldRow) * K + ldCE;
    const size_t gB = (size_t)(blockIdx.x * 128 + ldRow) * K + ldCE;
    const uint32_t dRow = ldRow * 80 + ldCE * 2;

    const int rb = ((lane >> 4) << 3) + (lane & 7);
    const int cb = ((lane >> 3) & 1) * 8;
    uint32_t aoff[2][2], boff[4][2];
#pragma unroll
    for (int mt = 0; mt < 2; mt++)
#pragma unroll
        for (int kk = 0; kk < 2; kk++)
            aoff[mt][kk] = (uint32_t)((wm * 32 + mt * 16 + (lane & 15)) * 80 +
                                      (lane >> 4) * 16 + kk * 32);
#pragma unroll
    for (int p = 0; p < 4; p++)
#pragma unroll
        for (int kk = 0; kk < 2; kk++)
            boff[p][kk] = (uint32_t)((wn * 64 + p * 16 + rb) * 80 + cb * 2 + kk * 32);

    float acc[2][8][4];
#pragma unroll
    for (int mt = 0; mt < 2; mt++)
#pragma unroll
        for (int nt = 0; nt < 8; nt++)
#pragma unroll
            for (int i = 0; i < 4; i++) acc[mt][nt][i] = 0.0f;

    auto load_stage = [&](int s, int k0) {
        uint32_t b = smem_base + (uint32_t)s * sizeof(GStage) + dRow;
        CP16(b + AH_OFF,      Ahg + gA + k0);
        CP16(b + AH_OFF + 16, Ahg + gA + k0 + 8);
        CP16(b + AL_OFF,      Alg + gA + k0);
        CP16(b + AL_OFF + 16, Alg + gA + k0 + 8);
        CP16(b + BH_OFF,      Bhg + gB + k0);
        CP16(b + BH_OFF + 16, Bhg + gB + k0 + 8);
        CP16(b + BL_OFF,      Blg + gB + k0);
        CP16(b + BL_OFF + 16, Blg + gB + k0 + 8);
    };

    load_stage(0, 0); CP_COMMIT;

    const int NK = K / 32;  // 32
    for (int i = 0; i < NK; i++) {
        if (i + 1 < NK) {
            load_stage((i + 1) & 1, (i + 1) * 32);
            CP_COMMIT;
            CP_WAIT1;
        } else {
            CP_WAIT0;
        }
        __syncthreads();

        const uint32_t sb = smem_base + (uint32_t)(i & 1) * sizeof(GStage);
#pragma unroll
        for (int kk = 0; kk < 2; kk++) {
            uint32_t bh[8][2], bl[8][2];
#pragma unroll
            for (int p = 0; p < 4; p++) {
                LDSM4(bh[2 * p][0], bh[2 * p][1], bh[2 * p + 1][0], bh[2 * p + 1][1],
                      sb + BH_OFF + boff[p][kk]);
                LDSM4(bl[2 * p][0], bl[2 * p][1], bl[2 * p + 1][0], bl[2 * p + 1][1],
                      sb + BL_OFF + boff[p][kk]);
            }
#pragma unroll
            for (int mt = 0; mt < 2; mt++) {
                uint32_t ah[4], al[4];
                LDSM4(ah[0], ah[1], ah[2], ah[3], sb + AH_OFF + aoff[mt][kk]);
                LDSM4(al[0], al[1], al[2], al[3], sb + AL_OFF + aoff[mt][kk]);
#pragma unroll
                for (int nt = 0; nt < 8; nt++)
                    MMA16816(acc[mt][nt], ah[0], ah[1], ah[2], ah[3], bh[nt][0], bh[nt][1]);
#pragma unroll
                for (int nt = 0; nt < 8; nt++)
                    MMA16816(acc[mt][nt], ah[0], ah[1], ah[2], ah[3], bl[nt][0], bl[nt][1]);
#pragma unroll
                for (int nt = 0; nt < 8; nt++)
                    MMA16816(acc[mt][nt], al[0], al[1], al[2], al[3], bh[nt][0], bh[nt][1]);
            }
        }
        __syncthreads();
    }

    const int rowBase = blockIdx.y * 128 + wm * 32;
    const int colBase = blockIdx.x * 128 + wn * 64;
#pragma unroll
    for (int mt = 0; mt < 2; mt++) {
        int row = rowBase + mt * 16 + (lane >> 2);
#pragma unroll
        for (int nt = 0; nt < 8; nt++) {
            int col = colBase + nt * 8 + (lane & 3) * 2;
            float2 bv = *(const float2*)&bias[col];
            float o00 = acc[mt][nt][0] + bv.x, o01 = acc[mt][nt][1] + bv.y;
            float o10 = acc[mt][nt][2] + bv.x, o11 = acc[mt][nt][3] + bv.y;
            if (SPLIT_OUT) {
                float r00 = o00 - __bfloat162float(__float2bfloat16_rn(o00));
                float r01 = o01 - __bfloat162float(__float2bfloat16_rn(o01));
                float r10 = o10 - __bfloat162float(__float2bfloat16_rn(o10));
                float r11 = o11 - __bfloat162float(__float2bfloat16_rn(o11));
                *(uint32_t*)&Yh[(size_t)row * N + col]       = pack_bf2(o00, o01);
                *(uint32_t*)&Yh[(size_t)(row + 8) * N + col] = pack_bf2(o10, o11);
                *(uint32_t*)&Yl[(size_t)row * N + col]       = pack_bf2(r00, r01);
                *(uint32_t*)&Yl[(size_t)(row + 8) * N + col] = pack_bf2(r10, r11);
            } else {
                *(float2*)&Y[(size_t)row * N + col]       = make_float2(o00, o01);
                *(float2*)&Y[(size_t)(row + 8) * N + col] = make_float2(o10, o11);
            }
        }
    }
}

// ---------------------------------------------------------------------------
// Tensor-core flash attention. R9: 64 q-rows / 4 warps / 128 threads per CTA,
// launch_bounds(128,3) -> 3 CTAs (12 warps)/SM. Per-warp layout unchanged.
// ---------------------------------------------------------------------------
struct QStage { __nv_bfloat16 h[64][72], l[64][72]; };
struct KVStage {
    __nv_bfloat16 kh[64][72], kl[64][72];
    __nv_bfloat16 vth[64][72], vtl[64][72];
    uint32_t mw[64][2];
};

__global__ __launch_bounds__(128, 3) void attn_tc(
    const __nv_bfloat16* __restrict__ Qh, const __nv_bfloat16* __restrict__ Ql,
    const __nv_bfloat16* __restrict__ Kh, const __nv_bfloat16* __restrict__ Kl,
    const __nv_bfloat16* __restrict__ Vh, const __nv_bfloat16* __restrict__ Vl,
    const uint32_t* __restrict__ mbits,
    __nv_bfloat16* __restrict__ Oh, __nv_bfloat16* __restrict__ Ol) {
    const int qt = blockIdx.x, h = blockIdx.y, b = blockIdx.z;
    const int tid = threadIdx.x, lane = tid & 31, warp = tid >> 5;
    const float SC = 0.125f * 1.44269504f;

    __shared__ union { QStage q; KVStage kv; } sm;

    const size_t qrow0 = (size_t)b * Ss + qt * 64;

    // ---- Stage Q tile (64 rows), ldmatrix Q fragments to registers.
    {
        int r = tid >> 1, half = tid & 1;  // 2 threads/row, 32 halves each
        const uint4* gh = (const uint4*)(Qh + (qrow0 + r) * Dd + h * 64 + half * 32);
        const uint4* gl = (const uint4*)(Ql + (qrow0 + r) * Dd + h * 64 + half * 32);
        uint4* sh = (uint4*)&sm.q.h[r][half * 32];
        uint4* sl = (uint4*)&sm.q.l[r][half * 32];
#pragma unroll
        for (int i = 0; i < 4; i++) { sh[i] = gh[i]; sl[i] = gl[i]; }
    }
    __syncthreads();

    uint32_t qfh[4][4], qfl[4][4];
    {
        uint32_t bqh = (uint32_t)__cvta_generic_to_shared(&sm.q.h[0][0]);
        uint32_t bql = (uint32_t)__cvta_generic_to_shared(&sm.q.l[0][0]);
        int r = warp * 16 + (lane & 15);
#pragma unroll
        for (int s = 0; s < 4; s++) {
            uint32_t off = (uint32_t)((r * 72 + s * 16 + (lane >> 4) * 8) * 2);
            LDSM4(qfh[s][0], qfh[s][1], qfh[s][2], qfh[s][3], bqh + off);
            LDSM4(qfl[s][0], qfl[s][1], qfl[s][2], qfl[s][3], bql + off);
        }
    }
    __syncthreads();

    float oacc[8][4];
#pragma unroll
    for (int nt = 0; nt < 8; nt++)
#pragma unroll
        for (int i = 0; i < 4; i++) oacc[nt][i] = 0.0f;
    float m1 = -1e30f, m2 = -1e30f, l1 = 0.0f, l2 = 0.0f;

    const int rb = ((lane >> 4) << 3) + (lane & 7);
    const int cb = ((lane >> 3) & 1) * 8;
    const int r1 = lane >> 2;

    for (int kt = 0; kt < 16; kt++) {
        // ---- Load K (straight) + V (transposed) tiles + mask words.
        {
            int r = tid >> 1, h2 = tid & 1;  // 2 threads/row, 32 halves each
            size_t g = ((size_t)b * Ss + kt * 64 + r) * Dd + h * 64 + h2 * 32;
#pragma unroll
            for (int i = 0; i < 4; i++) {
                *(uint4*)&sm.kv.kh[r][h2 * 32 + 8 * i] = *(const uint4*)(Kh + g + 8 * i);
                *(uint4*)&sm.kv.kl[r][h2 * 32 + 8 * i] = *(const uint4*)(Kl + g + 8 * i);
            }
            union { uint4 v[4]; __nv_bfloat16 e[32]; } th, tl;
#pragma unroll
            for (int i = 0; i < 4; i++) {
                th.v[i] = *(const uint4*)(Vh + g + 8 * i);
                tl.v[i] = *(const uint4*)(Vl + g + 8 * i);
            }
#pragma unroll
            for (int i = 0; i < 32; i++) {
                sm.kv.vth[h2 * 32 + i][r] = th.e[i];
                sm.kv.vtl[h2 * 32 + i][r] = tl.e[i];
            }
            sm.kv.mw[r][h2] = mbits[(qrow0 + r) * 32 + kt * 2 + h2];
        }
        __syncthreads();

        // ---- S = Q K^T (split, 3 passes), fp32 accum.
        float sacc[8][4];
#pragma unroll
        for (int nt = 0; nt < 8; nt++)
#pragma unroll
            for (int i = 0; i < 4; i++) sacc[nt][i] = 0.0f;
        {
            uint32_t kbh = (uint32_t)__cvta_generic_to_shared(&sm.kv.kh[0][0]);
            uint32_t kbl = (uint32_t)__cvta_generic_to_shared(&sm.kv.kl[0][0]);
#pragma unroll
            for (int s = 0; s < 4; s++) {
                uint32_t bh[8][2], bl[8][2];
#pragma unroll
                for (int p = 0; p < 4; p++) {
                    uint32_t off = (uint32_t)(((p * 16 + rb) * 72 + s * 16 + cb) * 2);
                    LDSM4(bh[2 * p][0], bh[2 * p][1], bh[2 * p + 1][0], bh[2 * p + 1][1], kbh + off);
                    LDSM4(bl[2 * p][0], bl[2 * p][1], bl[2 * p + 1][0], bl[2 * p + 1][1], kbl + off);
                }
#pragma unroll
                for (int nt = 0; nt < 8; nt++) {
                    MMA16816(sacc[nt], qfh[s][0], qfh[s][1], qfh[s][2], qfh[s][3], bh[nt][0], bh[nt][1]);
                    MMA16816(sacc[nt], qfh[s][0], qfh[s][1], qfh[s][2], qfh[s][3], bl[nt][0], bl[nt][1]);
                    MMA16816(sacc[nt], qfl[s][0], qfl[s][1], qfl[s][2], qfl[s][3], bh[nt][0], bh[nt][1]);
                }
            }
        }

        // ---- Scale, mask, row max.
        uint32_t w10 = sm.kv.mw[warp * 16 + r1][0];
        uint32_t w11 = sm.kv.mw[warp * 16 + r1][1];
        uint32_t w20 = sm.kv.mw[warp * 16 + r1 + 8][0];
        uint32_t w21 = sm.kv.mw[warp * 16 + r1 + 8][1];
        float tm1 = -1e30f, tm2 = -1e30f;
#pragma unroll
        for (int nt = 0; nt < 8; nt++) {
            int cbase = nt * 8 + (lane & 3) * 2;
            uint32_t wA = (nt < 4) ? w10 : w11;
            uint32_t wB = (nt < 4) ? w20 : w21;
            int shf = cbase & 31;
            float s0 = sacc[nt][0] * SC, s1 = sacc[nt][1] * SC;
            float s2 = sacc[nt][2] * SC, s3 = sacc[nt][3] * SC;
            if (!((wA >> shf) & 1))       s0 = -1e9f;
            if (!((wA >> (shf + 1)) & 1)) s1 = -1e9f;
            if (!((wB >> shf) & 1))       s2 = -1e9f;
            if (!((wB >> (shf + 1)) & 1)) s3 = -1e9f;
            sacc[nt][0] = s0; sacc[nt][1] = s1; sacc[nt][2] = s2; sacc[nt][3] = s3;
            tm1 = fmaxf(tm1, fmaxf(s0, s1));
            tm2 = fmaxf(tm2, fmaxf(s2, s3));
        }
        tm1 = fmaxf(tm1, __shfl_xor_sync(0xffffffff, tm1, 1));
        tm1 = fmaxf(tm1, __shfl_xor_sync(0xffffffff, tm1, 2));
        tm2 = fmaxf(tm2, __shfl_xor_sync(0xffffffff, tm2, 1));
        tm2 = fmaxf(tm2, __shfl_xor_sync(0xffffffff, tm2, 2));

        float mn1 = fmaxf(m1, tm1), mn2 = fmaxf(m2, tm2);
        float a1 = exp2f(m1 - mn1), a2 = exp2f(m2 - mn2);
        m1 = mn1; m2 = mn2;
        l1 *= a1; l2 *= a2;
#pragma unroll
        for (int nt = 0; nt < 8; nt++) {
            oacc[nt][0] *= a1; oacc[nt][1] *= a1;
            oacc[nt][2] *= a2; oacc[nt][3] *= a2;
        }

        // ---- p = exp2(s - m); split hi/lo; pack as A fragments.
        uint32_t pah[4][4], pal[4][4];
#pragma unroll
        for (int nt = 0; nt < 8; nt++) {
            float p0 = exp2f(sacc[nt][0] - m1), p1 = exp2f(sacc[nt][1] - m1);
            float p2 = exp2f(sacc[nt][2] - m2), p3 = exp2f(sacc[nt][3] - m2);
            l1 += p0 + p1; l2 += p2 + p3;
            __nv_bfloat16 h0 = __float2bfloat16_rn(p0), h1 = __float2bfloat16_rn(p1);
            __nv_bfloat16 h2 = __float2bfloat16_rn(p2), h3 = __float2bfloat16_rn(p3);
            int s = nt >> 1, base = (nt & 1) * 2;
            pah[s][base]     = pack_bf2(p0, p1);
            pah[s][base + 1] = pack_bf2(p2, p3);
            pal[s][base]     = pack_bf2(p0 - __bfloat162float(h0), p1 - __bfloat162float(h1));
            pal[s][base + 1] = pack_bf2(p2 - __bfloat162float(h2), p3 - __bfloat162float(h3));
        }

        // ---- O += P V (split, 3 passes).
        {
            uint32_t vbh = (uint32_t)__cvta_generic_to_shared(&sm.kv.vth[0][0]);
            uint32_t vbl = (uint32_t)__cvta_generic_to_shared(&sm.kv.vtl[0][0]);
#pragma unroll
            for (int s = 0; s < 4; s++) {
                uint32_t bh[8][2], bl[8][2];
#pragma unroll
                for (int p = 0; p < 4; p++) {
                    uint32_t off = (uint32_t)(((p * 16 + rb) * 72 + s * 16 + cb) * 2);
                    LDSM4(bh[2 * p][0], bh[2 * p][1], bh[2 * p + 1][0], bh[2 * p + 1][1], vbh + off);
                    LDSM4(bl[2 * p][0], bl[2 * p][1], bl[2 * p + 1][0], bl[2 * p + 1][1], vbl + off);
                }
#pragma unroll
                for (int dt = 0; dt < 8; dt++) {
                    MMA16816(oacc[dt], pah[s][0], pah[s][1], pah[s][2], pah[s][3], bh[dt][0], bh[dt][1]);
                    MMA16816(oacc[dt], pah[s][0], pah[s][1], pah[s][2], pah[s][3], bl[dt][0], bl[dt][1]);
                    MMA16816(oacc[dt], pal[s][0], pal[s][1], pal[s][2], pal[s][3], bh[dt][0], bh[dt][1]);
                }
            }
        }
        __syncthreads();
    }

    l1 += __shfl_xor_sync(0xffffffff, l1, 1);
    l1 += __shfl_xor_sync(0xffffffff, l1, 2);
    l2 += __shfl_xor_sync(0xffffffff, l2, 1);
    l2 += __shfl_xor_sync(0xffffffff, l2, 2);
    float inv1 = 1.0f / l1, inv2 = 1.0f / l2;

    size_t row1 = qrow0 + warp * 16 + r1;
#pragma unroll
    for (int nt = 0; nt < 8; nt++) {
        int col = h * 64 + nt * 8 + (lane & 3) * 2;
        float o00 = oacc[nt][0] * inv1, o01 = oacc[nt][1] * inv1;
        float o10 = oacc[nt][2] * inv2, o11 = oacc[nt][3] * inv2;
        float r00 = o00 - __bfloat162float(__float2bfloat16_rn(o00));
        float r01 = o01 - __bfloat162float(__float2bfloat16_rn(o01));
        float r10 = o10 - __bfloat162float(__float2bfloat16_rn(o10));
        float r11 = o11 - __bfloat162float(__float2bfloat16_rn(o11));
        *(uint32_t*)&Oh[row1 * Dd + col]       = pack_bf2(o00, o01);
        *(uint32_t*)&Oh[(row1 + 8) * Dd + col] = pack_bf2(o10, o11);
        *(uint32_t*)&Ol[row1 * Dd + col]       = pack_bf2(r00, r01);
        *(uint32_t*)&Ol[(row1 + 8) * Dd + col] = pack_bf2(r10, r11);
    }
}

// ---------------------------------------------------------------------------
extern "C" void kernel_launch(void* const* d_in, const int* in_sizes, int n_in,
                              void* d_out, int out_size) {
    (void)in_sizes; (void)n_in; (void)out_size;

    const float* q    = (const float*)d_in[0];
    const float* k    = (const float*)d_in[1];
    const float* v    = (const float*)d_in[2];
    const int*   mask = (const int*)d_in[3];
    const float* WQw  = (const float*)d_in[4];
    const float* WQb  = (const float*)d_in[5];
    const float* WKw  = (const float*)d_in[6];
    const float* WKb  = (const float*)d_in[7];
    const float* WVw  = (const float*)d_in[8];
    const float* WVb  = (const float*)d_in[9];
    const float* WOw  = (const float*)d_in[10];
    const float* WOb  = (const float*)d_in[11];
    float* out = (float*)d_out;

    __nv_bfloat16 *qh, *ql, *kh, *kl, *vh, *vl;
    __nv_bfloat16 *Qh, *Ql, *Kh, *Kl, *Vh, *Vl, *AOh, *AOl;
    __nv_bfloat16 *WQh, *WQl, *WKh, *WKl, *WVh, *WVl, *WOh, *WOl;
    uint32_t* Mb;
    cudaGetSymbolAddress((void**)&qh, g_qh);   cudaGetSymbolAddress((void**)&ql, g_ql);
    cudaGetSymbolAddress((void**)&kh, g_kh);   cudaGetSymbolAddress((void**)&kl, g_kl);
    cudaGetSymbolAddress((void**)&vh, g_vh);   cudaGetSymbolAddress((void**)&vl, g_vl);
    cudaGetSymbolAddress((void**)&Qh, g_Qh);   cudaGetSymbolAddress((void**)&Ql, g_Ql);
    cudaGetSymbolAddress((void**)&Kh, g_Kh);   cudaGetSymbolAddress((void**)&Kl, g_Kl);
    cudaGetSymbolAddress((void**)&Vh, g_Vh);   cudaGetSymbolAddress((void**)&Vl, g_Vl);
    cudaGetSymbolAddress((void**)&AOh, g_AOh); cudaGetSymbolAddress((void**)&AOl, g_AOl);
    cudaGetSymbolAddress((void**)&WQh, g_WQh); cudaGetSymbolAddress((void**)&WQl, g_WQl);
    cudaGetSymbolAddress((void**)&WKh, g_WKh); cudaGetSymbolAddress((void**)&WKl, g_WKl);
    cudaGetSymbolAddress((void**)&WVh, g_WVh); cudaGetSymbolAddress((void**)&WVl, g_WVl);
    cudaGetSymbolAddress((void**)&WOh, g_WOh); cudaGetSymbolAddress((void**)&WOl, g_WOl);
    cudaGetSymbolAddress((void**)&Mb, g_mbits);

    cudaFuncSetAttribute(gemm_sp<1>, cudaFuncAttributeMaxDynamicSharedMemorySize, GSMEM);
    cudaFuncSetAttribute(gemm_sp<0>, cudaFuncAttributeMaxDynamicSharedMemorySize, GSMEM);

    pack_mask<<<(Bb * Ss * (Ss / 32)) / 256, 256>>>(mask, Mb);

    const int nTok = Bb * Ss * Dd;
    const int nW   = Dd * Dd;
    split_f32<<<nTok / 1024, 256>>>(q, qh, ql);
    split_f32<<<nTok / 1024, 256>>>(k, kh, kl);
    split_f32<<<nTok / 1024, 256>>>(v, vh, vl);
    split_f32<<<nW / 1024, 256>>>(WQw, WQh, WQl);
    split_f32<<<nW / 1024, 256>>>(WKw, WKh, WKl);
    split_f32<<<nW / 1024, 256>>>(WVw, WVh, WVl);
    split_f32<<<nW / 1024, 256>>>(WOw, WOh, WOl);

    dim3 gg(Dd / 128, (Bb * Ss) / 128);  // (8, 64)
    gemm_sp<1><<<gg, 256, GSMEM>>>(qh, ql, WQh, WQl, WQb, nullptr, Qh, Ql);
    gemm_sp<1><<<gg, 256, GSMEM>>>(kh, kl, WKh, WKl, WKb, nullptr, Kh, Kl);
    gemm_sp<1><<<gg, 256, GSMEM>>>(vh, vl, WVh, WVl, WVb, nullptr, Vh, Vl);

    attn_tc<<<dim3(Ss / 64, Hh, Bb), 128>>>(Qh, Ql, Kh, Kl, Vh, Vl, Mb, AOh, AOl);

    gemm_sp<0><<<gg, 256, GSMEM>>>(AOh, AOl, WOh, WOl, WOb, out, nullptr, nullptr);
}

// round 10
// speedup vs baseline: 4.3496x; 1.5159x over previous
#include <cuda_runtime.h>
#include <cuda_fp16.h>
#include <math.h>
#include <cstdint>

#define Bb 8
#define Ss 1024
#define Dd 1024
#define Hh 16
#define DKk 64

// ---- Scratch ----
// Activations split (hi+lo fp16); weights / K / V hi-only fp16.
__device__ __half g_qh[(size_t)Bb * Ss * Dd], g_ql[(size_t)Bb * Ss * Dd];
__device__ __half g_kh[(size_t)Bb * Ss * Dd], g_kl[(size_t)Bb * Ss * Dd];
__device__ __half g_vh[(size_t)Bb * Ss * Dd], g_vl[(size_t)Bb * Ss * Dd];
__device__ __half g_Qh[(size_t)Bb * Ss * Dd], g_Ql[(size_t)Bb * Ss * Dd];
__device__ __half g_Kh[(size_t)Bb * Ss * Dd];
__device__ __half g_Vh[(size_t)Bb * Ss * Dd];
__device__ __half g_AOh[(size_t)Bb * Ss * Dd], g_AOl[(size_t)Bb * Ss * Dd];
__device__ __half g_WQh[Dd * Dd], g_WKh[Dd * Dd], g_WVh[Dd * Dd], g_WOh[Dd * Dd];
__device__ uint32_t g_mbits[(size_t)Bb * Ss * (Ss / 32)];

#define LDSM4(r0, r1, r2, r3, addr)                                          \
    asm volatile("ldmatrix.sync.aligned.m8n8.x4.shared.b16 {%0,%1,%2,%3}, [%4];" \
                 : "=r"(r0), "=r"(r1), "=r"(r2), "=r"(r3) : "r"(addr))

#define MMA16816(d, a0, a1, a2, a3, b0, b1)                                  \
    asm volatile(                                                            \
        "mma.sync.aligned.m16n8k16.row.col.f32.f16.f16.f32 "                 \
        "{%0,%1,%2,%3}, {%4,%5,%6,%7}, {%8,%9}, {%0,%1,%2,%3};"              \
        : "+f"(d[0]), "+f"(d[1]), "+f"(d[2]), "+f"(d[3])                     \
        : "r"(a0), "r"(a1), "r"(a2), "r"(a3), "r"(b0), "r"(b1))

#define CP16(dst, src)                                                       \
    asm volatile("cp.async.cg.shared.global [%0], [%1], 16;" ::"r"(dst), "l"(src))
#define CP_COMMIT asm volatile("cp.async.commit_group;")
#define CP_WAIT1  asm volatile("cp.async.wait_group 1;")
#define CP_WAIT0  asm volatile("cp.async.wait_group 0;")

__device__ __forceinline__ uint32_t pack_h2(float a, float b) {
    __half2 t = __floats2half2_rn(a, b);
    return *(uint32_t*)&t;
}

// ---------------------------------------------------------------------------
// fp32 -> split fp16 (hi = rn(x), lo = rn(x - hi)).
// ---------------------------------------------------------------------------
__global__ void split2_f32(const float* __restrict__ in,
                           __half* __restrict__ hi, __half* __restrict__ lo) {
    size_t i = ((size_t)blockIdx.x * 256 + threadIdx.x) * 4;
    float4 v = *(const float4*)(in + i);
    float r0 = v.x - __half2float(__float2half_rn(v.x));
    float r1 = v.y - __half2float(__float2half_rn(v.y));
    float r2 = v.z - __half2float(__float2half_rn(v.z));
    float r3 = v.w - __half2float(__float2half_rn(v.w));
    *(uint2*)(hi + i) = make_uint2(pack_h2(v.x, v.y), pack_h2(v.z, v.w));
    *(uint2*)(lo + i) = make_uint2(pack_h2(r0, r1), pack_h2(r2, r3));
}

// fp32 -> fp16 hi only (weights).
__global__ void quant_f32(const float* __restrict__ in, __half* __restrict__ hi) {
    size_t i = ((size_t)blockIdx.x * 256 + threadIdx.x) * 4;
    float4 v = *(const float4*)(in + i);
    *(uint2*)(hi + i) = make_uint2(pack_h2(v.x, v.y), pack_h2(v.z, v.w));
}

__global__ void pack_mask(const int* __restrict__ mask, uint32_t* __restrict__ bits) {
    size_t w = (size_t)blockIdx.x * 256 + threadIdx.x;
    const int* p = mask + w * 32;
    uint32_t v = 0;
#pragma unroll
    for (int i = 0; i < 32; i += 4) {
        int4 t = *(const int4*)(p + i);
        v |= (uint32_t)(t.x != 0) << i;
        v |= (uint32_t)(t.y != 0) << (i + 1);
        v |= (uint32_t)(t.z != 0) << (i + 2);
        v |= (uint32_t)(t.w != 0) << (i + 3);
    }
    bits[w] = v;
}

// ---------------------------------------------------------------------------
// fp16 2-pass GEMM: Y = A[M,K] @ B[N,K]^T + bias, A split (h+l), B hi-only.
// acc = Ah*Bh + Al*Bh  (== A_exact * fp16(B), error ~2^-12 of one operand).
// 2-stage cp.async, BK=32, 128x128 tile, 256 thr, 2 CTAs/SM.
// OUT_MODE: 0 = f32, 1 = split h+l, 2 = h only.
// ---------------------------------------------------------------------------
struct GStage {
    __half ah[128][40];
    __half al[128][40];
    __half bh[128][40];
};
#define AH_OFF 0
#define AL_OFF 10240
#define BH_OFF 20480
#define GSMEM (2u * sizeof(GStage))  // 61440

template <int OUT_MODE>
__global__ __launch_bounds__(256, 2) void gemm_sp(
    const __half* __restrict__ Ahg, const __half* __restrict__ Alg,
    const __half* __restrict__ Bhg,
    const float* __restrict__ bias, float* __restrict__ Y,
    __half* __restrict__ Yh, __half* __restrict__ Yl) {
    const int K = 1024, N = 1024;
    extern __shared__ char smem_raw[];
    const uint32_t smem_base = (uint32_t)__cvta_generic_to_shared(smem_raw);

    const int tid  = threadIdx.x;
    const int lane = tid & 31;
    const int warp = tid >> 5;
    const int wm   = warp >> 1;
    const int wn   = warp & 1;

    const int ldRow = tid >> 1;
    const int ldCE  = (tid & 1) * 16;
    const size_t gA = (size_t)(blockIdx.y * 128 + ldRow) * K + ldCE;
    const size_t gB = (size_t)(blockIdx.x * 128 + ldRow) * K + ldCE;
    const uint32_t dRow = ldRow * 80 + ldCE * 2;

    const int rb = ((lane >> 4) << 3) + (lane & 7);
    const int cb = ((lane >> 3) & 1) * 8;
    uint32_t aoff[2][2], boff[4][2];
#pragma unroll
    for (int mt = 0; mt < 2; mt++)
#pragma unroll
        for (int kk = 0; kk < 2; kk++)
            aoff[mt][kk] = (uint32_t)((wm * 32 + mt * 16 + (lane & 15)) * 80 +
                                      (lane >> 4) * 16 + kk * 32);
#pragma unroll
    for (int p = 0; p < 4; p++)
#pragma unroll
        for (int kk = 0; kk < 2; kk++)
            boff[p][kk] = (uint32_t)((wn * 64 + p * 16 + rb) * 80 + cb * 2 + kk * 32);

    float acc[2][8][4];
#pragma unroll
    for (int mt = 0; mt < 2; mt++)
#pragma unroll
        for (int nt = 0; nt < 8; nt++)
#pragma unroll
            for (int i = 0; i < 4; i++) acc[mt][nt][i] = 0.0f;

    auto load_stage = [&](int s, int k0) {
        uint32_t b = smem_base + (uint32_t)s * sizeof(GStage) + dRow;
        CP16(b + AH_OFF,      Ahg + gA + k0);
        CP16(b + AH_OFF + 16, Ahg + gA + k0 + 8);
        CP16(b + AL_OFF,      Alg + gA + k0);
        CP16(b + AL_OFF + 16, Alg + gA + k0 + 8);
        CP16(b + BH_OFF,      Bhg + gB + k0);
        CP16(b + BH_OFF + 16, Bhg + gB + k0 + 8);
    };

    load_stage(0, 0); CP_COMMIT;

    const int NK = K / 32;  // 32
    for (int i = 0; i < NK; i++) {
        if (i + 1 < NK) {
            load_stage((i + 1) & 1, (i + 1) * 32);
            CP_COMMIT;
            CP_WAIT1;
        } else {
            CP_WAIT0;
        }
        __syncthreads();

        const uint32_t sb = smem_base + (uint32_t)(i & 1) * sizeof(GStage);
#pragma unroll
        for (int kk = 0; kk < 2; kk++) {
            uint32_t bh[8][2];
#pragma unroll
            for (int p = 0; p < 4; p++)
                LDSM4(bh[2 * p][0], bh[2 * p][1], bh[2 * p + 1][0], bh[2 * p + 1][1],
                      sb + BH_OFF + boff[p][kk]);
#pragma unroll
            for (int mt = 0; mt < 2; mt++) {
                uint32_t ah[4], al[4];
                LDSM4(ah[0], ah[1], ah[2], ah[3], sb + AH_OFF + aoff[mt][kk]);
                LDSM4(al[0], al[1], al[2], al[3], sb + AL_OFF + aoff[mt][kk]);
#pragma unroll
                for (int nt = 0; nt < 8; nt++)
                    MMA16816(acc[mt][nt], ah[0], ah[1], ah[2], ah[3], bh[nt][0], bh[nt][1]);
#pragma unroll
                for (int nt = 0; nt < 8; nt++)
                    MMA16816(acc[mt][nt], al[0], al[1], al[2], al[3], bh[nt][0], bh[nt][1]);
            }
        }
        __syncthreads();
    }

    const int rowBase = blockIdx.y * 128 + wm * 32;
    const int colBase = blockIdx.x * 128 + wn * 64;
#pragma unroll
    for (int mt = 0; mt < 2; mt++) {
        int row = rowBase + mt * 16 + (lane >> 2);
#pragma unroll
        for (int nt = 0; nt < 8; nt++) {
            int col = colBase + nt * 8 + (lane & 3) * 2;
            float2 bv = *(const float2*)&bias[col];
            float o00 = acc[mt][nt][0] + bv.x, o01 = acc[mt][nt][1] + bv.y;
            float o10 = acc[mt][nt][2] + bv.x, o11 = acc[mt][nt][3] + bv.y;
            if (OUT_MODE == 1) {
                float r00 = o00 - __half2float(__float2half_rn(o00));
                float r01 = o01 - __half2float(__float2half_rn(o01));
                float r10 = o10 - __half2float(__float2half_rn(o10));
                float r11 = o11 - __half2float(__float2half_rn(o11));
                *(uint32_t*)&Yh[(size_t)row * N + col]       = pack_h2(o00, o01);
                *(uint32_t*)&Yh[(size_t)(row + 8) * N + col] = pack_h2(o10, o11);
                *(uint32_t*)&Yl[(size_t)row * N + col]       = pack_h2(r00, r01);
                *(uint32_t*)&Yl[(size_t)(row + 8) * N + col] = pack_h2(r10, r11);
            } else if (OUT_MODE == 2) {
                *(uint32_t*)&Yh[(size_t)row * N + col]       = pack_h2(o00, o01);
                *(uint32_t*)&Yh[(size_t)(row + 8) * N + col] = pack_h2(o10, o11);
            } else {
                *(float2*)&Y[(size_t)row * N + col]       = make_float2(o00, o01);
                *(float2*)&Y[(size_t)(row + 8) * N + col] = make_float2(o10, o11);
            }
        }
    }
}

// ---------------------------------------------------------------------------
// fp16 2-pass flash attention. 64 q-rows / 4 warps / 128 thr, 3 CTAs/SM.
// S = Q_split . Kh^T ; O += P_split . Vh  (K, V hi-only).
// ---------------------------------------------------------------------------
struct QStage { __half h[64][72], l[64][72]; };
struct KVStage {
    __half kh[64][72];
    __half vth[64][72];  // transposed: [dim][key]
    uint32_t mw[64][2];
};

__global__ __launch_bounds__(128, 3) void attn_tc(
    const __half* __restrict__ Qh, const __half* __restrict__ Ql,
    const __half* __restrict__ Kh, const __half* __restrict__ Vh,
    const uint32_t* __restrict__ mbits,
    __half* __restrict__ Oh, __half* __restrict__ Ol) {
    const int qt = blockIdx.x, h = blockIdx.y, b = blockIdx.z;
    const int tid = threadIdx.x, lane = tid & 31, warp = tid >> 5;
    const float SC = 0.125f * 1.44269504f;

    __shared__ union { QStage q; KVStage kv; } sm;

    const size_t qrow0 = (size_t)b * Ss + qt * 64;

    {
        int r = tid >> 1, half = tid & 1;
        const uint4* gh = (const uint4*)(Qh + (qrow0 + r) * Dd + h * 64 + half * 32);
        const uint4* gl = (const uint4*)(Ql + (qrow0 + r) * Dd + h * 64 + half * 32);
        uint4* sh = (uint4*)&sm.q.h[r][half * 32];
        uint4* sl = (uint4*)&sm.q.l[r][half * 32];
#pragma unroll
        for (int i = 0; i < 4; i++) { sh[i] = gh[i]; sl[i] = gl[i]; }
    }
    __syncthreads();

    uint32_t qfh[4][4], qfl[4][4];
    {
        uint32_t bqh = (uint32_t)__cvta_generic_to_shared(&sm.q.h[0][0]);
        uint32_t bql = (uint32_t)__cvta_generic_to_shared(&sm.q.l[0][0]);
        int r = warp * 16 + (lane & 15);
#pragma unroll
        for (int s = 0; s < 4; s++) {
            uint32_t off = (uint32_t)((r * 72 + s * 16 + (lane >> 4) * 8) * 2);
            LDSM4(qfh[s][0], qfh[s][1], qfh[s][2], qfh[s][3], bqh + off);
            LDSM4(qfl[s][0], qfl[s][1], qfl[s][2], qfl[s][3], bql + off);
        }
    }
    __syncthreads();

    float oacc[8][4];
#pragma unroll
    for (int nt = 0; nt < 8; nt++)
#pragma unroll
        for (int i = 0; i < 4; i++) oacc[nt][i] = 0.0f;
    float m1 = -1e30f, m2 = -1e30f, l1 = 0.0f, l2 = 0.0f;

    const int rb = ((lane >> 4) << 3) + (lane & 7);
    const int cb = ((lane >> 3) & 1) * 8;
    const int r1 = lane >> 2;

    for (int kt = 0; kt < 16; kt++) {
        // ---- Load K (straight) + V (transposed) hi tiles + mask words.
        {
            int r = tid >> 1, h2 = tid & 1;
            size_t g = ((size_t)b * Ss + kt * 64 + r) * Dd + h * 64 + h2 * 32;
#pragma unroll
            for (int i = 0; i < 4; i++)
                *(uint4*)&sm.kv.kh[r][h2 * 32 + 8 * i] = *(const uint4*)(Kh + g + 8 * i);
            union { uint4 v[4]; __half e[32]; } th;
#pragma unroll
            for (int i = 0; i < 4; i++) th.v[i] = *(const uint4*)(Vh + g + 8 * i);
#pragma unroll
            for (int i = 0; i < 32; i++) sm.kv.vth[h2 * 32 + i][r] = th.e[i];
            sm.kv.mw[r][h2] = mbits[(qrow0 + r) * 32 + kt * 2 + h2];
        }
        __syncthreads();

        // ---- S = Q Kh^T (2 passes), fp32 accum.
        float sacc[8][4];
#pragma unroll
        for (int nt = 0; nt < 8; nt++)
#pragma unroll
            for (int i = 0; i < 4; i++) sacc[nt][i] = 0.0f;
        {
            uint32_t kbh = (uint32_t)__cvta_generic_to_shared(&sm.kv.kh[0][0]);
#pragma unroll
            for (int s = 0; s < 4; s++) {
                uint32_t bh[8][2];
#pragma unroll
                for (int p = 0; p < 4; p++) {
                    uint32_t off = (uint32_t)(((p * 16 + rb) * 72 + s * 16 + cb) * 2);
                    LDSM4(bh[2 * p][0], bh[2 * p][1], bh[2 * p + 1][0], bh[2 * p + 1][1], kbh + off);
                }
#pragma unroll
                for (int nt = 0; nt < 8; nt++) {
                    MMA16816(sacc[nt], qfh[s][0], qfh[s][1], qfh[s][2], qfh[s][3], bh[nt][0], bh[nt][1]);
                    MMA16816(sacc[nt], qfl[s][0], qfl[s][1], qfl[s][2], qfl[s][3], bh[nt][0], bh[nt][1]);
                }
            }
        }

        // ---- Scale, mask, row max.
        uint32_t w10 = sm.kv.mw[warp * 16 + r1][0];
        uint32_t w11 = sm.kv.mw[warp * 16 + r1][1];
        uint32_t w20 = sm.kv.mw[warp * 16 + r1 + 8][0];
        uint32_t w21 = sm.kv.mw[warp * 16 + r1 + 8][1];
        float tm1 = -1e30f, tm2 = -1e30f;
#pragma unroll
        for (int nt = 0; nt < 8; nt++) {
            int cbase = nt * 8 + (lane & 3) * 2;
            uint32_t wA = (nt < 4) ? w10 : w11;
            uint32_t wB = (nt < 4) ? w20 : w21;
            int shf = cbase & 31;
            float s0 = sacc[nt][0] * SC, s1 = sacc[nt][1] * SC;
            float s2 = sacc[nt][2] * SC, s3 = sacc[nt][3] * SC;
            if (!((wA >> shf) & 1))       s0 = -1e9f;
            if (!((wA >> (shf + 1)) & 1)) s1 = -1e9f;
            if (!((wB >> shf) & 1))       s2 = -1e9f;
            if (!((wB >> (shf + 1)) & 1)) s3 = -1e9f;
            sacc[nt][0] = s0; sacc[nt][1] = s1; sacc[nt][2] = s2; sacc[nt][3] = s3;
            tm1 = fmaxf(tm1, fmaxf(s0, s1));
            tm2 = fmaxf(tm2, fmaxf(s2, s3));
        }
        tm1 = fmaxf(tm1, __shfl_xor_sync(0xffffffff, tm1, 1));
        tm1 = fmaxf(tm1, __shfl_xor_sync(0xffffffff, tm1, 2));
        tm2 = fmaxf(tm2, __shfl_xor_sync(0xffffffff, tm2, 1));
        tm2 = fmaxf(tm2, __shfl_xor_sync(0xffffffff, tm2, 2));

        float mn1 = fmaxf(m1, tm1), mn2 = fmaxf(m2, tm2);
        float a1 = exp2f(m1 - mn1), a2 = exp2f(m2 - mn2);
        m1 = mn1; m2 = mn2;
        l1 *= a1; l2 *= a2;
#pragma unroll
        for (int nt = 0; nt < 8; nt++) {
            oacc[nt][0] *= a1; oacc[nt][1] *= a1;
            oacc[nt][2] *= a2; oacc[nt][3] *= a2;
        }

        // ---- p = exp2(s - m); split hi/lo fp16; pack as A fragments.
        uint32_t pah[4][4], pal[4][4];
#pragma unroll
        for (int nt = 0; nt < 8; nt++) {
            float p0 = exp2f(sacc[nt][0] - m1), p1 = exp2f(sacc[nt][1] - m1);
            float p2 = exp2f(sacc[nt][2] - m2), p3 = exp2f(sacc[nt][3] - m2);
            l1 += p0 + p1; l2 += p2 + p3;
            float q0 = p0 - __half2float(__float2half_rn(p0));
            float q1 = p1 - __half2float(__float2half_rn(p1));
            float q2 = p2 - __half2float(__float2half_rn(p2));
            float q3 = p3 - __half2float(__float2half_rn(p3));
            int s = nt >> 1, base = (nt & 1) * 2;
            pah[s][base]     = pack_h2(p0, p1);
            pah[s][base + 1] = pack_h2(p2, p3);
            pal[s][base]     = pack_h2(q0, q1);
            pal[s][base + 1] = pack_h2(q2, q3);
        }

        // ---- O += P Vh (2 passes).
        {
            uint32_t vbh = (uint32_t)__cvta_generic_to_shared(&sm.kv.vth[0][0]);
#pragma unroll
            for (int s = 0; s < 4; s++) {
                uint32_t bh[8][2];
#pragma unroll
                for (int p = 0; p < 4; p++) {
                    uint32_t off = (uint32_t)(((p * 16 + rb) * 72 + s * 16 + cb) * 2);
                    LDSM4(bh[2 * p][0], bh[2 * p][1], bh[2 * p + 1][0], bh[2 * p + 1][1], vbh + off);
                }
#pragma unroll
                for (int dt = 0; dt < 8; dt++) {
                    MMA16816(oacc[dt], pah[s][0], pah[s][1], pah[s][2], pah[s][3], bh[dt][0], bh[dt][1]);
                    MMA16816(oacc[dt], pal[s][0], pal[s][1], pal[s][2], pal[s][3], bh[dt][0], bh[dt][1]);
                }
            }
        }
        __syncthreads();
    }

    l1 += __shfl_xor_sync(0xffffffff, l1, 1);
    l1 += __shfl_xor_sync(0xffffffff, l1, 2);
    l2 += __shfl_xor_sync(0xffffffff, l2, 1);
    l2 += __shfl_xor_sync(0xffffffff, l2, 2);
    float inv1 = 1.0f / l1, inv2 = 1.0f / l2;

    size_t row1 = qrow0 + warp * 16 + r1;
#pragma unroll
    for (int nt = 0; nt < 8; nt++) {
        int col = h * 64 + nt * 8 + (lane & 3) * 2;
        float o00 = oacc[nt][0] * inv1, o01 = oacc[nt][1] * inv1;
        float o10 = oacc[nt][2] * inv2, o11 = oacc[nt][3] * inv2;
        float r00 = o00 - __half2float(__float2half_rn(o00));
        float r01 = o01 - __half2float(__float2half_rn(o01));
        float r10 = o10 - __half2float(__float2half_rn(o10));
        float r11 = o11 - __half2float(__float2half_rn(o11));
        *(uint32_t*)&Oh[row1 * Dd + col]       = pack_h2(o00, o01);
        *(uint32_t*)&Oh[(row1 + 8) * Dd + col] = pack_h2(o10, o11);
        *(uint32_t*)&Ol[row1 * Dd + col]       = pack_h2(r00, r01);
        *(uint32_t*)&Ol[(row1 + 8) * Dd + col] = pack_h2(r10, r11);
    }
}

// ---------------------------------------------------------------------------
extern "C" void kernel_launch(void* const* d_in, const int* in_sizes, int n_in,
                              void* d_out, int out_size) {
    (void)in_sizes; (void)n_in; (void)out_size;

    const float* q    = (const float*)d_in[0];
    const float* k    = (const float*)d_in[1];
    const float* v    = (const float*)d_in[2];
    const int*   mask = (const int*)d_in[3];
    const float* WQw  = (const float*)d_in[4];
    const float* WQb  = (const float*)d_in[5];
    const float* WKw  = (const float*)d_in[6];
    const float* WKb  = (const float*)d_in[7];
    const float* WVw  = (const float*)d_in[8];
    const float* WVb  = (const float*)d_in[9];
    const float* WOw  = (const float*)d_in[10];
    const float* WOb  = (const float*)d_in[11];
    float* out = (float*)d_out;

    __half *qh, *ql, *kh, *kl, *vh, *vl;
    __half *Qh, *Ql, *Kh, *Vh, *AOh, *AOl;
    __half *WQh, *WKh, *WVh, *WOh;
    uint32_t* Mb;
    cudaGetSymbolAddress((void**)&qh, g_qh);   cudaGetSymbolAddress((void**)&ql, g_ql);
    cudaGetSymbolAddress((void**)&kh, g_kh);   cudaGetSymbolAddress((void**)&kl, g_kl);
    cudaGetSymbolAddress((void**)&vh, g_vh);   cudaGetSymbolAddress((void**)&vl, g_vl);
    cudaGetSymbolAddress((void**)&Qh, g_Qh);   cudaGetSymbolAddress((void**)&Ql, g_Ql);
    cudaGetSymbolAddress((void**)&Kh, g_Kh);   cudaGetSymbolAddress((void**)&Vh, g_Vh);
    cudaGetSymbolAddress((void**)&AOh, g_AOh); cudaGetSymbolAddress((void**)&AOl, g_AOl);
    cudaGetSymbolAddress((void**)&WQh, g_WQh); cudaGetSymbolAddress((void**)&WKh, g_WKh);
    cudaGetSymbolAddress((void**)&WVh, g_WVh); cudaGetSymbolAddress((void**)&WOh, g_WOh);
    cudaGetSymbolAddress((void**)&Mb, g_mbits);

    cudaFuncSetAttribute(gemm_sp<0>, cudaFuncAttributeMaxDynamicSharedMemorySize, GSMEM);
    cudaFuncSetAttribute(gemm_sp<1>, cudaFuncAttributeMaxDynamicSharedMemorySize, GSMEM);
    cudaFuncSetAttribute(gemm_sp<2>, cudaFuncAttributeMaxDynamicSharedMemorySize, GSMEM);

    pack_mask<<<(Bb * Ss * (Ss / 32)) / 256, 256>>>(mask, Mb);

    const int nTok = Bb * Ss * Dd;
    const int nW   = Dd * Dd;
    split2_f32<<<nTok / 1024, 256>>>(q, qh, ql);
    split2_f32<<<nTok / 1024, 256>>>(k, kh, kl);
    split2_f32<<<nTok / 1024, 256>>>(v, vh, vl);
    quant_f32<<<nW / 1024, 256>>>(WQw, WQh);
    quant_f32<<<nW / 1024, 256>>>(WKw, WKh);
    quant_f32<<<nW / 1024, 256>>>(WVw, WVh);
    quant_f32<<<nW / 1024, 256>>>(WOw, WOh);

    dim3 gg(Dd / 128, (Bb * Ss) / 128);  // (8, 64)
    gemm_sp<1><<<gg, 256, GSMEM>>>(qh, ql, WQh, WQb, nullptr, Qh, Ql);    // Q: h+l
    gemm_sp<2><<<gg, 256, GSMEM>>>(kh, kl, WKh, WKb, nullptr, Kh, nullptr); // K: h
    gemm_sp<2><<<gg, 256, GSMEM>>>(vh, vl, WVh, WVb, nullptr, Vh, nullptr); // V: h

    attn_tc<<<dim3(Ss / 64, Hh, Bb), 128>>>(Qh, Ql, Kh, Vh, Mb, AOh, AOl);

    gemm_sp<0><<<gg, 256, GSMEM>>>(AOh, AOl, WOh, WOb, out, nullptr, nullptr);
}

// round 11
// speedup vs baseline: 6.2976x; 1.4479x over previous
#include <cuda_runtime.h>
#include <cuda_fp16.h>
#include <math.h>
#include <cstdint>

#define Bb 8
#define Ss 1024
#define Dd 1024
#define Hh 16
#define DKk 64

// ---- Scratch: everything single-plane fp16 ----
__device__ __half g_qh[(size_t)Bb * Ss * Dd];
__device__ __half g_kh[(size_t)Bb * Ss * Dd];
__device__ __half g_vh[(size_t)Bb * Ss * Dd];
__device__ __half g_Qh[(size_t)Bb * Ss * Dd];
__device__ __half g_Kh[(size_t)Bb * Ss * Dd];
__device__ __half g_Vh[(size_t)Bb * Ss * Dd];
__device__ __half g_AOh[(size_t)Bb * Ss * Dd];
__device__ __half g_WQh[Dd * Dd], g_WKh[Dd * Dd], g_WVh[Dd * Dd], g_WOh[Dd * Dd];
__device__ uint32_t g_mbits[(size_t)Bb * Ss * (Ss / 32)];

#define LDSM4(r0, r1, r2, r3, addr)                                          \
    asm volatile("ldmatrix.sync.aligned.m8n8.x4.shared.b16 {%0,%1,%2,%3}, [%4];" \
                 : "=r"(r0), "=r"(r1), "=r"(r2), "=r"(r3) : "r"(addr))

#define MMA16816(d, a0, a1, a2, a3, b0, b1)                                  \
    asm volatile(                                                            \
        "mma.sync.aligned.m16n8k16.row.col.f32.f16.f16.f32 "                 \
        "{%0,%1,%2,%3}, {%4,%5,%6,%7}, {%8,%9}, {%0,%1,%2,%3};"              \
        : "+f"(d[0]), "+f"(d[1]), "+f"(d[2]), "+f"(d[3])                     \
        : "r"(a0), "r"(a1), "r"(a2), "r"(a3), "r"(b0), "r"(b1))

#define CP16(dst, src)                                                       \
    asm volatile("cp.async.cg.shared.global [%0], [%1], 16;" ::"r"(dst), "l"(src))
#define CP_COMMIT asm volatile("cp.async.commit_group;")
#define CP_WAIT1  asm volatile("cp.async.wait_group 1;")
#define CP_WAIT0  asm volatile("cp.async.wait_group 0;")

__device__ __forceinline__ uint32_t pack_h2(float a, float b) {
    __half2 t = __floats2half2_rn(a, b);
    return *(uint32_t*)&t;
}

// ---------------------------------------------------------------------------
// fp32 -> fp16.
// ---------------------------------------------------------------------------
__global__ void quant_f32(const float* __restrict__ in, __half* __restrict__ hi) {
    size_t i = ((size_t)blockIdx.x * 256 + threadIdx.x) * 4;
    float4 v = *(const float4*)(in + i);
    *(uint2*)(hi + i) = make_uint2(pack_h2(v.x, v.y), pack_h2(v.z, v.w));
}

__global__ void pack_mask(const int* __restrict__ mask, uint32_t* __restrict__ bits) {
    size_t w = (size_t)blockIdx.x * 256 + threadIdx.x;
    const int* p = mask + w * 32;
    uint32_t v = 0;
#pragma unroll
    for (int i = 0; i < 32; i += 4) {
        int4 t = *(const int4*)(p + i);
        v |= (uint32_t)(t.x != 0) << i;
        v |= (uint32_t)(t.y != 0) << (i + 1);
        v |= (uint32_t)(t.z != 0) << (i + 2);
        v |= (uint32_t)(t.w != 0) << (i + 3);
    }
    bits[w] = v;
}

// ---------------------------------------------------------------------------
// fp16 single-pass GEMM: Y = A[M,K] @ B[N,K]^T + bias, fp32 accum.
// 2-stage cp.async, BK=32, 128x128 tile, 256 thr, 2 CTAs/SM.
// OUT_MODE: 0 = f32, 2 = fp16.
// ---------------------------------------------------------------------------
struct GStage {
    __half ah[128][40];
    __half bh[128][40];
};
#define AH_OFF 0
#define BH_OFF 10240
#define GSMEM (2u * sizeof(GStage))  // 40960

template <int OUT_MODE>
__global__ __launch_bounds__(256, 2) void gemm_sp(
    const __half* __restrict__ Ahg, const __half* __restrict__ Bhg,
    const float* __restrict__ bias, float* __restrict__ Y,
    __half* __restrict__ Yh) {
    const int K = 1024, N = 1024;
    extern __shared__ char smem_raw[];
    const uint32_t smem_base = (uint32_t)__cvta_generic_to_shared(smem_raw);

    const int tid  = threadIdx.x;
    const int lane = tid & 31;
    const int warp = tid >> 5;
    const int wm   = warp >> 1;
    const int wn   = warp & 1;

    const int ldRow = tid >> 1;
    const int ldCE  = (tid & 1) * 16;
    const size_t gA = (size_t)(blockIdx.y * 128 + ldRow) * K + ldCE;
    const size_t gB = (size_t)(blockIdx.x * 128 + ldRow) * K + ldCE;
    const uint32_t dRow = ldRow * 80 + ldCE * 2;

    const int rb = ((lane >> 4) << 3) + (lane & 7);
    const int cb = ((lane >> 3) & 1) * 8;
    uint32_t aoff[2][2], boff[4][2];
#pragma unroll
    for (int mt = 0; mt < 2; mt++)
#pragma unroll
        for (int kk = 0; kk < 2; kk++)
            aoff[mt][kk] = (uint32_t)((wm * 32 + mt * 16 + (lane & 15)) * 80 +
                                      (lane >> 4) * 16 + kk * 32);
#pragma unroll
    for (int p = 0; p < 4; p++)
#pragma unroll
        for (int kk = 0; kk < 2; kk++)
            boff[p][kk] = (uint32_t)((wn * 64 + p * 16 + rb) * 80 + cb * 2 + kk * 32);

    float acc[2][8][4];
#pragma unroll
    for (int mt = 0; mt < 2; mt++)
#pragma unroll
        for (int nt = 0; nt < 8; nt++)
#pragma unroll
            for (int i = 0; i < 4; i++) acc[mt][nt][i] = 0.0f;

    auto load_stage = [&](int s, int k0) {
        uint32_t b = smem_base + (uint32_t)s * sizeof(GStage) + dRow;
        CP16(b + AH_OFF,      Ahg + gA + k0);
        CP16(b + AH_OFF + 16, Ahg + gA + k0 + 8);
        CP16(b + BH_OFF,      Bhg + gB + k0);
        CP16(b + BH_OFF + 16, Bhg + gB + k0 + 8);
    };

    load_stage(0, 0); CP_COMMIT;

    const int NK = K / 32;  // 32
    for (int i = 0; i < NK; i++) {
        if (i + 1 < NK) {
            load_stage((i + 1) & 1, (i + 1) * 32);
            CP_COMMIT;
            CP_WAIT1;
        } else {
            CP_WAIT0;
        }
        __syncthreads();

        const uint32_t sb = smem_base + (uint32_t)(i & 1) * sizeof(GStage);
#pragma unroll
        for (int kk = 0; kk < 2; kk++) {
            uint32_t bh[8][2];
#pragma unroll
            for (int p = 0; p < 4; p++)
                LDSM4(bh[2 * p][0], bh[2 * p][1], bh[2 * p + 1][0], bh[2 * p + 1][1],
                      sb + BH_OFF + boff[p][kk]);
#pragma unroll
            for (int mt = 0; mt < 2; mt++) {
                uint32_t ah[4];
                LDSM4(ah[0], ah[1], ah[2], ah[3], sb + AH_OFF + aoff[mt][kk]);
#pragma unroll
                for (int nt = 0; nt < 8; nt++)
                    MMA16816(acc[mt][nt], ah[0], ah[1], ah[2], ah[3], bh[nt][0], bh[nt][1]);
            }
        }
        __syncthreads();
    }

    const int rowBase = blockIdx.y * 128 + wm * 32;
    const int colBase = blockIdx.x * 128 + wn * 64;
#pragma unroll
    for (int mt = 0; mt < 2; mt++) {
        int row = rowBase + mt * 16 + (lane >> 2);
#pragma unroll
        for (int nt = 0; nt < 8; nt++) {
            int col = colBase + nt * 8 + (lane & 3) * 2;
            float2 bv = *(const float2*)&bias[col];
            float o00 = acc[mt][nt][0] + bv.x, o01 = acc[mt][nt][1] + bv.y;
            float o10 = acc[mt][nt][2] + bv.x, o11 = acc[mt][nt][3] + bv.y;
            if (OUT_MODE == 2) {
                *(uint32_t*)&Yh[(size_t)row * N + col]       = pack_h2(o00, o01);
                *(uint32_t*)&Yh[(size_t)(row + 8) * N + col] = pack_h2(o10, o11);
            } else {
                *(float2*)&Y[(size_t)row * N + col]       = make_float2(o00, o01);
                *(float2*)&Y[(size_t)(row + 8) * N + col] = make_float2(o10, o11);
            }
        }
    }
}

// ---------------------------------------------------------------------------
// fp16 single-pass flash attention. 64 q-rows / 4 warps / 128 thr, 4 CTAs/SM.
// ---------------------------------------------------------------------------
struct QStage { __half h[64][72]; };
struct KVStage {
    __half kh[64][72];
    __half vth[64][72];  // transposed: [dim][key]
    uint32_t mw[64][2];
};

__global__ __launch_bounds__(128, 4) void attn_tc(
    const __half* __restrict__ Qh, const __half* __restrict__ Kh,
    const __half* __restrict__ Vh,
    const uint32_t* __restrict__ mbits, __half* __restrict__ Oh) {
    const int qt = blockIdx.x, h = blockIdx.y, b = blockIdx.z;
    const int tid = threadIdx.x, lane = tid & 31, warp = tid >> 5;
    const float SC = 0.125f * 1.44269504f;

    __shared__ union { QStage q; KVStage kv; } sm;

    const size_t qrow0 = (size_t)b * Ss + qt * 64;

    // ---- Stage Q tile (64 rows), ldmatrix Q fragments to registers.
    {
        int r = tid >> 1, half = tid & 1;
        const uint4* gh = (const uint4*)(Qh + (qrow0 + r) * Dd + h * 64 + half * 32);
        uint4* sh = (uint4*)&sm.q.h[r][half * 32];
#pragma unroll
        for (int i = 0; i < 4; i++) sh[i] = gh[i];
    }
    __syncthreads();

    uint32_t qfh[4][4];
    {
        uint32_t bqh = (uint32_t)__cvta_generic_to_shared(&sm.q.h[0][0]);
        int r = warp * 16 + (lane & 15);
#pragma unroll
        for (int s = 0; s < 4; s++) {
            uint32_t off = (uint32_t)((r * 72 + s * 16 + (lane >> 4) * 8) * 2);
            LDSM4(qfh[s][0], qfh[s][1], qfh[s][2], qfh[s][3], bqh + off);
        }
    }
    __syncthreads();

    float oacc[8][4];
#pragma unroll
    for (int nt = 0; nt < 8; nt++)
#pragma unroll
        for (int i = 0; i < 4; i++) oacc[nt][i] = 0.0f;
    float m1 = -1e30f, m2 = -1e30f, l1 = 0.0f, l2 = 0.0f;

    const int rb = ((lane >> 4) << 3) + (lane & 7);
    const int cb = ((lane >> 3) & 1) * 8;
    const int r1 = lane >> 2;

    for (int kt = 0; kt < 16; kt++) {
        // ---- Load K (straight) + V (transposed) tiles + mask words.
        {
            int r = tid >> 1, h2 = tid & 1;
            size_t g = ((size_t)b * Ss + kt * 64 + r) * Dd + h * 64 + h2 * 32;
#pragma unroll
            for (int i = 0; i < 4; i++)
                *(uint4*)&sm.kv.kh[r][h2 * 32 + 8 * i] = *(const uint4*)(Kh + g + 8 * i);
            union { uint4 v[4]; __half e[32]; } th;
#pragma unroll
            for (int i = 0; i < 4; i++) th.v[i] = *(const uint4*)(Vh + g + 8 * i);
#pragma unroll
            for (int i = 0; i < 32; i++) sm.kv.vth[h2 * 32 + i][r] = th.e[i];
            sm.kv.mw[r][h2] = mbits[(qrow0 + r) * 32 + kt * 2 + h2];
        }
        __syncthreads();

        // ---- S = Q K^T (1 pass), fp32 accum.
        float sacc[8][4];
#pragma unroll
        for (int nt = 0; nt < 8; nt++)
#pragma unroll
            for (int i = 0; i < 4; i++) sacc[nt][i] = 0.0f;
        {
            uint32_t kbh = (uint32_t)__cvta_generic_to_shared(&sm.kv.kh[0][0]);
#pragma unroll
            for (int s = 0; s < 4; s++) {
                uint32_t bh[8][2];
#pragma unroll
                for (int p = 0; p < 4; p++) {
                    uint32_t off = (uint32_t)(((p * 16 + rb) * 72 + s * 16 + cb) * 2);
                    LDSM4(bh[2 * p][0], bh[2 * p][1], bh[2 * p + 1][0], bh[2 * p + 1][1], kbh + off);
                }
#pragma unroll
                for (int nt = 0; nt < 8; nt++)
                    MMA16816(sacc[nt], qfh[s][0], qfh[s][1], qfh[s][2], qfh[s][3], bh[nt][0], bh[nt][1]);
            }
        }

        // ---- Scale, mask, row max.
        uint32_t w10 = sm.kv.mw[warp * 16 + r1][0];
        uint32_t w11 = sm.kv.mw[warp * 16 + r1][1];
        uint32_t w20 = sm.kv.mw[warp * 16 + r1 + 8][0];
        uint32_t w21 = sm.kv.mw[warp * 16 + r1 + 8][1];
        float tm1 = -1e30f, tm2 = -1e30f;
#pragma unroll
        for (int nt = 0; nt < 8; nt++) {
            int cbase = nt * 8 + (lane & 3) * 2;
            uint32_t wA = (nt < 4) ? w10 : w11;
            uint32_t wB = (nt < 4) ? w20 : w21;
            int shf = cbase & 31;
            float s0 = sacc[nt][0] * SC, s1 = sacc[nt][1] * SC;
            float s2 = sacc[nt][2] * SC, s3 = sacc[nt][3] * SC;
            if (!((wA >> shf) & 1))       s0 = -1e9f;
            if (!((wA >> (shf + 1)) & 1)) s1 = -1e9f;
            if (!((wB >> shf) & 1))       s2 = -1e9f;
            if (!((wB >> (shf + 1)) & 1)) s3 = -1e9f;
            sacc[nt][0] = s0; sacc[nt][1] = s1; sacc[nt][2] = s2; sacc[nt][3] = s3;
            tm1 = fmaxf(tm1, fmaxf(s0, s1));
            tm2 = fmaxf(tm2, fmaxf(s2, s3));
        }
        tm1 = fmaxf(tm1, __shfl_xor_sync(0xffffffff, tm1, 1));
        tm1 = fmaxf(tm1, __shfl_xor_sync(0xffffffff, tm1, 2));
        tm2 = fmaxf(tm2, __shfl_xor_sync(0xffffffff, tm2, 1));
        tm2 = fmaxf(tm2, __shfl_xor_sync(0xffffffff, tm2, 2));

        float mn1 = fmaxf(m1, tm1), mn2 = fmaxf(m2, tm2);
        float a1 = exp2f(m1 - mn1), a2 = exp2f(m2 - mn2);
        m1 = mn1; m2 = mn2;
        l1 *= a1; l2 *= a2;
#pragma unroll
        for (int nt = 0; nt < 8; nt++) {
            oacc[nt][0] *= a1; oacc[nt][1] *= a1;
            oacc[nt][2] *= a2; oacc[nt][3] *= a2;
        }

        // ---- p = exp2(s - m); pack fp16 A fragments.
        uint32_t pah[4][4];
#pragma unroll
        for (int nt = 0; nt < 8; nt++) {
            float p0 = exp2f(sacc[nt][0] - m1), p1 = exp2f(sacc[nt][1] - m1);
            float p2 = exp2f(sacc[nt][2] - m2), p3 = exp2f(sacc[nt][3] - m2);
            l1 += p0 + p1; l2 += p2 + p3;
            int s = nt >> 1, base = (nt & 1) * 2;
            pah[s][base]     = pack_h2(p0, p1);
            pah[s][base + 1] = pack_h2(p2, p3);
        }

        // ---- O += P V (1 pass).
        {
            uint32_t vbh = (uint32_t)__cvta_generic_to_shared(&sm.kv.vth[0][0]);
#pragma unroll
            for (int s = 0; s < 4; s++) {
                uint32_t bh[8][2];
#pragma unroll
                for (int p = 0; p < 4; p++) {
                    uint32_t off = (uint32_t)(((p * 16 + rb) * 72 + s * 16 + cb) * 2);
                    LDSM4(bh[2 * p][0], bh[2 * p][1], bh[2 * p + 1][0], bh[2 * p + 1][1], vbh + off);
                }
#pragma unroll
                for (int dt = 0; dt < 8; dt++)
                    MMA16816(oacc[dt], pah[s][0], pah[s][1], pah[s][2], pah[s][3], bh[dt][0], bh[dt][1]);
            }
        }
        __syncthreads();
    }

    l1 += __shfl_xor_sync(0xffffffff, l1, 1);
    l1 += __shfl_xor_sync(0xffffffff, l1, 2);
    l2 += __shfl_xor_sync(0xffffffff, l2, 1);
    l2 += __shfl_xor_sync(0xffffffff, l2, 2);
    float inv1 = 1.0f / l1, inv2 = 1.0f / l2;

    size_t row1 = qrow0 + warp * 16 + r1;
#pragma unroll
    for (int nt = 0; nt < 8; nt++) {
        int col = h * 64 + nt * 8 + (lane & 3) * 2;
        *(uint32_t*)&Oh[row1 * Dd + col] =
            pack_h2(oacc[nt][0] * inv1, oacc[nt][1] * inv1);
        *(uint32_t*)&Oh[(row1 + 8) * Dd + col] =
            pack_h2(oacc[nt][2] * inv2, oacc[nt][3] * inv2);
    }
}

// ---------------------------------------------------------------------------
extern "C" void kernel_launch(void* const* d_in, const int* in_sizes, int n_in,
                              void* d_out, int out_size) {
    (void)in_sizes; (void)n_in; (void)out_size;

    const float* q    = (const float*)d_in[0];
    const float* k    = (const float*)d_in[1];
    const float* v    = (const float*)d_in[2];
    const int*   mask = (const int*)d_in[3];
    const float* WQw  = (const float*)d_in[4];
    const float* WQb  = (const float*)d_in[5];
    const float* WKw  = (const float*)d_in[6];
    const float* WKb  = (const float*)d_in[7];
    const float* WVw  = (const float*)d_in[8];
    const float* WVb  = (const float*)d_in[9];
    const float* WOw  = (const float*)d_in[10];
    const float* WOb  = (const float*)d_in[11];
    float* out = (float*)d_out;

    __half *qh, *kh, *vh, *Qh, *Kh, *Vh, *AOh;
    __half *WQh, *WKh, *WVh, *WOh;
    uint32_t* Mb;
    cudaGetSymbolAddress((void**)&qh, g_qh);
    cudaGetSymbolAddress((void**)&kh, g_kh);
    cudaGetSymbolAddress((void**)&vh, g_vh);
    cudaGetSymbolAddress((void**)&Qh, g_Qh);
    cudaGetSymbolAddress((void**)&Kh, g_Kh);
    cudaGetSymbolAddress((void**)&Vh, g_Vh);
    cudaGetSymbolAddress((void**)&AOh, g_AOh);
    cudaGetSymbolAddress((void**)&WQh, g_WQh);
    cudaGetSymbolAddress((void**)&WKh, g_WKh);
    cudaGetSymbolAddress((void**)&WVh, g_WVh);
    cudaGetSymbolAddress((void**)&WOh, g_WOh);
    cudaGetSymbolAddress((void**)&Mb, g_mbits);

    cudaFuncSetAttribute(gemm_sp<0>, cudaFuncAttributeMaxDynamicSharedMemorySize, GSMEM);
    cudaFuncSetAttribute(gemm_sp<2>, cudaFuncAttributeMaxDynamicSharedMemorySize, GSMEM);

    pack_mask<<<(Bb * Ss * (Ss / 32)) / 256, 256>>>(mask, Mb);

    const int nTok = Bb * Ss * Dd;
    const int nW   = Dd * Dd;
    quant_f32<<<nTok / 1024, 256>>>(q, qh);
    quant_f32<<<nTok / 1024, 256>>>(k, kh);
    quant_f32<<<nTok / 1024, 256>>>(v, vh);
    quant_f32<<<nW / 1024, 256>>>(WQw, WQh);
    quant_f32<<<nW / 1024, 256>>>(WKw, WKh);
    quant_f32<<<nW / 1024, 256>>>(WVw, WVh);
    quant_f32<<<nW / 1024, 256>>>(WOw, WOh);

    dim3 gg(Dd / 128, (Bb * Ss) / 128);  // (8, 64)
    gemm_sp<2><<<gg, 256, GSMEM>>>(qh, WQh, WQb, nullptr, Qh);
    gemm_sp<2><<<gg, 256, GSMEM>>>(kh, WKh, WKb, nullptr, Kh);
    gemm_sp<2><<<gg, 256, GSMEM>>>(vh, WVh, WVb, nullptr, Vh);

    attn_tc<<<dim3(Ss / 64, Hh, Bb), 128>>>(Qh, Kh, Vh, Mb, AOh);

    gemm_sp<0><<<gg, 256, GSMEM>>>(AOh, WOh, WOb, out, nullptr);
}

// round 12
// speedup vs baseline: 7.8549x; 1.2473x over previous
#include <cuda_runtime.h>
#include <cuda_fp16.h>
#include <math.h>
#include <cstdint>

#define Bb 8
#define Ss 1024
#define Dd 1024
#define Hh 16
#define DKk 64

// ---- Scratch: everything single-plane fp16 ----
__device__ __half g_qh[(size_t)Bb * Ss * Dd];
__device__ __half g_kh[(size_t)Bb * Ss * Dd];
__device__ __half g_vh[(size_t)Bb * Ss * Dd];
__device__ __half g_Qh[(size_t)Bb * Ss * Dd];
__device__ __half g_Kh[(size_t)Bb * Ss * Dd];
__device__ __half g_Vh[(size_t)Bb * Ss * Dd];
__device__ __half g_AOh[(size_t)Bb * Ss * Dd];
__device__ __half g_WQh[Dd * Dd], g_WKh[Dd * Dd], g_WVh[Dd * Dd], g_WOh[Dd * Dd];
__device__ uint32_t g_mbits[(size_t)Bb * Ss * (Ss / 32)];

#define LDSM4(r0, r1, r2, r3, addr)                                          \
    asm volatile("ldmatrix.sync.aligned.m8n8.x4.shared.b16 {%0,%1,%2,%3}, [%4];" \
                 : "=r"(r0), "=r"(r1), "=r"(r2), "=r"(r3) : "r"(addr))

#define LDSM4T(r0, r1, r2, r3, addr)                                         \
    asm volatile("ldmatrix.sync.aligned.m8n8.x4.trans.shared.b16 {%0,%1,%2,%3}, [%4];" \
                 : "=r"(r0), "=r"(r1), "=r"(r2), "=r"(r3) : "r"(addr))

#define MMA16816(d, a0, a1, a2, a3, b0, b1)                                  \
    asm volatile(                                                            \
        "mma.sync.aligned.m16n8k16.row.col.f32.f16.f16.f32 "                 \
        "{%0,%1,%2,%3}, {%4,%5,%6,%7}, {%8,%9}, {%0,%1,%2,%3};"              \
        : "+f"(d[0]), "+f"(d[1]), "+f"(d[2]), "+f"(d[3])                     \
        : "r"(a0), "r"(a1), "r"(a2), "r"(a3), "r"(b0), "r"(b1))

#define CP16(dst, src)                                                       \
    asm volatile("cp.async.cg.shared.global [%0], [%1], 16;" ::"r"(dst), "l"(src))
#define CP_COMMIT asm volatile("cp.async.commit_group;")
#define CP_WAIT1  asm volatile("cp.async.wait_group 1;")
#define CP_WAIT0  asm volatile("cp.async.wait_group 0;")

__device__ __forceinline__ uint32_t pack_h2(float a, float b) {
    __half2 t = __floats2half2_rn(a, b);
    return *(uint32_t*)&t;
}

// ---------------------------------------------------------------------------
// fp32 -> fp16 quantize; mask -> bit words.
// ---------------------------------------------------------------------------
__global__ void quant_f32(const float* __restrict__ in, __half* __restrict__ hi) {
    size_t i = ((size_t)blockIdx.x * 256 + threadIdx.x) * 4;
    float4 v = *(const float4*)(in + i);
    *(uint2*)(hi + i) = make_uint2(pack_h2(v.x, v.y), pack_h2(v.z, v.w));
}

__global__ void pack_mask(const int* __restrict__ mask, uint32_t* __restrict__ bits) {
    size_t w = (size_t)blockIdx.x * 256 + threadIdx.x;
    const int* p = mask + w * 32;
    uint32_t v = 0;
#pragma unroll
    for (int i = 0; i < 32; i += 4) {
        int4 t = *(const int4*)(p + i);
        v |= (uint32_t)(t.x != 0) << i;
        v |= (uint32_t)(t.y != 0) << (i + 1);
        v |= (uint32_t)(t.z != 0) << (i + 2);
        v |= (uint32_t)(t.w != 0) << (i + 3);
    }
    bits[w] = v;
}

// ---------------------------------------------------------------------------
// fp16 single-pass GEMM, BK=64, stride-72 stages, 2-stage cp.async, 2 CTAs/SM.
// OUT_MODE: 0 = f32, 2 = fp16.
// ---------------------------------------------------------------------------
#define GSTG 36864u            // (128 A rows + 128 B rows) * 144 B
#define GA_OFF 0u
#define GB_OFF 18432u
#define GSMEM (2u * GSTG)      // 73728

template <int OUT_MODE>
__global__ __launch_bounds__(256, 2) void gemm_sp(
    const __half* __restrict__ Ahg, const __half* __restrict__ Bhg,
    const float* __restrict__ bias, float* __restrict__ Y,
    __half* __restrict__ Yh) {
    const int K = 1024, N = 1024;
    extern __shared__ char smem_raw[];
    const uint32_t smem_base = (uint32_t)__cvta_generic_to_shared(smem_raw);

    const int tid  = threadIdx.x;
    const int lane = tid & 31;
    const int warp = tid >> 5;
    const int wm   = warp >> 1;
    const int wn   = warp & 1;

    // Loader: 4 (row, chunk) pairs each for A and B per stage.
    const __half* srcA[4];
    const __half* srcB[4];
    uint32_t dst[4];
#pragma unroll
    for (int i = 0; i < 4; i++) {
        int idx = i * 256 + tid, r = idx >> 3, c = idx & 7;
        srcA[i] = Ahg + (size_t)(blockIdx.y * 128 + r) * K + c * 8;
        srcB[i] = Bhg + (size_t)(blockIdx.x * 128 + r) * K + c * 8;
        dst[i]  = (uint32_t)(r * 144 + c * 16);
    }

    const int rb = ((lane >> 4) << 3) + (lane & 7);
    const int cb = ((lane >> 3) & 1) * 8;
    uint32_t aoff[2][4], boff[4][4];
#pragma unroll
    for (int mt = 0; mt < 2; mt++)
#pragma unroll
        for (int kk = 0; kk < 4; kk++)
            aoff[mt][kk] = (uint32_t)((wm * 32 + mt * 16 + (lane & 15)) * 144 +
                                      (lane >> 4) * 16 + kk * 32);
#pragma unroll
    for (int p = 0; p < 4; p++)
#pragma unroll
        for (int kk = 0; kk < 4; kk++)
            boff[p][kk] = (uint32_t)((wn * 64 + p * 16 + rb) * 144 + cb * 2 + kk * 32);

    float acc[2][8][4];
#pragma unroll
    for (int mt = 0; mt < 2; mt++)
#pragma unroll
        for (int nt = 0; nt < 8; nt++)
#pragma unroll
            for (int i = 0; i < 4; i++) acc[mt][nt][i] = 0.0f;

    auto load_stage = [&](int s, int k0) {
        uint32_t b = smem_base + (uint32_t)s * GSTG;
#pragma unroll
        for (int i = 0; i < 4; i++) {
            CP16(b + GA_OFF + dst[i], srcA[i] + k0);
            CP16(b + GB_OFF + dst[i], srcB[i] + k0);
        }
    };

    load_stage(0, 0); CP_COMMIT;

    const int NK = K / 64;  // 16
    for (int i = 0; i < NK; i++) {
        if (i + 1 < NK) {
            load_stage((i + 1) & 1, (i + 1) * 64);
            CP_COMMIT;
            CP_WAIT1;
        } else {
            CP_WAIT0;
        }
        __syncthreads();

        const uint32_t sb = smem_base + (uint32_t)(i & 1) * GSTG;
#pragma unroll
        for (int kk = 0; kk < 4; kk++) {
            uint32_t bh[8][2];
#pragma unroll
            for (int p = 0; p < 4; p++)
                LDSM4(bh[2 * p][0], bh[2 * p][1], bh[2 * p + 1][0], bh[2 * p + 1][1],
                      sb + GB_OFF + boff[p][kk]);
#pragma unroll
            for (int mt = 0; mt < 2; mt++) {
                uint32_t ah[4];
                LDSM4(ah[0], ah[1], ah[2], ah[3], sb + GA_OFF + aoff[mt][kk]);
#pragma unroll
                for (int nt = 0; nt < 8; nt++)
                    MMA16816(acc[mt][nt], ah[0], ah[1], ah[2], ah[3], bh[nt][0], bh[nt][1]);
            }
        }
        __syncthreads();
    }

    const int rowBase = blockIdx.y * 128 + wm * 32;
    const int colBase = blockIdx.x * 128 + wn * 64;
#pragma unroll
    for (int mt = 0; mt < 2; mt++) {
        int row = rowBase + mt * 16 + (lane >> 2);
#pragma unroll
        for (int nt = 0; nt < 8; nt++) {
            int col = colBase + nt * 8 + (lane & 3) * 2;
            float2 bv = *(const float2*)&bias[col];
            float o00 = acc[mt][nt][0] + bv.x, o01 = acc[mt][nt][1] + bv.y;
            float o10 = acc[mt][nt][2] + bv.x, o11 = acc[mt][nt][3] + bv.y;
            if (OUT_MODE == 2) {
                *(uint32_t*)&Yh[(size_t)row * N + col]       = pack_h2(o00, o01);
                *(uint32_t*)&Yh[(size_t)(row + 8) * N + col] = pack_h2(o10, o11);
            } else {
                *(float2*)&Y[(size_t)row * N + col]       = make_float2(o00, o01);
                *(float2*)&Y[(size_t)(row + 8) * N + col] = make_float2(o10, o11);
            }
        }
    }
}

// ---------------------------------------------------------------------------
// fp16 flash attention. 64 q-rows / 4 warps / 128 thr, 4 CTAs/SM.
// K, V both stored straight; V fragments via ldmatrix.trans.
// KV double-buffered via cp.async; mask via direct LDG.
// ---------------------------------------------------------------------------
struct QStage { __half h[64][72]; };
struct KVStage { __half kh[64][72]; __half vh[64][72]; };

__global__ __launch_bounds__(128, 4) void attn_tc(
    const __half* __restrict__ Qh, const __half* __restrict__ Kh,
    const __half* __restrict__ Vh,
    const uint32_t* __restrict__ mbits, __half* __restrict__ Oh) {
    const int qt = blockIdx.x, h = blockIdx.y, b = blockIdx.z;
    const int tid = threadIdx.x, lane = tid & 31, warp = tid >> 5;
    const float SC = 0.125f * 1.44269504f;

    __shared__ union { QStage q; KVStage kv[2]; } sm;

    const size_t qrow0 = (size_t)b * Ss + qt * 64;

    // ---- Stage Q tile, ldmatrix fragments to registers.
    {
        int r = tid >> 1, half = tid & 1;
        const uint4* gh = (const uint4*)(Qh + (qrow0 + r) * Dd + h * 64 + half * 32);
        uint4* sh = (uint4*)&sm.q.h[r][half * 32];
#pragma unroll
        for (int i = 0; i < 4; i++) sh[i] = gh[i];
    }
    __syncthreads();

    uint32_t qfh[4][4];
    {
        uint32_t bqh = (uint32_t)__cvta_generic_to_shared(&sm.q.h[0][0]);
        int r = warp * 16 + (lane & 15);
#pragma unroll
        for (int s = 0; s < 4; s++) {
            uint32_t off = (uint32_t)((r * 72 + s * 16 + (lane >> 4) * 8) * 2);
            LDSM4(qfh[s][0], qfh[s][1], qfh[s][2], qfh[s][3], bqh + off);
        }
    }
    __syncthreads();

    const uint32_t kvbase = (uint32_t)__cvta_generic_to_shared(&sm.kv[0]);
    const uint32_t STG = (uint32_t)sizeof(KVStage);  // 18432
    const uint32_t VOFF = 9216;

    // Loader: 4 (row, chunk) pairs per stage (64 rows x 8 chunks / 128 thr).
    const size_t kvrow0 = ((size_t)b * Ss) * Dd + h * 64;
    uint32_t ldst[4];
    size_t lsrc[4];
#pragma unroll
    for (int i = 0; i < 4; i++) {
        int idx = i * 128 + tid, r = idx >> 3, c = idx & 7;
        ldst[i] = (uint32_t)(r * 144 + c * 16);
        lsrc[i] = (size_t)r * Dd + c * 8;
    }
    auto load_kv = [&](int s, int kt) {
        uint32_t bb = kvbase + (uint32_t)s * STG;
        size_t g = kvrow0 + (size_t)kt * 64 * Dd;
#pragma unroll
        for (int i = 0; i < 4; i++) {
            CP16(bb + ldst[i],        Kh + g + lsrc[i]);
            CP16(bb + VOFF + ldst[i], Vh + g + lsrc[i]);
        }
    };

    float oacc[8][4];
#pragma unroll
    for (int nt = 0; nt < 8; nt++)
#pragma unroll
        for (int i = 0; i < 4; i++) oacc[nt][i] = 0.0f;
    float m1 = -1e30f, m2 = -1e30f, l1 = 0.0f, l2 = 0.0f;

    const int rb = ((lane >> 4) << 3) + (lane & 7);
    const int cb = ((lane >> 3) & 1) * 8;
    const int r1 = lane >> 2;
    // V trans ldmatrix lane address components.
    const int vrow = ((lane >> 3) & 1) * 8 + (lane & 7);
    const int vcol = (lane >> 4) * 8;

    const uint32_t* mrow1 = mbits + (qrow0 + warp * 16 + r1) * 32;
    const uint32_t* mrow2 = mrow1 + 8 * 32;

    load_kv(0, 0); CP_COMMIT;

    for (int kt = 0; kt < 16; kt++) {
        if (kt + 1 < 16) {
            load_kv((kt + 1) & 1, kt + 1);
            CP_COMMIT;
            CP_WAIT1;
        } else {
            CP_WAIT0;
        }
        __syncthreads();

        const uint32_t kb = kvbase + (uint32_t)(kt & 1) * STG;
        const uint32_t vb = kb + VOFF;

        // ---- S = Q K^T, fp32 accum.
        float sacc[8][4];
#pragma unroll
        for (int nt = 0; nt < 8; nt++)
#pragma unroll
            for (int i = 0; i < 4; i++) sacc[nt][i] = 0.0f;
#pragma unroll
        for (int s = 0; s < 4; s++) {
            uint32_t bh[8][2];
#pragma unroll
            for (int p = 0; p < 4; p++) {
                uint32_t off = (uint32_t)(((p * 16 + rb) * 72 + s * 16 + cb) * 2);
                LDSM4(bh[2 * p][0], bh[2 * p][1], bh[2 * p + 1][0], bh[2 * p + 1][1], kb + off);
            }
#pragma unroll
            for (int nt = 0; nt < 8; nt++)
                MMA16816(sacc[nt], qfh[s][0], qfh[s][1], qfh[s][2], qfh[s][3], bh[nt][0], bh[nt][1]);
        }

        // ---- Scale, mask (direct LDG), row max.
        uint32_t w10 = mrow1[kt * 2], w11 = mrow1[kt * 2 + 1];
        uint32_t w20 = mrow2[kt * 2], w21 = mrow2[kt * 2 + 1];
        float tm1 = -1e30f, tm2 = -1e30f;
#pragma unroll
        for (int nt = 0; nt < 8; nt++) {
            int shf = (nt * 8 + (lane & 3) * 2) & 31;
            uint32_t wA = (nt < 4) ? w10 : w11;
            uint32_t wB = (nt < 4) ? w20 : w21;
            float s0 = sacc[nt][0] * SC, s1 = sacc[nt][1] * SC;
            float s2 = sacc[nt][2] * SC, s3 = sacc[nt][3] * SC;
            if (!((wA >> shf) & 1))       s0 = -1e9f;
            if (!((wA >> (shf + 1)) & 1)) s1 = -1e9f;
            if (!((wB >> shf) & 1))       s2 = -1e9f;
            if (!((wB >> (shf + 1)) & 1)) s3 = -1e9f;
            sacc[nt][0] = s0; sacc[nt][1] = s1; sacc[nt][2] = s2; sacc[nt][3] = s3;
            tm1 = fmaxf(tm1, fmaxf(s0, s1));
            tm2 = fmaxf(tm2, fmaxf(s2, s3));
        }
        tm1 = fmaxf(tm1, __shfl_xor_sync(0xffffffff, tm1, 1));
        tm1 = fmaxf(tm1, __shfl_xor_sync(0xffffffff, tm1, 2));
        tm2 = fmaxf(tm2, __shfl_xor_sync(0xffffffff, tm2, 1));
        tm2 = fmaxf(tm2, __shfl_xor_sync(0xffffffff, tm2, 2));

        float mn1 = fmaxf(m1, tm1), mn2 = fmaxf(m2, tm2);
        float a1 = exp2f(m1 - mn1), a2 = exp2f(m2 - mn2);
        m1 = mn1; m2 = mn2;
        l1 *= a1; l2 *= a2;
#pragma unroll
        for (int nt = 0; nt < 8; nt++) {
            oacc[nt][0] *= a1; oacc[nt][1] *= a1;
            oacc[nt][2] *= a2; oacc[nt][3] *= a2;
        }

        // ---- p = exp2(s - m); pack fp16 A fragments.
        uint32_t pah[4][4];
#pragma unroll
        for (int nt = 0; nt < 8; nt++) {
            float p0 = exp2f(sacc[nt][0] - m1), p1 = exp2f(sacc[nt][1] - m1);
            float p2 = exp2f(sacc[nt][2] - m2), p3 = exp2f(sacc[nt][3] - m2);
            l1 += p0 + p1; l2 += p2 + p3;
            int s = nt >> 1, base = (nt & 1) * 2;
            pah[s][base]     = pack_h2(p0, p1);
            pah[s][base + 1] = pack_h2(p2, p3);
        }

        // ---- O += P V : V fragments via ldmatrix.trans from straight layout.
#pragma unroll
        for (int s = 0; s < 4; s++) {
            uint32_t bt[8][2];
#pragma unroll
            for (int p = 0; p < 4; p++) {
                uint32_t off = (uint32_t)(((s * 16 + vrow) * 72 + p * 16 + vcol) * 2);
                LDSM4T(bt[2 * p][0], bt[2 * p][1], bt[2 * p + 1][0], bt[2 * p + 1][1], vb + off);
            }
#pragma unroll
            for (int dt = 0; dt < 8; dt++)
                MMA16816(oacc[dt], pah[s][0], pah[s][1], pah[s][2], pah[s][3], bt[dt][0], bt[dt][1]);
        }
        __syncthreads();
    }

    l1 += __shfl_xor_sync(0xffffffff, l1, 1);
    l1 += __shfl_xor_sync(0xffffffff, l1, 2);
    l2 += __shfl_xor_sync(0xffffffff, l2, 1);
    l2 += __shfl_xor_sync(0xffffffff, l2, 2);
    float inv1 = 1.0f / l1, inv2 = 1.0f / l2;

    size_t row1 = qrow0 + warp * 16 + r1;
#pragma unroll
    for (int nt = 0; nt < 8; nt++) {
        int col = h * 64 + nt * 8 + (lane & 3) * 2;
        *(uint32_t*)&Oh[row1 * Dd + col] =
            pack_h2(oacc[nt][0] * inv1, oacc[nt][1] * inv1);
        *(uint32_t*)&Oh[(row1 + 8) * Dd + col] =
            pack_h2(oacc[nt][2] * inv2, oacc[nt][3] * inv2);
    }
}

// ---------------------------------------------------------------------------
extern "C" void kernel_launch(void* const* d_in, const int* in_sizes, int n_in,
                              void* d_out, int out_size) {
    (void)in_sizes; (void)n_in; (void)out_size;

    const float* q    = (const float*)d_in[0];
    const float* k    = (const float*)d_in[1];
    const float* v    = (const float*)d_in[2];
    const int*   mask = (const int*)d_in[3];
    const float* WQw  = (const float*)d_in[4];
    const float* WQb  = (const float*)d_in[5];
    const float* WKw  = (const float*)d_in[6];
    const float* WKb  = (const float*)d_in[7];
    const float* WVw  = (const float*)d_in[8];
    const float* WVb  = (const float*)d_in[9];
    const float* WOw  = (const float*)d_in[10];
    const float* WOb  = (const float*)d_in[11];
    float* out = (float*)d_out;

    __half *qh, *kh, *vh, *Qh, *Kh, *Vh, *AOh;
    __half *WQh, *WKh, *WVh, *WOh;
    uint32_t* Mb;
    cudaGetSymbolAddress((void**)&qh, g_qh);
    cudaGetSymbolAddress((void**)&kh, g_kh);
    cudaGetSymbolAddress((void**)&vh, g_vh);
    cudaGetSymbolAddress((void**)&Qh, g_Qh);
    cudaGetSymbolAddress((void**)&Kh, g_Kh);
    cudaGetSymbolAddress((void**)&Vh, g_Vh);
    cudaGetSymbolAddress((void**)&AOh, g_AOh);
    cudaGetSymbolAddress((void**)&WQh, g_WQh);
    cudaGetSymbolAddress((void**)&WKh, g_WKh);
    cudaGetSymbolAddress((void**)&WVh, g_WVh);
    cudaGetSymbolAddress((void**)&WOh, g_WOh);
    cudaGetSymbolAddress((void**)&Mb, g_mbits);

    cudaFuncSetAttribute(gemm_sp<0>, cudaFuncAttributeMaxDynamicSharedMemorySize, GSMEM);
    cudaFuncSetAttribute(gemm_sp<2>, cudaFuncAttributeMaxDynamicSharedMemorySize, GSMEM);

    pack_mask<<<(Bb * Ss * (Ss / 32)) / 256, 256>>>(mask, Mb);

    const int nTok = Bb * Ss * Dd;
    const int nW   = Dd * Dd;
    quant_f32<<<nTok / 1024, 256>>>(q, qh);
    quant_f32<<<nTok / 1024, 256>>>(k, kh);
    quant_f32<<<nTok / 1024, 256>>>(v, vh);
    quant_f32<<<nW / 1024, 256>>>(WQw, WQh);
    quant_f32<<<nW / 1024, 256>>>(WKw, WKh);
    quant_f32<<<nW / 1024, 256>>>(WVw, WVh);
    quant_f32<<<nW / 1024, 256>>>(WOw, WOh);

    dim3 gg(Dd / 128, (Bb * Ss) / 128);  // (8, 64)
    gemm_sp<2><<<gg, 256, GSMEM>>>(qh, WQh, WQb, nullptr, Qh);
    gemm_sp<2><<<gg, 256, GSMEM>>>(kh, WKh, WKb, nullptr, Kh);
    gemm_sp<2><<<gg, 256, GSMEM>>>(vh, WVh, WVb, nullptr, Vh);

    attn_tc<<<dim3(Ss / 64, Hh, Bb), 128>>>(Qh, Kh, Vh, Mb, AOh);

    gemm_sp<0><<<gg, 256, GSMEM>>>(AOh, WOh, WOb, out, nullptr);
}

// round 13
// speedup vs baseline: 8.1204x; 1.0338x over previous
#include <cuda_runtime.h>
#include <cuda_fp16.h>
#include <math.h>
#include <cstdint>

#define Bb 8
#define Ss 1024
#define Dd 1024
#define Hh 16
#define DKk 64

// ---- Scratch: everything single-plane fp16 ----
__device__ __half g_qh[(size_t)Bb * Ss * Dd];
__device__ __half g_kh[(size_t)Bb * Ss * Dd];
__device__ __half g_vh[(size_t)Bb * Ss * Dd];
__device__ __half g_Qh[(size_t)Bb * Ss * Dd];   // pre-scaled by 0.125*log2(e)
__device__ __half g_Kh[(size_t)Bb * Ss * Dd];
__device__ __half g_Vh[(size_t)Bb * Ss * Dd];
__device__ __half g_AOh[(size_t)Bb * Ss * Dd];
__device__ __half g_WQh[Dd * Dd], g_WKh[Dd * Dd], g_WVh[Dd * Dd], g_WOh[Dd * Dd];
__device__ uint32_t g_mbits[(size_t)Bb * Ss * (Ss / 32)];

#define LDSM4(r0, r1, r2, r3, addr)                                          \
    asm volatile("ldmatrix.sync.aligned.m8n8.x4.shared.b16 {%0,%1,%2,%3}, [%4];" \
                 : "=r"(r0), "=r"(r1), "=r"(r2), "=r"(r3) : "r"(addr))

#define LDSM4T(r0, r1, r2, r3, addr)                                         \
    asm volatile("ldmatrix.sync.aligned.m8n8.x4.trans.shared.b16 {%0,%1,%2,%3}, [%4];" \
                 : "=r"(r0), "=r"(r1), "=r"(r2), "=r"(r3) : "r"(addr))

#define MMA16816(d, a0, a1, a2, a3, b0, b1)                                  \
    asm volatile(                                                            \
        "mma.sync.aligned.m16n8k16.row.col.f32.f16.f16.f32 "                 \
        "{%0,%1,%2,%3}, {%4,%5,%6,%7}, {%8,%9}, {%0,%1,%2,%3};"              \
        : "+f"(d[0]), "+f"(d[1]), "+f"(d[2]), "+f"(d[3])                     \
        : "r"(a0), "r"(a1), "r"(a2), "r"(a3), "r"(b0), "r"(b1))

#define CP16(dst, src)                                                       \
    asm volatile("cp.async.cg.shared.global [%0], [%1], 16;" ::"r"(dst), "l"(src))
#define CP_COMMIT asm volatile("cp.async.commit_group;")
#define CP_WAIT1  asm volatile("cp.async.wait_group 1;")
#define CP_WAIT0  asm volatile("cp.async.wait_group 0;")

__device__ __forceinline__ uint32_t pack_h2(float a, float b) {
    __half2 t = __floats2half2_rn(a, b);
    return *(uint32_t*)&t;
}
// exp2 on a packed half2 (single MUFU.EX2.F16x2).
__device__ __forceinline__ uint32_t h2exp2_u(uint32_t x) {
    __half2 v = *(__half2*)&x;
    __half2 r = h2exp2(v);
    return *(uint32_t*)&r;
}

// ---------------------------------------------------------------------------
// Fused quantizers + mask pack.
// ---------------------------------------------------------------------------
__global__ void quant3(const float* __restrict__ a, const float* __restrict__ b,
                       const float* __restrict__ c,
                       __half* __restrict__ oa, __half* __restrict__ ob,
                       __half* __restrict__ oc) {
    const float* src = (blockIdx.y == 0) ? a : (blockIdx.y == 1) ? b : c;
    __half* dst      = (blockIdx.y == 0) ? oa : (blockIdx.y == 1) ? ob : oc;
    size_t i = ((size_t)blockIdx.x * 256 + threadIdx.x) * 4;
    float4 v = *(const float4*)(src + i);
    *(uint2*)(dst + i) = make_uint2(pack_h2(v.x, v.y), pack_h2(v.z, v.w));
}

__global__ void quant4(const float* __restrict__ a, const float* __restrict__ b,
                       const float* __restrict__ c, const float* __restrict__ d,
                       __half* __restrict__ oa, __half* __restrict__ ob,
                       __half* __restrict__ oc, __half* __restrict__ od) {
    int s = blockIdx.y;
    const float* src = (s == 0) ? a : (s == 1) ? b : (s == 2) ? c : d;
    __half* dst      = (s == 0) ? oa : (s == 1) ? ob : (s == 2) ? oc : od;
    size_t i = ((size_t)blockIdx.x * 256 + threadIdx.x) * 4;
    float4 v = *(const float4*)(src + i);
    *(uint2*)(dst + i) = make_uint2(pack_h2(v.x, v.y), pack_h2(v.z, v.w));
}

__global__ void pack_mask(const int* __restrict__ mask, uint32_t* __restrict__ bits) {
    size_t w = (size_t)blockIdx.x * 256 + threadIdx.x;
    const int* p = mask + w * 32;
    uint32_t v = 0;
#pragma unroll
    for (int i = 0; i < 32; i += 4) {
        int4 t = *(const int4*)(p + i);
        v |= (uint32_t)(t.x != 0) << i;
        v |= (uint32_t)(t.y != 0) << (i + 1);
        v |= (uint32_t)(t.z != 0) << (i + 2);
        v |= (uint32_t)(t.w != 0) << (i + 3);
    }
    bits[w] = v;
}

// ---------------------------------------------------------------------------
// fp16 single-pass GEMM, BK=64, 2-stage cp.async, 2 CTAs/SM.
// OUT_MODE: 0 = f32, 2 = fp16 (output scaled by oscale).
// ---------------------------------------------------------------------------
#define GSTG 36864u
#define GA_OFF 0u
#define GB_OFF 18432u
#define GSMEM (2u * GSTG)  // 73728

template <int OUT_MODE>
__global__ __launch_bounds__(256, 2) void gemm_sp(
    const __half* __restrict__ Ahg, const __half* __restrict__ Bhg,
    const float* __restrict__ bias, float* __restrict__ Y,
    __half* __restrict__ Yh, float oscale) {
    const int K = 1024, N = 1024;
    extern __shared__ char smem_raw[];
    const uint32_t smem_base = (uint32_t)__cvta_generic_to_shared(smem_raw);

    const int tid  = threadIdx.x;
    const int lane = tid & 31;
    const int warp = tid >> 5;
    const int wm   = warp >> 1;
    const int wn   = warp & 1;

    const __half* srcA[4];
    const __half* srcB[4];
    uint32_t dst[4];
#pragma unroll
    for (int i = 0; i < 4; i++) {
        int idx = i * 256 + tid, r = idx >> 3, c = idx & 7;
        srcA[i] = Ahg + (size_t)(blockIdx.y * 128 + r) * K + c * 8;
        srcB[i] = Bhg + (size_t)(blockIdx.x * 128 + r) * K + c * 8;
        dst[i]  = (uint32_t)(r * 144 + c * 16);
    }

    const int rb = ((lane >> 4) << 3) + (lane & 7);
    const int cb = ((lane >> 3) & 1) * 8;
    uint32_t aoff[2][4], boff[4][4];
#pragma unroll
    for (int mt = 0; mt < 2; mt++)
#pragma unroll
        for (int kk = 0; kk < 4; kk++)
            aoff[mt][kk] = (uint32_t)((wm * 32 + mt * 16 + (lane & 15)) * 144 +
                                      (lane >> 4) * 16 + kk * 32);
#pragma unroll
    for (int p = 0; p < 4; p++)
#pragma unroll
        for (int kk = 0; kk < 4; kk++)
            boff[p][kk] = (uint32_t)((wn * 64 + p * 16 + rb) * 144 + cb * 2 + kk * 32);

    float acc[2][8][4];
#pragma unroll
    for (int mt = 0; mt < 2; mt++)
#pragma unroll
        for (int nt = 0; nt < 8; nt++)
#pragma unroll
            for (int i = 0; i < 4; i++) acc[mt][nt][i] = 0.0f;

    auto load_stage = [&](int s, int k0) {
        uint32_t b = smem_base + (uint32_t)s * GSTG;
#pragma unroll
        for (int i = 0; i < 4; i++) {
            CP16(b + GA_OFF + dst[i], srcA[i] + k0);
            CP16(b + GB_OFF + dst[i], srcB[i] + k0);
        }
    };

    load_stage(0, 0); CP_COMMIT;

    const int NK = K / 64;  // 16
    for (int i = 0; i < NK; i++) {
        if (i + 1 < NK) {
            load_stage((i + 1) & 1, (i + 1) * 64);
            CP_COMMIT;
            CP_WAIT1;
        } else {
            CP_WAIT0;
        }
        __syncthreads();

        const uint32_t sb = smem_base + (uint32_t)(i & 1) * GSTG;
#pragma unroll
        for (int kk = 0; kk < 4; kk++) {
            uint32_t bh[8][2];
#pragma unroll
            for (int p = 0; p < 4; p++)
                LDSM4(bh[2 * p][0], bh[2 * p][1], bh[2 * p + 1][0], bh[2 * p + 1][1],
                      sb + GB_OFF + boff[p][kk]);
#pragma unroll
            for (int mt = 0; mt < 2; mt++) {
                uint32_t ah[4];
                LDSM4(ah[0], ah[1], ah[2], ah[3], sb + GA_OFF + aoff[mt][kk]);
#pragma unroll
                for (int nt = 0; nt < 8; nt++)
                    MMA16816(acc[mt][nt], ah[0], ah[1], ah[2], ah[3], bh[nt][0], bh[nt][1]);
            }
        }
        __syncthreads();
    }

    const int rowBase = blockIdx.y * 128 + wm * 32;
    const int colBase = blockIdx.x * 128 + wn * 64;
#pragma unroll
    for (int mt = 0; mt < 2; mt++) {
        int row = rowBase + mt * 16 + (lane >> 2);
#pragma unroll
        for (int nt = 0; nt < 8; nt++) {
            int col = colBase + nt * 8 + (lane & 3) * 2;
            float2 bv = *(const float2*)&bias[col];
            float o00 = (acc[mt][nt][0] + bv.x) * oscale;
            float o01 = (acc[mt][nt][1] + bv.y) * oscale;
            float o10 = (acc[mt][nt][2] + bv.x) * oscale;
            float o11 = (acc[mt][nt][3] + bv.y) * oscale;
            if (OUT_MODE == 2) {
                *(uint32_t*)&Yh[(size_t)row * N + col]       = pack_h2(o00, o01);
                *(uint32_t*)&Yh[(size_t)(row + 8) * N + col] = pack_h2(o10, o11);
            } else {
                *(float2*)&Y[(size_t)row * N + col]       = make_float2(o00, o01);
                *(float2*)&Y[(size_t)(row + 8) * N + col] = make_float2(o10, o11);
            }
        }
    }
}

// ---------------------------------------------------------------------------
// fp16 flash attention. 64 q-rows / 4 warps / 128 thr, 4 CTAs/SM.
// Q pre-scaled by 0.125*log2(e): scores land directly in exp2 domain.
// p = h2exp2(s - m) packed; l via ones-column MMA (fp32 accum, no shfl).
// ---------------------------------------------------------------------------
struct QStage { __half h[64][72]; };
struct KVStage { __half kh[64][72]; __half vh[64][72]; };
#define ONES_H2 0x3C003C00u  // half2(1.0, 1.0)

__global__ __launch_bounds__(128, 4) void attn_tc(
    const __half* __restrict__ Qh, const __half* __restrict__ Kh,
    const __half* __restrict__ Vh,
    const uint32_t* __restrict__ mbits, __half* __restrict__ Oh) {
    const int qt = blockIdx.x, h = blockIdx.y, b = blockIdx.z;
    const int tid = threadIdx.x, lane = tid & 31, warp = tid >> 5;

    __shared__ union { QStage q; KVStage kv[2]; } sm;

    const size_t qrow0 = (size_t)b * Ss + qt * 64;

    {
        int r = tid >> 1, half = tid & 1;
        const uint4* gh = (const uint4*)(Qh + (qrow0 + r) * Dd + h * 64 + half * 32);
        uint4* sh = (uint4*)&sm.q.h[r][half * 32];
#pragma unroll
        for (int i = 0; i < 4; i++) sh[i] = gh[i];
    }
    __syncthreads();

    uint32_t qfh[4][4];
    {
        uint32_t bqh = (uint32_t)__cvta_generic_to_shared(&sm.q.h[0][0]);
        int r = warp * 16 + (lane & 15);
#pragma unroll
        for (int s = 0; s < 4; s++) {
            uint32_t off = (uint32_t)((r * 72 + s * 16 + (lane >> 4) * 8) * 2);
            LDSM4(qfh[s][0], qfh[s][1], qfh[s][2], qfh[s][3], bqh + off);
        }
    }
    __syncthreads();

    const uint32_t kvbase = (uint32_t)__cvta_generic_to_shared(&sm.kv[0]);
    const uint32_t STG = (uint32_t)sizeof(KVStage);  // 18432
    const uint32_t VOFF = 9216;

    const size_t kvrow0 = ((size_t)b * Ss) * Dd + h * 64;
    uint32_t ldst[4];
    size_t lsrc[4];
#pragma unroll
    for (int i = 0; i < 4; i++) {
        int idx = i * 128 + tid, r = idx >> 3, c = idx & 7;
        ldst[i] = (uint32_t)(r * 144 + c * 16);
        lsrc[i] = (size_t)r * Dd + c * 8;
    }
    auto load_kv = [&](int s, int kt) {
        uint32_t bb = kvbase + (uint32_t)s * STG;
        size_t g = kvrow0 + (size_t)kt * 64 * Dd;
#pragma unroll
        for (int i = 0; i < 4; i++) {
            CP16(bb + ldst[i],        Kh + g + lsrc[i]);
            CP16(bb + VOFF + ldst[i], Vh + g + lsrc[i]);
        }
    };

    float oacc[8][4];
#pragma unroll
    for (int nt = 0; nt < 8; nt++)
#pragma unroll
        for (int i = 0; i < 4; i++) oacc[nt][i] = 0.0f;
    float lacc[4] = {0.f, 0.f, 0.f, 0.f};  // ones-MMA row sums
    float m1 = -1e30f, m2 = -1e30f;

    const int rb = ((lane >> 4) << 3) + (lane & 7);
    const int cb = ((lane >> 3) & 1) * 8;
    const int r1 = lane >> 2;
    const int vrow = ((lane >> 3) & 1) * 8 + (lane & 7);
    const int vcol = (lane >> 4) * 8;
    const int lsh = (lane & 3) * 2;  // pre-shift for mask words

    const uint32_t* mrow1 = mbits + (qrow0 + warp * 16 + r1) * 32;
    const uint32_t* mrow2 = mrow1 + 8 * 32;

    load_kv(0, 0); CP_COMMIT;

    for (int kt = 0; kt < 16; kt++) {
        if (kt + 1 < 16) {
            load_kv((kt + 1) & 1, kt + 1);
            CP_COMMIT;
            CP_WAIT1;
        } else {
            CP_WAIT0;
        }
        __syncthreads();

        const uint32_t kb = kvbase + (uint32_t)(kt & 1) * STG;
        const uint32_t vb = kb + VOFF;

        // ---- S = Q K^T (scores already in exp2 domain; Q pre-scaled).
        float sacc[8][4];
#pragma unroll
        for (int nt = 0; nt < 8; nt++)
#pragma unroll
            for (int i = 0; i < 4; i++) sacc[nt][i] = 0.0f;
#pragma unroll
        for (int s = 0; s < 4; s++) {
            uint32_t bh[8][2];
#pragma unroll
            for (int p = 0; p < 4; p++) {
                uint32_t off = (uint32_t)(((p * 16 + rb) * 72 + s * 16 + cb) * 2);
                LDSM4(bh[2 * p][0], bh[2 * p][1], bh[2 * p + 1][0], bh[2 * p + 1][1], kb + off);
            }
#pragma unroll
            for (int nt = 0; nt < 8; nt++)
                MMA16816(sacc[nt], qfh[s][0], qfh[s][1], qfh[s][2], qfh[s][3], bh[nt][0], bh[nt][1]);
        }

        // ---- Mask (pre-shifted words, compile-time shifts), row max.
        uint32_t w10 = mrow1[kt * 2] >> lsh, w11 = mrow1[kt * 2 + 1] >> lsh;
        uint32_t w20 = mrow2[kt * 2] >> lsh, w21 = mrow2[kt * 2 + 1] >> lsh;
        float tm1 = -1e30f, tm2 = -1e30f;
#pragma unroll
        for (int nt = 0; nt < 8; nt++) {
            const int shf = (nt * 8) & 31;
            uint32_t wA = (nt < 4) ? w10 : w11;
            uint32_t wB = (nt < 4) ? w20 : w21;
            float s0 = sacc[nt][0], s1 = sacc[nt][1];
            float s2 = sacc[nt][2], s3 = sacc[nt][3];
            if (!((wA >> shf) & 1))       s0 = -1e9f;
            if (!((wA >> (shf + 1)) & 1)) s1 = -1e9f;
            if (!((wB >> shf) & 1))       s2 = -1e9f;
            if (!((wB >> (shf + 1)) & 1)) s3 = -1e9f;
            sacc[nt][0] = s0; sacc[nt][1] = s1; sacc[nt][2] = s2; sacc[nt][3] = s3;
            tm1 = fmaxf(tm1, fmaxf(s0, s1));
            tm2 = fmaxf(tm2, fmaxf(s2, s3));
        }
        tm1 = fmaxf(tm1, __shfl_xor_sync(0xffffffff, tm1, 1));
        tm1 = fmaxf(tm1, __shfl_xor_sync(0xffffffff, tm1, 2));
        tm2 = fmaxf(tm2, __shfl_xor_sync(0xffffffff, tm2, 1));
        tm2 = fmaxf(tm2, __shfl_xor_sync(0xffffffff, tm2, 2));

        float mn1 = fmaxf(m1, tm1), mn2 = fmaxf(m2, tm2);
        float a1 = exp2f(m1 - mn1), a2 = exp2f(m2 - mn2);
        m1 = mn1; m2 = mn2;
        lacc[0] *= a1; lacc[1] *= a1; lacc[2] *= a2; lacc[3] *= a2;
#pragma unroll
        for (int nt = 0; nt < 8; nt++) {
            oacc[nt][0] *= a1; oacc[nt][1] *= a1;
            oacc[nt][2] *= a2; oacc[nt][3] *= a2;
        }

        // ---- p = h2exp2(s - m): packed fp16 fragments directly.
        uint32_t pah[4][4];
#pragma unroll
        for (int nt = 0; nt < 8; nt++) {
            int s = nt >> 1, base = (nt & 1) * 2;
            pah[s][base]     = h2exp2_u(pack_h2(sacc[nt][0] - m1, sacc[nt][1] - m1));
            pah[s][base + 1] = h2exp2_u(pack_h2(sacc[nt][2] - m2, sacc[nt][3] - m2));
        }

        // ---- l += P . ones (row sums via tensor core, fp32 accum).
#pragma unroll
        for (int s = 0; s < 4; s++)
            MMA16816(lacc, pah[s][0], pah[s][1], pah[s][2], pah[s][3], ONES_H2, ONES_H2);

        // ---- O += P V : V fragments via ldmatrix.trans.
#pragma unroll
        for (int s = 0; s < 4; s++) {
            uint32_t bt[8][2];
#pragma unroll
            for (int p = 0; p < 4; p++) {
                uint32_t off = (uint32_t)(((s * 16 + vrow) * 72 + p * 16 + vcol) * 2);
                LDSM4T(bt[2 * p][0], bt[2 * p][1], bt[2 * p + 1][0], bt[2 * p + 1][1], vb + off);
            }
#pragma unroll
            for (int dt = 0; dt < 8; dt++)
                MMA16816(oacc[dt], pah[s][0], pah[s][1], pah[s][2], pah[s][3], bt[dt][0], bt[dt][1]);
        }
        __syncthreads();
    }

    float inv1 = 1.0f / lacc[0], inv2 = 1.0f / lacc[2];

    size_t row1 = qrow0 + warp * 16 + r1;
#pragma unroll
    for (int nt = 0; nt < 8; nt++) {
        int col = h * 64 + nt * 8 + (lane & 3) * 2;
        *(uint32_t*)&Oh[row1 * Dd + col] =
            pack_h2(oacc[nt][0] * inv1, oacc[nt][1] * inv1);
        *(uint32_t*)&Oh[(row1 + 8) * Dd + col] =
            pack_h2(oacc[nt][2] * inv2, oacc[nt][3] * inv2);
    }
}

// ---------------------------------------------------------------------------
extern "C" void kernel_launch(void* const* d_in, const int* in_sizes, int n_in,
                              void* d_out, int out_size) {
    (void)in_sizes; (void)n_in; (void)out_size;

    const float* q    = (const float*)d_in[0];
    const float* k    = (const float*)d_in[1];
    const float* v    = (const float*)d_in[2];
    const int*   mask = (const int*)d_in[3];
    const float* WQw  = (const float*)d_in[4];
    const float* WQb  = (const float*)d_in[5];
    const float* WKw  = (const float*)d_in[6];
    const float* WKb  = (const float*)d_in[7];
    const float* WVw  = (const float*)d_in[8];
    const float* WVb  = (const float*)d_in[9];
    const float* WOw  = (const float*)d_in[10];
    const float* WOb  = (const float*)d_in[11];
    float* out = (float*)d_out;

    __half *qh, *kh, *vh, *Qh, *Kh, *Vh, *AOh;
    __half *WQh, *WKh, *WVh, *WOh;
    uint32_t* Mb;
    cudaGetSymbolAddress((void**)&qh, g_qh);
    cudaGetSymbolAddress((void**)&kh, g_kh);
    cudaGetSymbolAddress((void**)&vh, g_vh);
    cudaGetSymbolAddress((void**)&Qh, g_Qh);
    cudaGetSymbolAddress((void**)&Kh, g_Kh);
    cudaGetSymbolAddress((void**)&Vh, g_Vh);
    cudaGetSymbolAddress((void**)&AOh, g_AOh);
    cudaGetSymbolAddress((void**)&WQh, g_WQh);
    cudaGetSymbolAddress((void**)&WKh, g_WKh);
    cudaGetSymbolAddress((void**)&WVh, g_WVh);
    cudaGetSymbolAddress((void**)&WOh, g_WOh);
    cudaGetSymbolAddress((void**)&Mb, g_mbits);

    cudaFuncSetAttribute(gemm_sp<0>, cudaFuncAttributeMaxDynamicSharedMemorySize, GSMEM);
    cudaFuncSetAttribute(gemm_sp<2>, cudaFuncAttributeMaxDynamicSharedMemorySize, GSMEM);

    pack_mask<<<(Bb * Ss * (Ss / 32)) / 256, 256>>>(mask, Mb);

    const int nTok = Bb * Ss * Dd;
    const int nW   = Dd * Dd;
    quant3<<<dim3(nTok / 1024, 3), 256>>>(q, k, v, qh, kh, vh);
    quant4<<<dim3(nW / 1024, 4), 256>>>(WQw, WKw, WVw, WOw, WQh, WKh, WVh, WOh);

    const float QSCALE = 0.125f * 1.44269504f;  // 1/sqrt(64) * log2(e)
    dim3 gg(Dd / 128, (Bb * Ss) / 128);  // (8, 64)
    gemm_sp<2><<<gg, 256, GSMEM>>>(qh, WQh, WQb, nullptr, Qh, QSCALE);
    gemm_sp<2><<<gg, 256, GSMEM>>>(kh, WKh, WKb, nullptr, Kh, 1.0f);
    gemm_sp<2><<<gg, 256, GSMEM>>>(vh, WVh, WVb, nullptr, Vh, 1.0f);

    attn_tc<<<dim3(Ss / 64, Hh, Bb), 128>>>(Qh, Kh, Vh, Mb, AOh);

    gemm_sp<0><<<gg, 256, GSMEM>>>(AOh, WOh, WOb, out, nullptr, 1.0f);
}

// round 14
// speedup vs baseline: 8.2998x; 1.0221x over previous
#include <cuda_runtime.h>
#include <cuda_fp16.h>
#include <math.h>
#include <cstdint>

#define Bb 8
#define Ss 1024
#define Dd 1024
#define Hh 16
#define DKk 64

// ---- Scratch: everything single-plane fp16 ----
__device__ __half g_qh[(size_t)Bb * Ss * Dd];
__device__ __half g_kh[(size_t)Bb * Ss * Dd];
__device__ __half g_vh[(size_t)Bb * Ss * Dd];
__device__ __half g_Qh[(size_t)Bb * Ss * Dd];   // pre-scaled by 0.125*log2(e)
__device__ __half g_Kh[(size_t)Bb * Ss * Dd];
__device__ __half g_Vh[(size_t)Bb * Ss * Dd];
__device__ __half g_AOh[(size_t)Bb * Ss * Dd];
__device__ __half g_WQh[Dd * Dd], g_WKh[Dd * Dd], g_WVh[Dd * Dd], g_WOh[Dd * Dd];
__device__ uint32_t g_mbits[(size_t)Bb * Ss * (Ss / 32)];

#define LDSM4(r0, r1, r2, r3, addr)                                          \
    asm volatile("ldmatrix.sync.aligned.m8n8.x4.shared.b16 {%0,%1,%2,%3}, [%4];" \
                 : "=r"(r0), "=r"(r1), "=r"(r2), "=r"(r3) : "r"(addr))

#define LDSM4T(r0, r1, r2, r3, addr)                                         \
    asm volatile("ldmatrix.sync.aligned.m8n8.x4.trans.shared.b16 {%0,%1,%2,%3}, [%4];" \
                 : "=r"(r0), "=r"(r1), "=r"(r2), "=r"(r3) : "r"(addr))

#define MMA16816(d, a0, a1, a2, a3, b0, b1)                                  \
    asm volatile(                                                            \
        "mma.sync.aligned.m16n8k16.row.col.f32.f16.f16.f32 "                 \
        "{%0,%1,%2,%3}, {%4,%5,%6,%7}, {%8,%9}, {%0,%1,%2,%3};"              \
        : "+f"(d[0]), "+f"(d[1]), "+f"(d[2]), "+f"(d[3])                     \
        : "r"(a0), "r"(a1), "r"(a2), "r"(a3), "r"(b0), "r"(b1))

#define CP16(dst, src)                                                       \
    asm volatile("cp.async.cg.shared.global [%0], [%1], 16;" ::"r"(dst), "l"(src))
#define CP_COMMIT asm volatile("cp.async.commit_group;")
#define CP_WAIT1  asm volatile("cp.async.wait_group 1;")
#define CP_WAIT0  asm volatile("cp.async.wait_group 0;")

__device__ __forceinline__ uint32_t pack_h2(float a, float b) {
    __half2 t = __floats2half2_rn(a, b);
    return *(uint32_t*)&t;
}
__device__ __forceinline__ uint32_t h2exp2_u(uint32_t x) {
    __half2 v = *(__half2*)&x;
    __half2 r = h2exp2(v);
    return *(uint32_t*)&r;
}

// ---------------------------------------------------------------------------
// Fused prep: token quant (y=0..2), weight quant (y=3..6), mask pack (y=7).
// grid = (8192, 8); weight/mask rows early-exit past their extent.
// ---------------------------------------------------------------------------
__global__ void prep_all(const float* __restrict__ q, const float* __restrict__ k,
                         const float* __restrict__ v,
                         const float* __restrict__ wq, const float* __restrict__ wk,
                         const float* __restrict__ wv, const float* __restrict__ wo,
                         const int* __restrict__ mask,
                         __half* __restrict__ qh, __half* __restrict__ kh,
                         __half* __restrict__ vh,
                         __half* __restrict__ wqh, __half* __restrict__ wkh,
                         __half* __restrict__ wvh, __half* __restrict__ woh,
                         uint32_t* __restrict__ bits) {
    const int y = blockIdx.y;
    if (y < 3) {
        const float* src = (y == 0) ? q : (y == 1) ? k : v;
        __half* dst      = (y == 0) ? qh : (y == 1) ? kh : vh;
        size_t i = ((size_t)blockIdx.x * 256 + threadIdx.x) * 4;
        float4 t = *(const float4*)(src + i);
        *(uint2*)(dst + i) = make_uint2(pack_h2(t.x, t.y), pack_h2(t.z, t.w));
    } else if (y < 7) {
        if (blockIdx.x >= 1024) return;
        const float* src = (y == 3) ? wq : (y == 4) ? wk : (y == 5) ? wv : wo;
        __half* dst      = (y == 3) ? wqh : (y == 4) ? wkh : (y == 5) ? wvh : woh;
        size_t i = ((size_t)blockIdx.x * 256 + threadIdx.x) * 4;
        float4 t = *(const float4*)(src + i);
        *(uint2*)(dst + i) = make_uint2(pack_h2(t.x, t.y), pack_h2(t.z, t.w));
    } else {
        if (blockIdx.x >= 1024) return;
        size_t w = (size_t)blockIdx.x * 256 + threadIdx.x;
        const int* p = mask + w * 32;
        uint32_t val = 0;
#pragma unroll
        for (int i = 0; i < 32; i += 4) {
            int4 t = *(const int4*)(p + i);
            val |= (uint32_t)(t.x != 0) << i;
            val |= (uint32_t)(t.y != 0) << (i + 1);
            val |= (uint32_t)(t.z != 0) << (i + 2);
            val |= (uint32_t)(t.w != 0) << (i + 3);
        }
        bits[w] = val;
    }
}

// ---------------------------------------------------------------------------
// fp16 single-pass GEMM, BK=64, 2-stage cp.async, 2 CTAs/SM.
// QKV_FUSED: blockIdx.z selects (A, W, bias, out, scale). Else single GEMM.
// OUT_MODE: 0 = f32 out, 2 = fp16 out.
// ---------------------------------------------------------------------------
#define GSTG 36864u
#define GA_OFF 0u
#define GB_OFF 18432u
#define GSMEM (2u * GSTG)  // 73728

template <int OUT_MODE, int QKV_FUSED>
__global__ __launch_bounds__(256, 2) void gemm_sp(
    const __half* __restrict__ A0, const __half* __restrict__ A1,
    const __half* __restrict__ A2,
    const __half* __restrict__ B0, const __half* __restrict__ B1,
    const __half* __restrict__ B2,
    const float* __restrict__ bias0, const float* __restrict__ bias1,
    const float* __restrict__ bias2,
    float* __restrict__ Y,
    __half* __restrict__ Yh0, __half* __restrict__ Yh1, __half* __restrict__ Yh2,
    float scale0) {
    const int K = 1024, N = 1024;
    extern __shared__ char smem_raw[];
    const uint32_t smem_base = (uint32_t)__cvta_generic_to_shared(smem_raw);

    const int z = QKV_FUSED ? blockIdx.z : 0;
    const __half* Ahg = (z == 0) ? A0 : (z == 1) ? A1 : A2;
    const __half* Bhg = (z == 0) ? B0 : (z == 1) ? B1 : B2;
    const float* bias = (z == 0) ? bias0 : (z == 1) ? bias1 : bias2;
    __half* Yh        = (z == 0) ? Yh0 : (z == 1) ? Yh1 : Yh2;
    const float oscale = (QKV_FUSED && z != 0) ? 1.0f : scale0;

    const int tid  = threadIdx.x;
    const int lane = tid & 31;
    const int warp = tid >> 5;
    const int wm   = warp >> 1;
    const int wn   = warp & 1;

    const __half* srcA[4];
    const __half* srcB[4];
    uint32_t dst[4];
#pragma unroll
    for (int i = 0; i < 4; i++) {
        int idx = i * 256 + tid, r = idx >> 3, c = idx & 7;
        srcA[i] = Ahg + (size_t)(blockIdx.y * 128 + r) * K + c * 8;
        srcB[i] = Bhg + (size_t)(blockIdx.x * 128 + r) * K + c * 8;
        dst[i]  = (uint32_t)(r * 144 + c * 16);
    }

    const int rb = ((lane >> 4) << 3) + (lane & 7);
    const int cb = ((lane >> 3) & 1) * 8;
    uint32_t aoff[2][4], boff[4][4];
#pragma unroll
    for (int mt = 0; mt < 2; mt++)
#pragma unroll
        for (int kk = 0; kk < 4; kk++)
            aoff[mt][kk] = (uint32_t)((wm * 32 + mt * 16 + (lane & 15)) * 144 +
                                      (lane >> 4) * 16 + kk * 32);
#pragma unroll
    for (int p = 0; p < 4; p++)
#pragma unroll
        for (int kk = 0; kk < 4; kk++)
            boff[p][kk] = (uint32_t)((wn * 64 + p * 16 + rb) * 144 + cb * 2 + kk * 32);

    float acc[2][8][4];
#pragma unroll
    for (int mt = 0; mt < 2; mt++)
#pragma unroll
        for (int nt = 0; nt < 8; nt++)
#pragma unroll
            for (int i = 0; i < 4; i++) acc[mt][nt][i] = 0.0f;

    auto load_stage = [&](int s, int k0) {
        uint32_t b = smem_base + (uint32_t)s * GSTG;
#pragma unroll
        for (int i = 0; i < 4; i++) {
            CP16(b + GA_OFF + dst[i], srcA[i] + k0);
            CP16(b + GB_OFF + dst[i], srcB[i] + k0);
        }
    };

    load_stage(0, 0); CP_COMMIT;

    const int NK = K / 64;  // 16
    for (int i = 0; i < NK; i++) {
        if (i + 1 < NK) {
            load_stage((i + 1) & 1, (i + 1) * 64);
            CP_COMMIT;
            CP_WAIT1;
        } else {
            CP_WAIT0;
        }
        __syncthreads();

        const uint32_t sb = smem_base + (uint32_t)(i & 1) * GSTG;
#pragma unroll
        for (int kk = 0; kk < 4; kk++) {
            uint32_t bh[8][2];
#pragma unroll
            for (int p = 0; p < 4; p++)
                LDSM4(bh[2 * p][0], bh[2 * p][1], bh[2 * p + 1][0], bh[2 * p + 1][1],
                      sb + GB_OFF + boff[p][kk]);
#pragma unroll
            for (int mt = 0; mt < 2; mt++) {
                uint32_t ah[4];
                LDSM4(ah[0], ah[1], ah[2], ah[3], sb + GA_OFF + aoff[mt][kk]);
#pragma unroll
                for (int nt = 0; nt < 8; nt++)
                    MMA16816(acc[mt][nt], ah[0], ah[1], ah[2], ah[3], bh[nt][0], bh[nt][1]);
            }
        }
        __syncthreads();
    }

    const int rowBase = blockIdx.y * 128 + wm * 32;
    const int colBase = blockIdx.x * 128 + wn * 64;
#pragma unroll
    for (int mt = 0; mt < 2; mt++) {
        int row = rowBase + mt * 16 + (lane >> 2);
#pragma unroll
        for (int nt = 0; nt < 8; nt++) {
            int col = colBase + nt * 8 + (lane & 3) * 2;
            float2 bv = *(const float2*)&bias[col];
            float o00 = (acc[mt][nt][0] + bv.x) * oscale;
            float o01 = (acc[mt][nt][1] + bv.y) * oscale;
            float o10 = (acc[mt][nt][2] + bv.x) * oscale;
            float o11 = (acc[mt][nt][3] + bv.y) * oscale;
            if (OUT_MODE == 2) {
                *(uint32_t*)&Yh[(size_t)row * N + col]       = pack_h2(o00, o01);
                *(uint32_t*)&Yh[(size_t)(row + 8) * N + col] = pack_h2(o10, o11);
            } else {
                *(float2*)&Y[(size_t)row * N + col]       = make_float2(o00, o01);
                *(float2*)&Y[(size_t)(row + 8) * N + col] = make_float2(o10, o11);
            }
        }
    }
}

// ---------------------------------------------------------------------------
// fp16 flash attention (unchanged from R13).
// ---------------------------------------------------------------------------
struct QStage { __half h[64][72]; };
struct KVStage { __half kh[64][72]; __half vh[64][72]; };
#define ONES_H2 0x3C003C00u

__global__ __launch_bounds__(128, 4) void attn_tc(
    const __half* __restrict__ Qh, const __half* __restrict__ Kh,
    const __half* __restrict__ Vh,
    const uint32_t* __restrict__ mbits, __half* __restrict__ Oh) {
    const int qt = blockIdx.x, h = blockIdx.y, b = blockIdx.z;
    const int tid = threadIdx.x, lane = tid & 31, warp = tid >> 5;

    __shared__ union { QStage q; KVStage kv[2]; } sm;

    const size_t qrow0 = (size_t)b * Ss + qt * 64;

    {
        int r = tid >> 1, half = tid & 1;
        const uint4* gh = (const uint4*)(Qh + (qrow0 + r) * Dd + h * 64 + half * 32);
        uint4* sh = (uint4*)&sm.q.h[r][half * 32];
#pragma unroll
        for (int i = 0; i < 4; i++) sh[i] = gh[i];
    }
    __syncthreads();

    uint32_t qfh[4][4];
    {
        uint32_t bqh = (uint32_t)__cvta_generic_to_shared(&sm.q.h[0][0]);
        int r = warp * 16 + (lane & 15);
#pragma unroll
        for (int s = 0; s < 4; s++) {
            uint32_t off = (uint32_t)((r * 72 + s * 16 + (lane >> 4) * 8) * 2);
            LDSM4(qfh[s][0], qfh[s][1], qfh[s][2], qfh[s][3], bqh + off);
        }
    }
    __syncthreads();

    const uint32_t kvbase = (uint32_t)__cvta_generic_to_shared(&sm.kv[0]);
    const uint32_t STG = (uint32_t)sizeof(KVStage);  // 18432
    const uint32_t VOFF = 9216;

    const size_t kvrow0 = ((size_t)b * Ss) * Dd + h * 64;
    uint32_t ldst[4];
    size_t lsrc[4];
#pragma unroll
    for (int i = 0; i < 4; i++) {
        int idx = i * 128 + tid, r = idx >> 3, c = idx & 7;
        ldst[i] = (uint32_t)(r * 144 + c * 16);
        lsrc[i] = (size_t)r * Dd + c * 8;
    }
    auto load_kv = [&](int s, int kt) {
        uint32_t bb = kvbase + (uint32_t)s * STG;
        size_t g = kvrow0 + (size_t)kt * 64 * Dd;
#pragma unroll
        for (int i = 0; i < 4; i++) {
            CP16(bb + ldst[i],        Kh + g + lsrc[i]);
            CP16(bb + VOFF + ldst[i], Vh + g + lsrc[i]);
        }
    };

    float oacc[8][4];
#pragma unroll
    for (int nt = 0; nt < 8; nt++)
#pragma unroll
        for (int i = 0; i < 4; i++) oacc[nt][i] = 0.0f;
    float lacc[4] = {0.f, 0.f, 0.f, 0.f};
    float m1 = -1e30f, m2 = -1e30f;

    const int rb = ((lane >> 4) << 3) + (lane & 7);
    const int cb = ((lane >> 3) & 1) * 8;
    const int r1 = lane >> 2;
    const int vrow = ((lane >> 3) & 1) * 8 + (lane & 7);
    const int vcol = (lane >> 4) * 8;
    const int lsh = (lane & 3) * 2;

    const uint32_t* mrow1 = mbits + (qrow0 + warp * 16 + r1) * 32;
    const uint32_t* mrow2 = mrow1 + 8 * 32;

    load_kv(0, 0); CP_COMMIT;

    for (int kt = 0; kt < 16; kt++) {
        if (kt + 1 < 16) {
            load_kv((kt + 1) & 1, kt + 1);
            CP_COMMIT;
            CP_WAIT1;
        } else {
            CP_WAIT0;
        }
        __syncthreads();

        const uint32_t kb = kvbase + (uint32_t)(kt & 1) * STG;
        const uint32_t vb = kb + VOFF;

        float sacc[8][4];
#pragma unroll
        for (int nt = 0; nt < 8; nt++)
#pragma unroll
            for (int i = 0; i < 4; i++) sacc[nt][i] = 0.0f;
#pragma unroll
        for (int s = 0; s < 4; s++) {
            uint32_t bh[8][2];
#pragma unroll
            for (int p = 0; p < 4; p++) {
                uint32_t off = (uint32_t)(((p * 16 + rb) * 72 + s * 16 + cb) * 2);
                LDSM4(bh[2 * p][0], bh[2 * p][1], bh[2 * p + 1][0], bh[2 * p + 1][1], kb + off);
            }
#pragma unroll
            for (int nt = 0; nt < 8; nt++)
                MMA16816(sacc[nt], qfh[s][0], qfh[s][1], qfh[s][2], qfh[s][3], bh[nt][0], bh[nt][1]);
        }

        uint32_t w10 = mrow1[kt * 2] >> lsh, w11 = mrow1[kt * 2 + 1] >> lsh;
        uint32_t w20 = mrow2[kt * 2] >> lsh, w21 = mrow2[kt * 2 + 1] >> lsh;
        float tm1 = -1e30f, tm2 = -1e30f;
#pragma unroll
        for (int nt = 0; nt < 8; nt++) {
            const int shf = (nt * 8) & 31;
            uint32_t wA = (nt < 4) ? w10 : w11;
            uint32_t wB = (nt < 4) ? w20 : w21;
            float s0 = sacc[nt][0], s1 = sacc[nt][1];
            float s2 = sacc[nt][2], s3 = sacc[nt][3];
            if (!((wA >> shf) & 1))       s0 = -1e9f;
            if (!((wA >> (shf + 1)) & 1)) s1 = -1e9f;
            if (!((wB >> shf) & 1))       s2 = -1e9f;
            if (!((wB >> (shf + 1)) & 1)) s3 = -1e9f;
            sacc[nt][0] = s0; sacc[nt][1] = s1; sacc[nt][2] = s2; sacc[nt][3] = s3;
            tm1 = fmaxf(tm1, fmaxf(s0, s1));
            tm2 = fmaxf(tm2, fmaxf(s2, s3));
        }
        tm1 = fmaxf(tm1, __shfl_xor_sync(0xffffffff, tm1, 1));
        tm1 = fmaxf(tm1, __shfl_xor_sync(0xffffffff, tm1, 2));
        tm2 = fmaxf(tm2, __shfl_xor_sync(0xffffffff, tm2, 1));
        tm2 = fmaxf(tm2, __shfl_xor_sync(0xffffffff, tm2, 2));

        float mn1 = fmaxf(m1, tm1), mn2 = fmaxf(m2, tm2);
        float a1 = exp2f(m1 - mn1), a2 = exp2f(m2 - mn2);
        m1 = mn1; m2 = mn2;
        lacc[0] *= a1; lacc[1] *= a1; lacc[2] *= a2; lacc[3] *= a2;
#pragma unroll
        for (int nt = 0; nt < 8; nt++) {
            oacc[nt][0] *= a1; oacc[nt][1] *= a1;
            oacc[nt][2] *= a2; oacc[nt][3] *= a2;
        }

        uint32_t pah[4][4];
#pragma unroll
        for (int nt = 0; nt < 8; nt++) {
            int s = nt >> 1, base = (nt & 1) * 2;
            pah[s][base]     = h2exp2_u(pack_h2(sacc[nt][0] - m1, sacc[nt][1] - m1));
            pah[s][base + 1] = h2exp2_u(pack_h2(sacc[nt][2] - m2, sacc[nt][3] - m2));
        }

#pragma unroll
        for (int s = 0; s < 4; s++)
            MMA16816(lacc, pah[s][0], pah[s][1], pah[s][2], pah[s][3], ONES_H2, ONES_H2);

#pragma unroll
        for (int s = 0; s < 4; s++) {
            uint32_t bt[8][2];
#pragma unroll
            for (int p = 0; p < 4; p++) {
                uint32_t off = (uint32_t)(((s * 16 + vrow) * 72 + p * 16 + vcol) * 2);
                LDSM4T(bt[2 * p][0], bt[2 * p][1], bt[2 * p + 1][0], bt[2 * p + 1][1], vb + off);
            }
#pragma unroll
            for (int dt = 0; dt < 8; dt++)
                MMA16816(oacc[dt], pah[s][0], pah[s][1], pah[s][2], pah[s][3], bt[dt][0], bt[dt][1]);
        }
        __syncthreads();
    }

    float inv1 = 1.0f / lacc[0], inv2 = 1.0f / lacc[2];

    size_t row1 = qrow0 + warp * 16 + r1;
#pragma unroll
    for (int nt = 0; nt < 8; nt++) {
        int col = h * 64 + nt * 8 + (lane & 3) * 2;
        *(uint32_t*)&Oh[row1 * Dd + col] =
            pack_h2(oacc[nt][0] * inv1, oacc[nt][1] * inv1);
        *(uint32_t*)&Oh[(row1 + 8) * Dd + col] =
            pack_h2(oacc[nt][2] * inv2, oacc[nt][3] * inv2);
    }
}

// ---------------------------------------------------------------------------
extern "C" void kernel_launch(void* const* d_in, const int* in_sizes, int n_in,
                              void* d_out, int out_size) {
    (void)in_sizes; (void)n_in; (void)out_size;

    const float* q    = (const float*)d_in[0];
    const float* k    = (const float*)d_in[1];
    const float* v    = (const float*)d_in[2];
    const int*   mask = (const int*)d_in[3];
    const float* WQw  = (const float*)d_in[4];
    const float* WQb  = (const float*)d_in[5];
    const float* WKw  = (const float*)d_in[6];
    const float* WKb  = (const float*)d_in[7];
    const float* WVw  = (const float*)d_in[8];
    const float* WVb  = (const float*)d_in[9];
    const float* WOw  = (const float*)d_in[10];
    const float* WOb  = (const float*)d_in[11];
    float* out = (float*)d_out;

    __half *qh, *kh, *vh, *Qh, *Kh, *Vh, *AOh;
    __half *WQh, *WKh, *WVh, *WOh;
    uint32_t* Mb;
    cudaGetSymbolAddress((void**)&qh, g_qh);
    cudaGetSymbolAddress((void**)&kh, g_kh);
    cudaGetSymbolAddress((void**)&vh, g_vh);
    cudaGetSymbolAddress((void**)&Qh, g_Qh);
    cudaGetSymbolAddress((void**)&Kh, g_Kh);
    cudaGetSymbolAddress((void**)&Vh, g_Vh);
    cudaGetSymbolAddress((void**)&AOh, g_AOh);
    cudaGetSymbolAddress((void**)&WQh, g_WQh);
    cudaGetSymbolAddress((void**)&WKh, g_WKh);
    cudaGetSymbolAddress((void**)&WVh, g_WVh);
    cudaGetSymbolAddress((void**)&WOh, g_WOh);
    cudaGetSymbolAddress((void**)&Mb, g_mbits);

    cudaFuncSetAttribute((const void*)gemm_sp<0, 0>,
                         cudaFuncAttributeMaxDynamicSharedMemorySize, GSMEM);
    cudaFuncSetAttribute((const void*)gemm_sp<2, 1>,
                         cudaFuncAttributeMaxDynamicSharedMemorySize, GSMEM);

    // 1) All prep in one launch.
    prep_all<<<dim3(8192, 8), 256>>>(q, k, v, WQw, WKw, WVw, WOw, mask,
                                     qh, kh, vh, WQh, WKh, WVh, WOh, Mb);

    // 2) Q/K/V projections fused via grid.z.
    const float QSCALE = 0.125f * 1.44269504f;  // 1/sqrt(64) * log2(e)
    dim3 gqkv(Dd / 128, (Bb * Ss) / 128, 3);  // (8, 64, 3)
    gemm_sp<2, 1><<<gqkv, 256, GSMEM>>>(qh, kh, vh, WQh, WKh, WVh,
                                        WQb, WKb, WVb, nullptr,
                                        Qh, Kh, Vh, QSCALE);

    // 3) Attention.
    attn_tc<<<dim3(Ss / 64, Hh, Bb), 128>>>(Qh, Kh, Vh, Mb, AOh);

    // 4) Output projection (f32 out).
    dim3 gg(Dd / 128, (Bb * Ss) / 128);
    gemm_sp<0, 0><<<gg, 256, GSMEM>>>(AOh, nullptr, nullptr, WOh, nullptr, nullptr,
                                      WOb, nullptr, nullptr, out,
                                      nullptr, nullptr, nullptr, 1.0f);
}

// round 15
// speedup vs baseline: 8.5684x; 1.0324x over previous
#include <cuda_runtime.h>
#include <cuda_fp16.h>
#include <math.h>
#include <cstdint>

#define Bb 8
#define Ss 1024
#define Dd 1024
#define Hh 16
#define DKk 64

// ---- Scratch: everything single-plane fp16 ----
__device__ __half g_qh[(size_t)Bb * Ss * Dd];
__device__ __half g_kh[(size_t)Bb * Ss * Dd];
__device__ __half g_vh[(size_t)Bb * Ss * Dd];
__device__ __half g_Qh[(size_t)Bb * Ss * Dd];   // pre-scaled by 0.125*log2(e)
__device__ __half g_Kh[(size_t)Bb * Ss * Dd];
__device__ __half g_Vh[(size_t)Bb * Ss * Dd];
__device__ __half g_AOh[(size_t)Bb * Ss * Dd];
__device__ __half g_WQh[Dd * Dd], g_WKh[Dd * Dd], g_WVh[Dd * Dd], g_WOh[Dd * Dd];
__device__ uint32_t g_mbits[(size_t)Bb * Ss * (Ss / 32)];

#define LDSM4(r0, r1, r2, r3, addr)                                          \
    asm volatile("ldmatrix.sync.aligned.m8n8.x4.shared.b16 {%0,%1,%2,%3}, [%4];" \
                 : "=r"(r0), "=r"(r1), "=r"(r2), "=r"(r3) : "r"(addr))

#define LDSM4T(r0, r1, r2, r3, addr)                                         \
    asm volatile("ldmatrix.sync.aligned.m8n8.x4.trans.shared.b16 {%0,%1,%2,%3}, [%4];" \
                 : "=r"(r0), "=r"(r1), "=r"(r2), "=r"(r3) : "r"(addr))

#define MMA16816(d, a0, a1, a2, a3, b0, b1)                                  \
    asm volatile(                                                            \
        "mma.sync.aligned.m16n8k16.row.col.f32.f16.f16.f32 "                 \
        "{%0,%1,%2,%3}, {%4,%5,%6,%7}, {%8,%9}, {%0,%1,%2,%3};"              \
        : "+f"(d[0]), "+f"(d[1]), "+f"(d[2]), "+f"(d[3])                     \
        : "r"(a0), "r"(a1), "r"(a2), "r"(a3), "r"(b0), "r"(b1))

#define CP16(dst, src)                                                       \
    asm volatile("cp.async.cg.shared.global [%0], [%1], 16;" ::"r"(dst), "l"(src))
#define CP_COMMIT asm volatile("cp.async.commit_group;")
#define CP_WAIT1  asm volatile("cp.async.wait_group 1;")
#define CP_WAIT0  asm volatile("cp.async.wait_group 0;")

__device__ __forceinline__ uint32_t pack_h2(float a, float b) {
    __half2 t = __floats2half2_rn(a, b);
    return *(uint32_t*)&t;
}
__device__ __forceinline__ uint32_t h2exp2_u(uint32_t x) {
    __half2 v = *(__half2*)&x;
    __half2 r = h2exp2(v);
    return *(uint32_t*)&r;
}

// ---------------------------------------------------------------------------
// Fused prep: token quant (y=0..2), weight quant (y=3..6), mask pack (y=7).
// ---------------------------------------------------------------------------
__global__ void prep_all(const float* __restrict__ q, const float* __restrict__ k,
                         const float* __restrict__ v,
                         const float* __restrict__ wq, const float* __restrict__ wk,
                         const float* __restrict__ wv, const float* __restrict__ wo,
                         const int* __restrict__ mask,
                         __half* __restrict__ qh, __half* __restrict__ kh,
                         __half* __restrict__ vh,
                         __half* __restrict__ wqh, __half* __restrict__ wkh,
                         __half* __restrict__ wvh, __half* __restrict__ woh,
                         uint32_t* __restrict__ bits) {
    const int y = blockIdx.y;
    if (y < 3) {
        const float* src = (y == 0) ? q : (y == 1) ? k : v;
        __half* dst      = (y == 0) ? qh : (y == 1) ? kh : vh;
        size_t i = ((size_t)blockIdx.x * 256 + threadIdx.x) * 4;
        float4 t = *(const float4*)(src + i);
        *(uint2*)(dst + i) = make_uint2(pack_h2(t.x, t.y), pack_h2(t.z, t.w));
    } else if (y < 7) {
        if (blockIdx.x >= 1024) return;
        const float* src = (y == 3) ? wq : (y == 4) ? wk : (y == 5) ? wv : wo;
        __half* dst      = (y == 3) ? wqh : (y == 4) ? wkh : (y == 5) ? wvh : woh;
        size_t i = ((size_t)blockIdx.x * 256 + threadIdx.x) * 4;
        float4 t = *(const float4*)(src + i);
        *(uint2*)(dst + i) = make_uint2(pack_h2(t.x, t.y), pack_h2(t.z, t.w));
    } else {
        if (blockIdx.x >= 1024) return;
        size_t w = (size_t)blockIdx.x * 256 + threadIdx.x;
        const int* p = mask + w * 32;
        uint32_t val = 0;
#pragma unroll
        for (int i = 0; i < 32; i += 4) {
            int4 t = *(const int4*)(p + i);
            val |= (uint32_t)(t.x != 0) << i;
            val |= (uint32_t)(t.y != 0) << (i + 1);
            val |= (uint32_t)(t.z != 0) << (i + 2);
            val |= (uint32_t)(t.w != 0) << (i + 3);
        }
        bits[w] = val;
    }
}

// ---------------------------------------------------------------------------
// fp16 GEMM, BK=64, 3-stage cp.async, warp tile 64x32 (2x4 layout), 2 CTAs/SM.
// Per warp per kk: 4 A-ldsm + 2 B-ldsm for 16 MMA (was 10 ldsm in 4x2 layout).
// ---------------------------------------------------------------------------
#define GSTG 36864u
#define GA_OFF 0u
#define GB_OFF 18432u
#define GSMEM (3u * GSTG)  // 110592

template <int OUT_MODE, int QKV_FUSED>
__global__ __launch_bounds__(256, 2) void gemm_sp(
    const __half* __restrict__ A0, const __half* __restrict__ A1,
    const __half* __restrict__ A2,
    const __half* __restrict__ B0, const __half* __restrict__ B1,
    const __half* __restrict__ B2,
    const float* __restrict__ bias0, const float* __restrict__ bias1,
    const float* __restrict__ bias2,
    float* __restrict__ Y,
    __half* __restrict__ Yh0, __half* __restrict__ Yh1, __half* __restrict__ Yh2,
    float scale0) {
    const int K = 1024, N = 1024;
    extern __shared__ char smem_raw[];
    const uint32_t smem_base = (uint32_t)__cvta_generic_to_shared(smem_raw);

    const int z = QKV_FUSED ? blockIdx.z : 0;
    const __half* Ahg = (z == 0) ? A0 : (z == 1) ? A1 : A2;
    const __half* Bhg = (z == 0) ? B0 : (z == 1) ? B1 : B2;
    const float* bias = (z == 0) ? bias0 : (z == 1) ? bias1 : bias2;
    __half* Yh        = (z == 0) ? Yh0 : (z == 1) ? Yh1 : Yh2;
    const float oscale = (QKV_FUSED && z != 0) ? 1.0f : scale0;

    const int tid  = threadIdx.x;
    const int lane = tid & 31;
    const int warp = tid >> 5;
    const int wm   = warp >> 2;  // 0..1 : 64-row slab
    const int wn   = warp & 3;   // 0..3 : 32-col slab

    const __half* srcA[4];
    const __half* srcB[4];
    uint32_t dst[4];
#pragma unroll
    for (int i = 0; i < 4; i++) {
        int idx = i * 256 + tid, r = idx >> 3, c = idx & 7;
        srcA[i] = Ahg + (size_t)(blockIdx.y * 128 + r) * K + c * 8;
        srcB[i] = Bhg + (size_t)(blockIdx.x * 128 + r) * K + c * 8;
        dst[i]  = (uint32_t)(r * 144 + c * 16);
    }

    const int rb = ((lane >> 4) << 3) + (lane & 7);
    const int cb = ((lane >> 3) & 1) * 8;
    uint32_t aoff[4][4], boff[2][4];
#pragma unroll
    for (int mt = 0; mt < 4; mt++)
#pragma unroll
        for (int kk = 0; kk < 4; kk++)
            aoff[mt][kk] = (uint32_t)((wm * 64 + mt * 16 + (lane & 15)) * 144 +
                                      (lane >> 4) * 16 + kk * 32);
#pragma unroll
    for (int p = 0; p < 2; p++)
#pragma unroll
        for (int kk = 0; kk < 4; kk++)
            boff[p][kk] = (uint32_t)((wn * 32 + p * 16 + rb) * 144 + cb * 2 + kk * 32);

    float acc[4][4][4];
#pragma unroll
    for (int mt = 0; mt < 4; mt++)
#pragma unroll
        for (int nt = 0; nt < 4; nt++)
#pragma unroll
            for (int i = 0; i < 4; i++) acc[mt][nt][i] = 0.0f;

    auto load_stage = [&](int s, int k0) {
        uint32_t b = smem_base + (uint32_t)s * GSTG;
#pragma unroll
        for (int i = 0; i < 4; i++) {
            CP16(b + GA_OFF + dst[i], srcA[i] + k0);
            CP16(b + GB_OFF + dst[i], srcB[i] + k0);
        }
    };

    load_stage(0, 0);  CP_COMMIT;
    load_stage(1, 64); CP_COMMIT;

    const int NK = K / 64;  // 16
    int stg = 0;
    for (int i = 0; i < NK; i++) {
        if (i + 1 < NK) { CP_WAIT1; } else { CP_WAIT0; }
        __syncthreads();
        if (i + 2 < NK) {
            int ns = stg + 2; if (ns >= 3) ns -= 3;
            load_stage(ns, (i + 2) * 64);
            CP_COMMIT;
        }

        const uint32_t sb = smem_base + (uint32_t)stg * GSTG;
#pragma unroll
        for (int kk = 0; kk < 4; kk++) {
            uint32_t bh[4][2];
#pragma unroll
            for (int p = 0; p < 2; p++)
                LDSM4(bh[2 * p][0], bh[2 * p][1], bh[2 * p + 1][0], bh[2 * p + 1][1],
                      sb + GB_OFF + boff[p][kk]);
#pragma unroll
            for (int mt = 0; mt < 4; mt++) {
                uint32_t ah[4];
                LDSM4(ah[0], ah[1], ah[2], ah[3], sb + GA_OFF + aoff[mt][kk]);
#pragma unroll
                for (int nt = 0; nt < 4; nt++)
                    MMA16816(acc[mt][nt], ah[0], ah[1], ah[2], ah[3], bh[nt][0], bh[nt][1]);
            }
        }
        if (++stg >= 3) stg = 0;
    }

    const int rowBase = blockIdx.y * 128 + wm * 64;
    const int colBase = blockIdx.x * 128 + wn * 32;
#pragma unroll
    for (int mt = 0; mt < 4; mt++) {
        int row = rowBase + mt * 16 + (lane >> 2);
#pragma unroll
        for (int nt = 0; nt < 4; nt++) {
            int col = colBase + nt * 8 + (lane & 3) * 2;
            float2 bv = *(const float2*)&bias[col];
            float o00 = (acc[mt][nt][0] + bv.x) * oscale;
            float o01 = (acc[mt][nt][1] + bv.y) * oscale;
            float o10 = (acc[mt][nt][2] + bv.x) * oscale;
            float o11 = (acc[mt][nt][3] + bv.y) * oscale;
            if (OUT_MODE == 2) {
                *(uint32_t*)&Yh[(size_t)row * N + col]       = pack_h2(o00, o01);
                *(uint32_t*)&Yh[(size_t)(row + 8) * N + col] = pack_h2(o10, o11);
            } else {
                *(float2*)&Y[(size_t)row * N + col]       = make_float2(o00, o01);
                *(float2*)&Y[(size_t)(row + 8) * N + col] = make_float2(o10, o11);
            }
        }
    }
}

// ---------------------------------------------------------------------------
// fp16 flash attention (unchanged from R13/R14).
// ---------------------------------------------------------------------------
struct QStage { __half h[64][72]; };
struct KVStage { __half kh[64][72]; __half vh[64][72]; };
#define ONES_H2 0x3C003C00u

__global__ __launch_bounds__(128, 4) void attn_tc(
    const __half* __restrict__ Qh, const __half* __restrict__ Kh,
    const __half* __restrict__ Vh,
    const uint32_t* __restrict__ mbits, __half* __restrict__ Oh) {
    const int qt = blockIdx.x, h = blockIdx.y, b = blockIdx.z;
    const int tid = threadIdx.x, lane = tid & 31, warp = tid >> 5;

    __shared__ union { QStage q; KVStage kv[2]; } sm;

    const size_t qrow0 = (size_t)b * Ss + qt * 64;

    {
        int r = tid >> 1, half = tid & 1;
        const uint4* gh = (const uint4*)(Qh + (qrow0 + r) * Dd + h * 64 + half * 32);
        uint4* sh = (uint4*)&sm.q.h[r][half * 32];
#pragma unroll
        for (int i = 0; i < 4; i++) sh[i] = gh[i];
    }
    __syncthreads();

    uint32_t qfh[4][4];
    {
        uint32_t bqh = (uint32_t)__cvta_generic_to_shared(&sm.q.h[0][0]);
        int r = warp * 16 + (lane & 15);
#pragma unroll
        for (int s = 0; s < 4; s++) {
            uint32_t off = (uint32_t)((r * 72 + s * 16 + (lane >> 4) * 8) * 2);
            LDSM4(qfh[s][0], qfh[s][1], qfh[s][2], qfh[s][3], bqh + off);
        }
    }
    __syncthreads();

    const uint32_t kvbase = (uint32_t)__cvta_generic_to_shared(&sm.kv[0]);
    const uint32_t STG = (uint32_t)sizeof(KVStage);  // 18432
    const uint32_t VOFF = 9216;

    const size_t kvrow0 = ((size_t)b * Ss) * Dd + h * 64;
    uint32_t ldst[4];
    size_t lsrc[4];
#pragma unroll
    for (int i = 0; i < 4; i++) {
        int idx = i * 128 + tid, r = idx >> 3, c = idx & 7;
        ldst[i] = (uint32_t)(r * 144 + c * 16);
        lsrc[i] = (size_t)r * Dd + c * 8;
    }
    auto load_kv = [&](int s, int kt) {
        uint32_t bb = kvbase + (uint32_t)s * STG;
        size_t g = kvrow0 + (size_t)kt * 64 * Dd;
#pragma unroll
        for (int i = 0; i < 4; i++) {
            CP16(bb + ldst[i],        Kh + g + lsrc[i]);
            CP16(bb + VOFF + ldst[i], Vh + g + lsrc[i]);
        }
    };

    float oacc[8][4];
#pragma unroll
    for (int nt = 0; nt < 8; nt++)
#pragma unroll
        for (int i = 0; i < 4; i++) oacc[nt][i] = 0.0f;
    float lacc[4] = {0.f, 0.f, 0.f, 0.f};
    float m1 = -1e30f, m2 = -1e30f;

    const int rb = ((lane >> 4) << 3) + (lane & 7);
    const int cb = ((lane >> 3) & 1) * 8;
    const int r1 = lane >> 2;
    const int vrow = ((lane >> 3) & 1) * 8 + (lane & 7);
    const int vcol = (lane >> 4) * 8;
    const int lsh = (lane & 3) * 2;

    const uint32_t* mrow1 = mbits + (qrow0 + warp * 16 + r1) * 32;
    const uint32_t* mrow2 = mrow1 + 8 * 32;

    load_kv(0, 0); CP_COMMIT;

    for (int kt = 0; kt < 16; kt++) {
        if (kt + 1 < 16) {
            load_kv((kt + 1) & 1, kt + 1);
            CP_COMMIT;
            CP_WAIT1;
        } else {
            CP_WAIT0;
        }
        __syncthreads();

        const uint32_t kb = kvbase + (uint32_t)(kt & 1) * STG;
        const uint32_t vb = kb + VOFF;

        float sacc[8][4];
#pragma unroll
        for (int nt = 0; nt < 8; nt++)
#pragma unroll
            for (int i = 0; i < 4; i++) sacc[nt][i] = 0.0f;
#pragma unroll
        for (int s = 0; s < 4; s++) {
            uint32_t bh[8][2];
#pragma unroll
            for (int p = 0; p < 4; p++) {
                uint32_t off = (uint32_t)(((p * 16 + rb) * 72 + s * 16 + cb) * 2);
                LDSM4(bh[2 * p][0], bh[2 * p][1], bh[2 * p + 1][0], bh[2 * p + 1][1], kb + off);
            }
#pragma unroll
            for (int nt = 0; nt < 8; nt++)
                MMA16816(sacc[nt], qfh[s][0], qfh[s][1], qfh[s][2], qfh[s][3], bh[nt][0], bh[nt][1]);
        }

        uint32_t w10 = mrow1[kt * 2] >> lsh, w11 = mrow1[kt * 2 + 1] >> lsh;
        uint32_t w20 = mrow2[kt * 2] >> lsh, w21 = mrow2[kt * 2 + 1] >> lsh;
        float tm1 = -1e30f, tm2 = -1e30f;
#pragma unroll
        for (int nt = 0; nt < 8; nt++) {
            const int shf = (nt * 8) & 31;
            uint32_t wA = (nt < 4) ? w10 : w11;
            uint32_t wB = (nt < 4) ? w20 : w21;
            float s0 = sacc[nt][0], s1 = sacc[nt][1];
            float s2 = sacc[nt][2], s3 = sacc[nt][3];
            if (!((wA >> shf) & 1))       s0 = -1e9f;
            if (!((wA >> (shf + 1)) & 1)) s1 = -1e9f;
            if (!((wB >> shf) & 1))       s2 = -1e9f;
            if (!((wB >> (shf + 1)) & 1)) s3 = -1e9f;
            sacc[nt][0] = s0; sacc[nt][1] = s1; sacc[nt][2] = s2; sacc[nt][3] = s3;
            tm1 = fmaxf(tm1, fmaxf(s0, s1));
            tm2 = fmaxf(tm2, fmaxf(s2, s3));
        }
        tm1 = fmaxf(tm1, __shfl_xor_sync(0xffffffff, tm1, 1));
        tm1 = fmaxf(tm1, __shfl_xor_sync(0xffffffff, tm1, 2));
        tm2 = fmaxf(tm2, __shfl_xor_sync(0xffffffff, tm2, 1));
        tm2 = fmaxf(tm2, __shfl_xor_sync(0xffffffff, tm2, 2));

        float mn1 = fmaxf(m1, tm1), mn2 = fmaxf(m2, tm2);
        float a1 = exp2f(m1 - mn1), a2 = exp2f(m2 - mn2);
        m1 = mn1; m2 = mn2;
        lacc[0] *= a1; lacc[1] *= a1; lacc[2] *= a2; lacc[3] *= a2;
#pragma unroll
        for (int nt = 0; nt < 8; nt++) {
            oacc[nt][0] *= a1; oacc[nt][1] *= a1;
            oacc[nt][2] *= a2; oacc[nt][3] *= a2;
        }

        uint32_t pah[4][4];
#pragma unroll
        for (int nt = 0; nt < 8; nt++) {
            int s = nt >> 1, base = (nt & 1) * 2;
            pah[s][base]     = h2exp2_u(pack_h2(sacc[nt][0] - m1, sacc[nt][1] - m1));
            pah[s][base + 1] = h2exp2_u(pack_h2(sacc[nt][2] - m2, sacc[nt][3] - m2));
        }

#pragma unroll
        for (int s = 0; s < 4; s++)
            MMA16816(lacc, pah[s][0], pah[s][1], pah[s][2], pah[s][3], ONES_H2, ONES_H2);

#pragma unroll
        for (int s = 0; s < 4; s++) {
            uint32_t bt[8][2];
#pragma unroll
            for (int p = 0; p < 4; p++) {
                uint32_t off = (uint32_t)(((s * 16 + vrow) * 72 + p * 16 + vcol) * 2);
                LDSM4T(bt[2 * p][0], bt[2 * p][1], bt[2 * p + 1][0], bt[2 * p + 1][1], vb + off);
            }
#pragma unroll
            for (int dt = 0; dt < 8; dt++)
                MMA16816(oacc[dt], pah[s][0], pah[s][1], pah[s][2], pah[s][3], bt[dt][0], bt[dt][1]);
        }
        __syncthreads();
    }

    float inv1 = 1.0f / lacc[0], inv2 = 1.0f / lacc[2];

    size_t row1 = qrow0 + warp * 16 + r1;
#pragma unroll
    for (int nt = 0; nt < 8; nt++) {
        int col = h * 64 + nt * 8 + (lane & 3) * 2;
        *(uint32_t*)&Oh[row1 * Dd + col] =
            pack_h2(oacc[nt][0] * inv1, oacc[nt][1] * inv1);
        *(uint32_t*)&Oh[(row1 + 8) * Dd + col] =
            pack_h2(oacc[nt][2] * inv2, oacc[nt][3] * inv2);
    }
}

// ---------------------------------------------------------------------------
extern "C" void kernel_launch(void* const* d_in, const int* in_sizes, int n_in,
                              void* d_out, int out_size) {
    (void)in_sizes; (void)n_in; (void)out_size;

    const float* q    = (const float*)d_in[0];
    const float* k    = (const float*)d_in[1];
    const float* v    = (const float*)d_in[2];
    const int*   mask = (const int*)d_in[3];
    const float* WQw  = (const float*)d_in[4];
    const float* WQb  = (const float*)d_in[5];
    const float* WKw  = (const float*)d_in[6];
    const float* WKb  = (const float*)d_in[7];
    const float* WVw  = (const float*)d_in[8];
    const float* WVb  = (const float*)d_in[9];
    const float* WOw  = (const float*)d_in[10];
    const float* WOb  = (const float*)d_in[11];
    float* out = (float*)d_out;

    __half *qh, *kh, *vh, *Qh, *Kh, *Vh, *AOh;
    __half *WQh, *WKh, *WVh, *WOh;
    uint32_t* Mb;
    cudaGetSymbolAddress((void**)&qh, g_qh);
    cudaGetSymbolAddress((void**)&kh, g_kh);
    cudaGetSymbolAddress((void**)&vh, g_vh);
    cudaGetSymbolAddress((void**)&Qh, g_Qh);
    cudaGetSymbolAddress((void**)&Kh, g_Kh);
    cudaGetSymbolAddress((void**)&Vh, g_Vh);
    cudaGetSymbolAddress((void**)&AOh, g_AOh);
    cudaGetSymbolAddress((void**)&WQh, g_WQh);
    cudaGetSymbolAddress((void**)&WKh, g_WKh);
    cudaGetSymbolAddress((void**)&WVh, g_WVh);
    cudaGetSymbolAddress((void**)&WOh, g_WOh);
    cudaGetSymbolAddress((void**)&Mb, g_mbits);

    cudaFuncSetAttribute((const void*)gemm_sp<0, 0>,
                         cudaFuncAttributeMaxDynamicSharedMemorySize, GSMEM);
    cudaFuncSetAttribute((const void*)gemm_sp<2, 1>,
                         cudaFuncAttributeMaxDynamicSharedMemorySize, GSMEM);

    prep_all<<<dim3(8192, 8), 256>>>(q, k, v, WQw, WKw, WVw, WOw, mask,
                                     qh, kh, vh, WQh, WKh, WVh, WOh, Mb);

    const float QSCALE = 0.125f * 1.44269504f;  // 1/sqrt(64) * log2(e)
    dim3 gqkv(Dd / 128, (Bb * Ss) / 128, 3);  // (8, 64, 3)
    gemm_sp<2, 1><<<gqkv, 256, GSMEM>>>(qh, kh, vh, WQh, WKh, WVh,
                                        WQb, WKb, WVb, nullptr,
                                        Qh, Kh, Vh, QSCALE);

    attn_tc<<<dim3(Ss / 64, Hh, Bb), 128>>>(Qh, Kh, Vh, Mb, AOh);

    dim3 gg(Dd / 128, (Bb * Ss) / 128);
    gemm_sp<0, 0><<<gg, 256, GSMEM>>>(AOh, nullptr, nullptr, WOh, nullptr, nullptr,
                                      WOb, nullptr, nullptr, out,
                                      nullptr, nullptr, nullptr, 1.0f);
}

// round 16
// speedup vs baseline: 8.7437x; 1.0205x over previous
#include <cuda_runtime.h>
#include <cuda_fp16.h>
#include <math.h>
#include <cstdint>

#define Bb 8
#define Ss 1024
#define Dd 1024
#define Hh 16
#define DKk 64

// ---- Scratch: everything single-plane fp16 ----
__device__ __half g_qh[(size_t)Bb * Ss * Dd];
__device__ __half g_kh[(size_t)Bb * Ss * Dd];
__device__ __half g_vh[(size_t)Bb * Ss * Dd];
__device__ __half g_Qh[(size_t)Bb * Ss * Dd];   // pre-scaled by 0.125*log2(e)
__device__ __half g_Kh[(size_t)Bb * Ss * Dd];
__device__ __half g_Vh[(size_t)Bb * Ss * Dd];
__device__ __half g_AOh[(size_t)Bb * Ss * Dd];
__device__ __half g_WQh[Dd * Dd], g_WKh[Dd * Dd], g_WVh[Dd * Dd], g_WOh[Dd * Dd];
__device__ uint32_t g_mbits[(size_t)Bb * Ss * (Ss / 32)];

#define LDSM4(r0, r1, r2, r3, addr)                                          \
    asm volatile("ldmatrix.sync.aligned.m8n8.x4.shared.b16 {%0,%1,%2,%3}, [%4];" \
                 : "=r"(r0), "=r"(r1), "=r"(r2), "=r"(r3) : "r"(addr))

#define LDSM4T(r0, r1, r2, r3, addr)                                         \
    asm volatile("ldmatrix.sync.aligned.m8n8.x4.trans.shared.b16 {%0,%1,%2,%3}, [%4];" \
                 : "=r"(r0), "=r"(r1), "=r"(r2), "=r"(r3) : "r"(addr))

#define MMA16816(d, a0, a1, a2, a3, b0, b1)                                  \
    asm volatile(                                                            \
        "mma.sync.aligned.m16n8k16.row.col.f32.f16.f16.f32 "                 \
        "{%0,%1,%2,%3}, {%4,%5,%6,%7}, {%8,%9}, {%0,%1,%2,%3};"              \
        : "+f"(d[0]), "+f"(d[1]), "+f"(d[2]), "+f"(d[3])                     \
        : "r"(a0), "r"(a1), "r"(a2), "r"(a3), "r"(b0), "r"(b1))

#define CP16(dst, src)                                                       \
    asm volatile("cp.async.cg.shared.global [%0], [%1], 16;" ::"r"(dst), "l"(src))
#define CP_COMMIT asm volatile("cp.async.commit_group;")
#define CP_WAIT1  asm volatile("cp.async.wait_group 1;")
#define CP_WAIT0  asm volatile("cp.async.wait_group 0;")

__device__ __forceinline__ uint32_t pack_h2(float a, float b) {
    __half2 t = __floats2half2_rn(a, b);
    return *(uint32_t*)&t;
}
__device__ __forceinline__ uint32_t h2exp2_u(uint32_t x) {
    __half2 v = *(__half2*)&x;
    __half2 r = h2exp2(v);
    return *(uint32_t*)&r;
}

// ---------------------------------------------------------------------------
// Fused prep: token quant (y=0..2), weight quant (y=3..6), mask pack (y=7).
// ---------------------------------------------------------------------------
__global__ void prep_all(const float* __restrict__ q, const float* __restrict__ k,
                         const float* __restrict__ v,
                         const float* __restrict__ wq, const float* __restrict__ wk,
                         const float* __restrict__ wv, const float* __restrict__ wo,
                         const int* __restrict__ mask,
                         __half* __restrict__ qh, __half* __restrict__ kh,
                         __half* __restrict__ vh,
                         __half* __restrict__ wqh, __half* __restrict__ wkh,
                         __half* __restrict__ wvh, __half* __restrict__ woh,
                         uint32_t* __restrict__ bits) {
    const int y = blockIdx.y;
    if (y < 3) {
        const float* src = (y == 0) ? q : (y == 1) ? k : v;
        __half* dst      = (y == 0) ? qh : (y == 1) ? kh : vh;
        size_t i = ((size_t)blockIdx.x * 256 + threadIdx.x) * 4;
        float4 t = *(const float4*)(src + i);
        *(uint2*)(dst + i) = make_uint2(pack_h2(t.x, t.y), pack_h2(t.z, t.w));
    } else if (y < 7) {
        if (blockIdx.x >= 1024) return;
        const float* src = (y == 3) ? wq : (y == 4) ? wk : (y == 5) ? wv : wo;
        __half* dst      = (y == 3) ? wqh : (y == 4) ? wkh : (y == 5) ? wvh : woh;
        size_t i = ((size_t)blockIdx.x * 256 + threadIdx.x) * 4;
        float4 t = *(const float4*)(src + i);
        *(uint2*)(dst + i) = make_uint2(pack_h2(t.x, t.y), pack_h2(t.z, t.w));
    } else {
        if (blockIdx.x >= 1024) return;
        size_t w = (size_t)blockIdx.x * 256 + threadIdx.x;
        const int* p = mask + w * 32;
        uint32_t val = 0;
#pragma unroll
        for (int i = 0; i < 32; i += 4) {
            int4 t = *(const int4*)(p + i);
            val |= (uint32_t)(t.x != 0) << i;
            val |= (uint32_t)(t.y != 0) << (i + 1);
            val |= (uint32_t)(t.z != 0) << (i + 2);
            val |= (uint32_t)(t.w != 0) << (i + 3);
        }
        bits[w] = val;
    }
}

// ---------------------------------------------------------------------------
// fp16 GEMM, BK=64, 3-stage cp.async, warp tile 64x32 (2x4 layout), 2 CTAs/SM.
// All 6 ldsm per kk hoisted ahead of the 16-MMA burst.
// ---------------------------------------------------------------------------
#define GSTG 36864u
#define GA_OFF 0u
#define GB_OFF 18432u
#define GSMEM (3u * GSTG)  // 110592

template <int OUT_MODE, int QKV_FUSED>
__global__ __launch_bounds__(256, 2) void gemm_sp(
    const __half* __restrict__ A0, const __half* __restrict__ A1,
    const __half* __restrict__ A2,
    const __half* __restrict__ B0, const __half* __restrict__ B1,
    const __half* __restrict__ B2,
    const float* __restrict__ bias0, const float* __restrict__ bias1,
    const float* __restrict__ bias2,
    float* __restrict__ Y,
    __half* __restrict__ Yh0, __half* __restrict__ Yh1, __half* __restrict__ Yh2,
    float scale0) {
    const int K = 1024, N = 1024;
    extern __shared__ char smem_raw[];
    const uint32_t smem_base = (uint32_t)__cvta_generic_to_shared(smem_raw);

    const int z = QKV_FUSED ? blockIdx.z : 0;
    const __half* Ahg = (z == 0) ? A0 : (z == 1) ? A1 : A2;
    const __half* Bhg = (z == 0) ? B0 : (z == 1) ? B1 : B2;
    const float* bias = (z == 0) ? bias0 : (z == 1) ? bias1 : bias2;
    __half* Yh        = (z == 0) ? Yh0 : (z == 1) ? Yh1 : Yh2;
    const float oscale = (QKV_FUSED && z != 0) ? 1.0f : scale0;

    const int tid  = threadIdx.x;
    const int lane = tid & 31;
    const int warp = tid >> 5;
    const int wm   = warp >> 2;  // 0..1
    const int wn   = warp & 3;   // 0..3

    const __half* srcA[4];
    const __half* srcB[4];
    uint32_t dst[4];
#pragma unroll
    for (int i = 0; i < 4; i++) {
        int idx = i * 256 + tid, r = idx >> 3, c = idx & 7;
        srcA[i] = Ahg + (size_t)(blockIdx.y * 128 + r) * K + c * 8;
        srcB[i] = Bhg + (size_t)(blockIdx.x * 128 + r) * K + c * 8;
        dst[i]  = (uint32_t)(r * 144 + c * 16);
    }

    const int rb = ((lane >> 4) << 3) + (lane & 7);
    const int cb = ((lane >> 3) & 1) * 8;
    uint32_t aoff[4][4], boff[2][4];
#pragma unroll
    for (int mt = 0; mt < 4; mt++)
#pragma unroll
        for (int kk = 0; kk < 4; kk++)
            aoff[mt][kk] = (uint32_t)((wm * 64 + mt * 16 + (lane & 15)) * 144 +
                                      (lane >> 4) * 16 + kk * 32);
#pragma unroll
    for (int p = 0; p < 2; p++)
#pragma unroll
        for (int kk = 0; kk < 4; kk++)
            boff[p][kk] = (uint32_t)((wn * 32 + p * 16 + rb) * 144 + cb * 2 + kk * 32);

    float acc[4][4][4];
#pragma unroll
    for (int mt = 0; mt < 4; mt++)
#pragma unroll
        for (int nt = 0; nt < 4; nt++)
#pragma unroll
            for (int i = 0; i < 4; i++) acc[mt][nt][i] = 0.0f;

    auto load_stage = [&](int s, int k0) {
        uint32_t b = smem_base + (uint32_t)s * GSTG;
#pragma unroll
        for (int i = 0; i < 4; i++) {
            CP16(b + GA_OFF + dst[i], srcA[i] + k0);
            CP16(b + GB_OFF + dst[i], srcB[i] + k0);
        }
    };

    load_stage(0, 0);  CP_COMMIT;
    load_stage(1, 64); CP_COMMIT;

    const int NK = K / 64;  // 16
    int stg = 0;
    for (int i = 0; i < NK; i++) {
        if (i + 1 < NK) { CP_WAIT1; } else { CP_WAIT0; }
        __syncthreads();
        if (i + 2 < NK) {
            int ns = stg + 2; if (ns >= 3) ns -= 3;
            load_stage(ns, (i + 2) * 64);
            CP_COMMIT;
        }

        const uint32_t sb = smem_base + (uint32_t)stg * GSTG;
#pragma unroll
        for (int kk = 0; kk < 4; kk++) {
            // Hoist ALL fragment loads ahead of the MMA burst.
            uint32_t bh[4][2], ah[4][4];
#pragma unroll
            for (int p = 0; p < 2; p++)
                LDSM4(bh[2 * p][0], bh[2 * p][1], bh[2 * p + 1][0], bh[2 * p + 1][1],
                      sb + GB_OFF + boff[p][kk]);
#pragma unroll
            for (int mt = 0; mt < 4; mt++)
                LDSM4(ah[mt][0], ah[mt][1], ah[mt][2], ah[mt][3],
                      sb + GA_OFF + aoff[mt][kk]);
#pragma unroll
            for (int mt = 0; mt < 4; mt++)
#pragma unroll
                for (int nt = 0; nt < 4; nt++)
                    MMA16816(acc[mt][nt], ah[mt][0], ah[mt][1], ah[mt][2], ah[mt][3],
                             bh[nt][0], bh[nt][1]);
        }
        if (++stg >= 3) stg = 0;
    }

    const int rowBase = blockIdx.y * 128 + wm * 64;
    const int colBase = blockIdx.x * 128 + wn * 32;
#pragma unroll
    for (int mt = 0; mt < 4; mt++) {
        int row = rowBase + mt * 16 + (lane >> 2);
#pragma unroll
        for (int nt = 0; nt < 4; nt++) {
            int col = colBase + nt * 8 + (lane & 3) * 2;
            float2 bv = *(const float2*)&bias[col];
            float o00 = (acc[mt][nt][0] + bv.x) * oscale;
            float o01 = (acc[mt][nt][1] + bv.y) * oscale;
            float o10 = (acc[mt][nt][2] + bv.x) * oscale;
            float o11 = (acc[mt][nt][3] + bv.y) * oscale;
            if (OUT_MODE == 2) {
                *(uint32_t*)&Yh[(size_t)row * N + col]       = pack_h2(o00, o01);
                *(uint32_t*)&Yh[(size_t)(row + 8) * N + col] = pack_h2(o10, o11);
            } else {
                *(float2*)&Y[(size_t)row * N + col]       = make_float2(o00, o01);
                *(float2*)&Y[(size_t)(row + 8) * N + col] = make_float2(o10, o11);
            }
        }
    }
}

// ---------------------------------------------------------------------------
// fp16 flash attention: dynamic smem, 3-stage KV pipeline, ONE barrier/tile.
// 64 q-rows / 4 warps / 128 thr, 4 CTAs/SM.
// ---------------------------------------------------------------------------
#define AQ_BYTES 9216u          // 64x72 fp16 Q staging (start of buffer)
#define AKV_STG 18432u          // one KV stage: K 64x72 + V 64x72
#define AKV_VOFF 9216u
#define ASMEM (3u * AKV_STG)    // 55296
#define ONES_H2 0x3C003C00u

__global__ __launch_bounds__(128, 4) void attn_tc(
    const __half* __restrict__ Qh, const __half* __restrict__ Kh,
    const __half* __restrict__ Vh,
    const uint32_t* __restrict__ mbits, __half* __restrict__ Oh) {
    const int qt = blockIdx.x, h = blockIdx.y, b = blockIdx.z;
    const int tid = threadIdx.x, lane = tid & 31, warp = tid >> 5;

    extern __shared__ char smem_raw[];
    __half* smq = (__half*)smem_raw;
    const uint32_t smbase = (uint32_t)__cvta_generic_to_shared(smem_raw);

    const size_t qrow0 = (size_t)b * Ss + qt * 64;

    // ---- Stage Q tile into the front of the buffer, read fragments.
    {
        int r = tid >> 1, half = tid & 1;
        const uint4* gh = (const uint4*)(Qh + (qrow0 + r) * Dd + h * 64 + half * 32);
        uint4* sh = (uint4*)&smq[r * 72 + half * 32];
#pragma unroll
        for (int i = 0; i < 4; i++) sh[i] = gh[i];
    }
    __syncthreads();

    uint32_t qfh[4][4];
    {
        int r = warp * 16 + (lane & 15);
#pragma unroll
        for (int s = 0; s < 4; s++) {
            uint32_t off = (uint32_t)((r * 72 + s * 16 + (lane >> 4) * 8) * 2);
            LDSM4(qfh[s][0], qfh[s][1], qfh[s][2], qfh[s][3], smbase + off);
        }
    }
    __syncthreads();  // Q reads done; KV stages may now overwrite the buffer.

    const size_t kvrow0 = ((size_t)b * Ss) * Dd + h * 64;
    uint32_t ldst[4];
    size_t lsrc[4];
#pragma unroll
    for (int i = 0; i < 4; i++) {
        int idx = i * 128 + tid, r = idx >> 3, c = idx & 7;
        ldst[i] = (uint32_t)(r * 144 + c * 16);
        lsrc[i] = (size_t)r * Dd + c * 8;
    }
    auto load_kv = [&](int s, int kt) {
        uint32_t bb = smbase + (uint32_t)s * AKV_STG;
        size_t g = kvrow0 + (size_t)kt * 64 * Dd;
#pragma unroll
        for (int i = 0; i < 4; i++) {
            CP16(bb + ldst[i],            Kh + g + lsrc[i]);
            CP16(bb + AKV_VOFF + ldst[i], Vh + g + lsrc[i]);
        }
    };

    float oacc[8][4];
#pragma unroll
    for (int nt = 0; nt < 8; nt++)
#pragma unroll
        for (int i = 0; i < 4; i++) oacc[nt][i] = 0.0f;
    float lacc[4] = {0.f, 0.f, 0.f, 0.f};
    float m1 = -1e30f, m2 = -1e30f;

    const int rb = ((lane >> 4) << 3) + (lane & 7);
    const int cb = ((lane >> 3) & 1) * 8;
    const int r1 = lane >> 2;
    const int vrow = ((lane >> 3) & 1) * 8 + (lane & 7);
    const int vcol = (lane >> 4) * 8;
    const int lsh = (lane & 3) * 2;

    const uint32_t* mrow1 = mbits + (qrow0 + warp * 16 + r1) * 32;
    const uint32_t* mrow2 = mrow1 + 8 * 32;

    load_kv(0, 0); CP_COMMIT;
    load_kv(1, 1); CP_COMMIT;

    int stg = 0;
    for (int kt = 0; kt < 16; kt++) {
        if (kt + 1 < 16) { CP_WAIT1; } else { CP_WAIT0; }
        __syncthreads();
        if (kt + 2 < 16) {
            int ns = stg + 2; if (ns >= 3) ns -= 3;
            load_kv(ns, kt + 2);
            CP_COMMIT;
        }

        const uint32_t kb = smbase + (uint32_t)stg * AKV_STG;
        const uint32_t vb = kb + AKV_VOFF;

        // ---- S = Q K^T.
        float sacc[8][4];
#pragma unroll
        for (int nt = 0; nt < 8; nt++)
#pragma unroll
            for (int i = 0; i < 4; i++) sacc[nt][i] = 0.0f;
#pragma unroll
        for (int s = 0; s < 4; s++) {
            uint32_t bh[8][2];
#pragma unroll
            for (int p = 0; p < 4; p++) {
                uint32_t off = (uint32_t)(((p * 16 + rb) * 72 + s * 16 + cb) * 2);
                LDSM4(bh[2 * p][0], bh[2 * p][1], bh[2 * p + 1][0], bh[2 * p + 1][1], kb + off);
            }
#pragma unroll
            for (int nt = 0; nt < 8; nt++)
                MMA16816(sacc[nt], qfh[s][0], qfh[s][1], qfh[s][2], qfh[s][3], bh[nt][0], bh[nt][1]);
        }

        // ---- Mask, row max.
        uint32_t w10 = mrow1[kt * 2] >> lsh, w11 = mrow1[kt * 2 + 1] >> lsh;
        uint32_t w20 = mrow2[kt * 2] >> lsh, w21 = mrow2[kt * 2 + 1] >> lsh;
        float tm1 = -1e30f, tm2 = -1e30f;
#pragma unroll
        for (int nt = 0; nt < 8; nt++) {
            const int shf = (nt * 8) & 31;
            uint32_t wA = (nt < 4) ? w10 : w11;
            uint32_t wB = (nt < 4) ? w20 : w21;
            float s0 = sacc[nt][0], s1 = sacc[nt][1];
            float s2 = sacc[nt][2], s3 = sacc[nt][3];
            if (!((wA >> shf) & 1))       s0 = -1e9f;
            if (!((wA >> (shf + 1)) & 1)) s1 = -1e9f;
            if (!((wB >> shf) & 1))       s2 = -1e9f;
            if (!((wB >> (shf + 1)) & 1)) s3 = -1e9f;
            sacc[nt][0] = s0; sacc[nt][1] = s1; sacc[nt][2] = s2; sacc[nt][3] = s3;
            tm1 = fmaxf(tm1, fmaxf(s0, s1));
            tm2 = fmaxf(tm2, fmaxf(s2, s3));
        }
        tm1 = fmaxf(tm1, __shfl_xor_sync(0xffffffff, tm1, 1));
        tm1 = fmaxf(tm1, __shfl_xor_sync(0xffffffff, tm1, 2));
        tm2 = fmaxf(tm2, __shfl_xor_sync(0xffffffff, tm2, 1));
        tm2 = fmaxf(tm2, __shfl_xor_sync(0xffffffff, tm2, 2));

        float mn1 = fmaxf(m1, tm1), mn2 = fmaxf(m2, tm2);
        float a1 = exp2f(m1 - mn1), a2 = exp2f(m2 - mn2);
        m1 = mn1; m2 = mn2;
        lacc[0] *= a1; lacc[1] *= a1; lacc[2] *= a2; lacc[3] *= a2;
#pragma unroll
        for (int nt = 0; nt < 8; nt++) {
            oacc[nt][0] *= a1; oacc[nt][1] *= a1;
            oacc[nt][2] *= a2; oacc[nt][3] *= a2;
        }

        // ---- p = h2exp2(s - m).
        uint32_t pah[4][4];
#pragma unroll
        for (int nt = 0; nt < 8; nt++) {
            int s = nt >> 1, base = (nt & 1) * 2;
            pah[s][base]     = h2exp2_u(pack_h2(sacc[nt][0] - m1, sacc[nt][1] - m1));
            pah[s][base + 1] = h2exp2_u(pack_h2(sacc[nt][2] - m2, sacc[nt][3] - m2));
        }

        // ---- l += P . ones.
#pragma unroll
        for (int s = 0; s < 4; s++)
            MMA16816(lacc, pah[s][0], pah[s][1], pah[s][2], pah[s][3], ONES_H2, ONES_H2);

        // ---- O += P V (trans ldmatrix).
#pragma unroll
        for (int s = 0; s < 4; s++) {
            uint32_t bt[8][2];
#pragma unroll
            for (int p = 0; p < 4; p++) {
                uint32_t off = (uint32_t)(((s * 16 + vrow) * 72 + p * 16 + vcol) * 2);
                LDSM4T(bt[2 * p][0], bt[2 * p][1], bt[2 * p + 1][0], bt[2 * p + 1][1], vb + off);
            }
#pragma unroll
            for (int dt = 0; dt < 8; dt++)
                MMA16816(oacc[dt], pah[s][0], pah[s][1], pah[s][2], pah[s][3], bt[dt][0], bt[dt][1]);
        }
        if (++stg >= 3) stg = 0;
    }

    float inv1 = 1.0f / lacc[0], inv2 = 1.0f / lacc[2];

    size_t row1 = qrow0 + warp * 16 + r1;
#pragma unroll
    for (int nt = 0; nt < 8; nt++) {
        int col = h * 64 + nt * 8 + (lane & 3) * 2;
        *(uint32_t*)&Oh[row1 * Dd + col] =
            pack_h2(oacc[nt][0] * inv1, oacc[nt][1] * inv1);
        *(uint32_t*)&Oh[(row1 + 8) * Dd + col] =
            pack_h2(oacc[nt][2] * inv2, oacc[nt][3] * inv2);
    }
}

// ---------------------------------------------------------------------------
extern "C" void kernel_launch(void* const* d_in, const int* in_sizes, int n_in,
                              void* d_out, int out_size) {
    (void)in_sizes; (void)n_in; (void)out_size;

    const float* q    = (const float*)d_in[0];
    const float* k    = (const float*)d_in[1];
    const float* v    = (const float*)d_in[2];
    const int*   mask = (const int*)d_in[3];
    const float* WQw  = (const float*)d_in[4];
    const float* WQb  = (const float*)d_in[5];
    const float* WKw  = (const float*)d_in[6];
    const float* WKb  = (const float*)d_in[7];
    const float* WVw  = (const float*)d_in[8];
    const float* WVb  = (const float*)d_in[9];
    const float* WOw  = (const float*)d_in[10];
    const float* WOb  = (const float*)d_in[11];
    float* out = (float*)d_out;

    __half *qh, *kh, *vh, *Qh, *Kh, *Vh, *AOh;
    __half *WQh, *WKh, *WVh, *WOh;
    uint32_t* Mb;
    cudaGetSymbolAddress((void**)&qh, g_qh);
    cudaGetSymbolAddress((void**)&kh, g_kh);
    cudaGetSymbolAddress((void**)&vh, g_vh);
    cudaGetSymbolAddress((void**)&Qh, g_Qh);
    cudaGetSymbolAddress((void**)&Kh, g_Kh);
    cudaGetSymbolAddress((void**)&Vh, g_Vh);
    cudaGetSymbolAddress((void**)&AOh, g_AOh);
    cudaGetSymbolAddress((void**)&WQh, g_WQh);
    cudaGetSymbolAddress((void**)&WKh, g_WKh);
    cudaGetSymbolAddress((void**)&WVh, g_WVh);
    cudaGetSymbolAddress((void**)&WOh, g_WOh);
    cudaGetSymbolAddress((void**)&Mb, g_mbits);

    cudaFuncSetAttribute((const void*)gemm_sp<0, 0>,
                         cudaFuncAttributeMaxDynamicSharedMemorySize, GSMEM);
    cudaFuncSetAttribute((const void*)gemm_sp<2, 1>,
                         cudaFuncAttributeMaxDynamicSharedMemorySize, GSMEM);
    cudaFuncSetAttribute((const void*)attn_tc,
                         cudaFuncAttributeMaxDynamicSharedMemorySize, ASMEM);

    prep_all<<<dim3(8192, 8), 256>>>(q, k, v, WQw, WKw, WVw, WOw, mask,
                                     qh, kh, vh, WQh, WKh, WVh, WOh, Mb);

    const float QSCALE = 0.125f * 1.44269504f;  // 1/sqrt(64) * log2(e)
    dim3 gqkv(Dd / 128, (Bb * Ss) / 128, 3);  // (8, 64, 3)
    gemm_sp<2, 1><<<gqkv, 256, GSMEM>>>(qh, kh, vh, WQh, WKh, WVh,
                                        WQb, WKb, WVb, nullptr,
                                        Qh, Kh, Vh, QSCALE);

    attn_tc<<<dim3(Ss / 64, Hh, Bb), 128, ASMEM>>>(Qh, Kh, Vh, Mb, AOh);

    dim3 gg(Dd / 128, (Bb * Ss) / 128);
    gemm_sp<0, 0><<<gg, 256, GSMEM>>>(AOh, nullptr, nullptr, WOh, nullptr, nullptr,
                                      WOb, nullptr, nullptr, out,
                                      nullptr, nullptr, nullptr, 1.0f);
}

// round 17
// speedup vs baseline: 9.1075x; 1.0416x over previous
#include <cuda_runtime.h>
#include <cuda_fp16.h>
#include <math.h>
#include <cstdint>

#define Bb 8
#define Ss 1024
#define Dd 1024
#define Hh 16
#define DKk 64

// ---- Scratch: everything single-plane fp16 ----
__device__ __half g_qh[(size_t)Bb * Ss * Dd];
__device__ __half g_kh[(size_t)Bb * Ss * Dd];
__device__ __half g_vh[(size_t)Bb * Ss * Dd];
__device__ __half g_Qh[(size_t)Bb * Ss * Dd];   // pre-scaled by 0.125*log2(e)
__device__ __half g_Kh[(size_t)Bb * Ss * Dd];
__device__ __half g_Vh[(size_t)Bb * Ss * Dd];
__device__ __half g_AOh[(size_t)Bb * Ss * Dd];
__device__ __half g_WQh[Dd * Dd], g_WKh[Dd * Dd], g_WVh[Dd * Dd], g_WOh[Dd * Dd];
__device__ uint32_t g_mbits[(size_t)Bb * Ss * (Ss / 32)];

#define LDSM4(r0, r1, r2, r3, addr)                                          \
    asm volatile("ldmatrix.sync.aligned.m8n8.x4.shared.b16 {%0,%1,%2,%3}, [%4];" \
                 : "=r"(r0), "=r"(r1), "=r"(r2), "=r"(r3) : "r"(addr))

#define LDSM4T(r0, r1, r2, r3, addr)                                         \
    asm volatile("ldmatrix.sync.aligned.m8n8.x4.trans.shared.b16 {%0,%1,%2,%3}, [%4];" \
                 : "=r"(r0), "=r"(r1), "=r"(r2), "=r"(r3) : "r"(addr))

#define MMA16816(d, a0, a1, a2, a3, b0, b1)                                  \
    asm volatile(                                                            \
        "mma.sync.aligned.m16n8k16.row.col.f32.f16.f16.f32 "                 \
        "{%0,%1,%2,%3}, {%4,%5,%6,%7}, {%8,%9}, {%0,%1,%2,%3};"              \
        : "+f"(d[0]), "+f"(d[1]), "+f"(d[2]), "+f"(d[3])                     \
        : "r"(a0), "r"(a1), "r"(a2), "r"(a3), "r"(b0), "r"(b1))

#define CP16(dst, src)                                                       \
    asm volatile("cp.async.cg.shared.global [%0], [%1], 16;" ::"r"(dst), "l"(src))
#define CP_COMMIT asm volatile("cp.async.commit_group;")
#define CP_WAIT1  asm volatile("cp.async.wait_group 1;")
#define CP_WAIT0  asm volatile("cp.async.wait_group 0;")

__device__ __forceinline__ uint32_t pack_h2(float a, float b) {
    __half2 t = __floats2half2_rn(a, b);
    return *(uint32_t*)&t;
}
__device__ __forceinline__ uint32_t h2exp2_u(uint32_t x) {
    __half2 v = *(__half2*)&x;
    __half2 r = h2exp2(v);
    return *(uint32_t*)&r;
}

// ---------------------------------------------------------------------------
// Fused prep, MLP=2 per thread: token quant (y=0..2), weight quant (y=3..6),
// mask pack (y=7). grid = (4096, 8).
// ---------------------------------------------------------------------------
__global__ void prep_all(const float* __restrict__ q, const float* __restrict__ k,
                         const float* __restrict__ v,
                         const float* __restrict__ wq, const float* __restrict__ wk,
                         const float* __restrict__ wv, const float* __restrict__ wo,
                         const int* __restrict__ mask,
                         __half* __restrict__ qh, __half* __restrict__ kh,
                         __half* __restrict__ vh,
                         __half* __restrict__ wqh, __half* __restrict__ wkh,
                         __half* __restrict__ wvh, __half* __restrict__ woh,
                         uint32_t* __restrict__ bits) {
    const int y = blockIdx.y;
    if (y < 3) {
        const float* src = (y == 0) ? q : (y == 1) ? k : v;
        __half* dst      = (y == 0) ? qh : (y == 1) ? kh : vh;
        size_t i = ((size_t)blockIdx.x * 256 + threadIdx.x) * 4;
        const size_t stride = (size_t)4096 * 256 * 4;  // second chain offset
        float4 t0 = *(const float4*)(src + i);
        float4 t1 = *(const float4*)(src + i + stride);
        *(uint2*)(dst + i)          = make_uint2(pack_h2(t0.x, t0.y), pack_h2(t0.z, t0.w));
        *(uint2*)(dst + i + stride) = make_uint2(pack_h2(t1.x, t1.y), pack_h2(t1.z, t1.w));
    } else if (y < 7) {
        if (blockIdx.x >= 512) return;
        const float* src = (y == 3) ? wq : (y == 4) ? wk : (y == 5) ? wv : wo;
        __half* dst      = (y == 3) ? wqh : (y == 4) ? wkh : (y == 5) ? wvh : woh;
        size_t i = ((size_t)blockIdx.x * 256 + threadIdx.x) * 4;
        const size_t stride = (size_t)512 * 256 * 4;
        float4 t0 = *(const float4*)(src + i);
        float4 t1 = *(const float4*)(src + i + stride);
        *(uint2*)(dst + i)          = make_uint2(pack_h2(t0.x, t0.y), pack_h2(t0.z, t0.w));
        *(uint2*)(dst + i + stride) = make_uint2(pack_h2(t1.x, t1.y), pack_h2(t1.z, t1.w));
    } else {
        if (blockIdx.x >= 1024) return;
        size_t w = (size_t)blockIdx.x * 256 + threadIdx.x;
        const int* p = mask + w * 32;
        uint32_t val = 0;
#pragma unroll
        for (int i = 0; i < 32; i += 4) {
            int4 t = *(const int4*)(p + i);
            val |= (uint32_t)(t.x != 0) << i;
            val |= (uint32_t)(t.y != 0) << (i + 1);
            val |= (uint32_t)(t.z != 0) << (i + 2);
            val |= (uint32_t)(t.w != 0) << (i + 3);
        }
        bits[w] = val;
    }
}

// ---------------------------------------------------------------------------
// fp16 GEMM, BK=64, 3-stage cp.async, warp tile 64x32 (2x4), 2 CTAs/SM.
// ---------------------------------------------------------------------------
#define GSTG 36864u
#define GA_OFF 0u
#define GB_OFF 18432u
#define GSMEM (3u * GSTG)  // 110592

template <int OUT_MODE, int QKV_FUSED>
__global__ __launch_bounds__(256, 2) void gemm_sp(
    const __half* __restrict__ A0, const __half* __restrict__ A1,
    const __half* __restrict__ A2,
    const __half* __restrict__ B0, const __half* __restrict__ B1,
    const __half* __restrict__ B2,
    const float* __restrict__ bias0, const float* __restrict__ bias1,
    const float* __restrict__ bias2,
    float* __restrict__ Y,
    __half* __restrict__ Yh0, __half* __restrict__ Yh1, __half* __restrict__ Yh2,
    float scale0) {
    const int K = 1024, N = 1024;
    extern __shared__ char smem_raw[];
    const uint32_t smem_base = (uint32_t)__cvta_generic_to_shared(smem_raw);

    const int z = QKV_FUSED ? blockIdx.z : 0;
    const __half* Ahg = (z == 0) ? A0 : (z == 1) ? A1 : A2;
    const __half* Bhg = (z == 0) ? B0 : (z == 1) ? B1 : B2;
    const float* bias = (z == 0) ? bias0 : (z == 1) ? bias1 : bias2;
    __half* Yh        = (z == 0) ? Yh0 : (z == 1) ? Yh1 : Yh2;
    const float oscale = (QKV_FUSED && z != 0) ? 1.0f : scale0;

    const int tid  = threadIdx.x;
    const int lane = tid & 31;
    const int warp = tid >> 5;
    const int wm   = warp >> 2;
    const int wn   = warp & 3;

    const __half* srcA[4];
    const __half* srcB[4];
    uint32_t dst[4];
#pragma unroll
    for (int i = 0; i < 4; i++) {
        int idx = i * 256 + tid, r = idx >> 3, c = idx & 7;
        srcA[i] = Ahg + (size_t)(blockIdx.y * 128 + r) * K + c * 8;
        srcB[i] = Bhg + (size_t)(blockIdx.x * 128 + r) * K + c * 8;
        dst[i]  = (uint32_t)(r * 144 + c * 16);
    }

    const int rb = ((lane >> 4) << 3) + (lane & 7);
    const int cb = ((lane >> 3) & 1) * 8;
    uint32_t aoff[4][4], boff[2][4];
#pragma unroll
    for (int mt = 0; mt < 4; mt++)
#pragma unroll
        for (int kk = 0; kk < 4; kk++)
            aoff[mt][kk] = (uint32_t)((wm * 64 + mt * 16 + (lane & 15)) * 144 +
                                      (lane >> 4) * 16 + kk * 32);
#pragma unroll
    for (int p = 0; p < 2; p++)
#pragma unroll
        for (int kk = 0; kk < 4; kk++)
            boff[p][kk] = (uint32_t)((wn * 32 + p * 16 + rb) * 144 + cb * 2 + kk * 32);

    float acc[4][4][4];
#pragma unroll
    for (int mt = 0; mt < 4; mt++)
#pragma unroll
        for (int nt = 0; nt < 4; nt++)
#pragma unroll
            for (int i = 0; i < 4; i++) acc[mt][nt][i] = 0.0f;

    auto load_stage = [&](int s, int k0) {
        uint32_t b = smem_base + (uint32_t)s * GSTG;
#pragma unroll
        for (int i = 0; i < 4; i++) {
            CP16(b + GA_OFF + dst[i], srcA[i] + k0);
            CP16(b + GB_OFF + dst[i], srcB[i] + k0);
        }
    };

    load_stage(0, 0);  CP_COMMIT;
    load_stage(1, 64); CP_COMMIT;

    const int NK = K / 64;  // 16
    int stg = 0;
    for (int i = 0; i < NK; i++) {
        if (i + 1 < NK) { CP_WAIT1; } else { CP_WAIT0; }
        __syncthreads();
        if (i + 2 < NK) {
            int ns = stg + 2; if (ns >= 3) ns -= 3;
            load_stage(ns, (i + 2) * 64);
            CP_COMMIT;
        }

        const uint32_t sb = smem_base + (uint32_t)stg * GSTG;
#pragma unroll
        for (int kk = 0; kk < 4; kk++) {
            uint32_t bh[4][2], ah[4][4];
#pragma unroll
            for (int p = 0; p < 2; p++)
                LDSM4(bh[2 * p][0], bh[2 * p][1], bh[2 * p + 1][0], bh[2 * p + 1][1],
                      sb + GB_OFF + boff[p][kk]);
#pragma unroll
            for (int mt = 0; mt < 4; mt++)
                LDSM4(ah[mt][0], ah[mt][1], ah[mt][2], ah[mt][3],
                      sb + GA_OFF + aoff[mt][kk]);
#pragma unroll
            for (int mt = 0; mt < 4; mt++)
#pragma unroll
                for (int nt = 0; nt < 4; nt++)
                    MMA16816(acc[mt][nt], ah[mt][0], ah[mt][1], ah[mt][2], ah[mt][3],
                             bh[nt][0], bh[nt][1]);
        }
        if (++stg >= 3) stg = 0;
    }

    const int rowBase = blockIdx.y * 128 + wm * 64;
    const int colBase = blockIdx.x * 128 + wn * 32;
#pragma unroll
    for (int mt = 0; mt < 4; mt++) {
        int row = rowBase + mt * 16 + (lane >> 2);
#pragma unroll
        for (int nt = 0; nt < 4; nt++) {
            int col = colBase + nt * 8 + (lane & 3) * 2;
            float2 bv = *(const float2*)&bias[col];
            float o00 = (acc[mt][nt][0] + bv.x) * oscale;
            float o01 = (acc[mt][nt][1] + bv.y) * oscale;
            float o10 = (acc[mt][nt][2] + bv.x) * oscale;
            float o11 = (acc[mt][nt][3] + bv.y) * oscale;
            if (OUT_MODE == 2) {
                *(uint32_t*)&Yh[(size_t)row * N + col]       = pack_h2(o00, o01);
                *(uint32_t*)&Yh[(size_t)(row + 8) * N + col] = pack_h2(o10, o11);
            } else {
                *(float2*)&Y[(size_t)row * N + col]       = make_float2(o00, o01);
                *(float2*)&Y[(size_t)(row + 8) * N + col] = make_float2(o10, o11);
            }
        }
    }
}

// ---------------------------------------------------------------------------
// fp16 flash attention: dynamic smem, 3-stage KV pipeline, one barrier/tile.
// Mask LDGs hoisted ahead of the QK^T MMA burst (latency overlap).
// ---------------------------------------------------------------------------
#define AKV_STG 18432u
#define AKV_VOFF 9216u
#define ASMEM (3u * AKV_STG)  // 55296
#define ONES_H2 0x3C003C00u

__global__ __launch_bounds__(128, 4) void attn_tc(
    const __half* __restrict__ Qh, const __half* __restrict__ Kh,
    const __half* __restrict__ Vh,
    const uint32_t* __restrict__ mbits, __half* __restrict__ Oh) {
    const int qt = blockIdx.x, h = blockIdx.y, b = blockIdx.z;
    const int tid = threadIdx.x, lane = tid & 31, warp = tid >> 5;

    extern __shared__ char smem_raw[];
    __half* smq = (__half*)smem_raw;
    const uint32_t smbase = (uint32_t)__cvta_generic_to_shared(smem_raw);

    const size_t qrow0 = (size_t)b * Ss + qt * 64;

    {
        int r = tid >> 1, half = tid & 1;
        const uint4* gh = (const uint4*)(Qh + (qrow0 + r) * Dd + h * 64 + half * 32);
        uint4* sh = (uint4*)&smq[r * 72 + half * 32];
#pragma unroll
        for (int i = 0; i < 4; i++) sh[i] = gh[i];
    }
    __syncthreads();

    uint32_t qfh[4][4];
    {
        int r = warp * 16 + (lane & 15);
#pragma unroll
        for (int s = 0; s < 4; s++) {
            uint32_t off = (uint32_t)((r * 72 + s * 16 + (lane >> 4) * 8) * 2);
            LDSM4(qfh[s][0], qfh[s][1], qfh[s][2], qfh[s][3], smbase + off);
        }
    }
    __syncthreads();

    const size_t kvrow0 = ((size_t)b * Ss) * Dd + h * 64;
    uint32_t ldst[4];
    size_t lsrc[4];
#pragma unroll
    for (int i = 0; i < 4; i++) {
        int idx = i * 128 + tid, r = idx >> 3, c = idx & 7;
        ldst[i] = (uint32_t)(r * 144 + c * 16);
        lsrc[i] = (size_t)r * Dd + c * 8;
    }
    auto load_kv = [&](int s, int kt) {
        uint32_t bb = smbase + (uint32_t)s * AKV_STG;
        size_t g = kvrow0 + (size_t)kt * 64 * Dd;
#pragma unroll
        for (int i = 0; i < 4; i++) {
            CP16(bb + ldst[i],            Kh + g + lsrc[i]);
            CP16(bb + AKV_VOFF + ldst[i], Vh + g + lsrc[i]);
        }
    };

    float oacc[8][4];
#pragma unroll
    for (int nt = 0; nt < 8; nt++)
#pragma unroll
        for (int i = 0; i < 4; i++) oacc[nt][i] = 0.0f;
    float lacc[4] = {0.f, 0.f, 0.f, 0.f};
    float m1 = -1e30f, m2 = -1e30f;

    const int rb = ((lane >> 4) << 3) + (lane & 7);
    const int cb = ((lane >> 3) & 1) * 8;
    const int r1 = lane >> 2;
    const int vrow = ((lane >> 3) & 1) * 8 + (lane & 7);
    const int vcol = (lane >> 4) * 8;
    const int lsh = (lane & 3) * 2;

    const uint32_t* mrow1 = mbits + (qrow0 + warp * 16 + r1) * 32;
    const uint32_t* mrow2 = mrow1 + 8 * 32;

    load_kv(0, 0); CP_COMMIT;
    load_kv(1, 1); CP_COMMIT;

    int stg = 0;
    for (int kt = 0; kt < 16; kt++) {
        if (kt + 1 < 16) { CP_WAIT1; } else { CP_WAIT0; }
        __syncthreads();
        if (kt + 2 < 16) {
            int ns = stg + 2; if (ns >= 3) ns -= 3;
            load_kv(ns, kt + 2);
            CP_COMMIT;
        }

        // ---- Hoisted mask loads: overlap L2 latency with the QK MMA burst.
        uint32_t w10 = mrow1[kt * 2], w11 = mrow1[kt * 2 + 1];
        uint32_t w20 = mrow2[kt * 2], w21 = mrow2[kt * 2 + 1];

        const uint32_t kb = smbase + (uint32_t)stg * AKV_STG;
        const uint32_t vb = kb + AKV_VOFF;

        // ---- S = Q K^T.
        float sacc[8][4];
#pragma unroll
        for (int nt = 0; nt < 8; nt++)
#pragma unroll
            for (int i = 0; i < 4; i++) sacc[nt][i] = 0.0f;
#pragma unroll
        for (int s = 0; s < 4; s++) {
            uint32_t bh[8][2];
#pragma unroll
            for (int p = 0; p < 4; p++) {
                uint32_t off = (uint32_t)(((p * 16 + rb) * 72 + s * 16 + cb) * 2);
                LDSM4(bh[2 * p][0], bh[2 * p][1], bh[2 * p + 1][0], bh[2 * p + 1][1], kb + off);
            }
#pragma unroll
            for (int nt = 0; nt < 8; nt++)
                MMA16816(sacc[nt], qfh[s][0], qfh[s][1], qfh[s][2], qfh[s][3], bh[nt][0], bh[nt][1]);
        }

        // ---- Mask (pre-shifted), row max.
        w10 >>= lsh; w11 >>= lsh; w20 >>= lsh; w21 >>= lsh;
        float tm1 = -1e30f, tm2 = -1e30f;
#pragma unroll
        for (int nt = 0; nt < 8; nt++) {
            const int shf = (nt * 8) & 31;
            uint32_t wA = (nt < 4) ? w10 : w11;
            uint32_t wB = (nt < 4) ? w20 : w21;
            float s0 = sacc[nt][0], s1 = sacc[nt][1];
            float s2 = sacc[nt][2], s3 = sacc[nt][3];
            if (!((wA >> shf) & 1))       s0 = -1e9f;
            if (!((wA >> (shf + 1)) & 1)) s1 = -1e9f;
            if (!((wB >> shf) & 1))       s2 = -1e9f;
            if (!((wB >> (shf + 1)) & 1)) s3 = -1e9f;
            sacc[nt][0] = s0; sacc[nt][1] = s1; sacc[nt][2] = s2; sacc[nt][3] = s3;
            tm1 = fmaxf(tm1, fmaxf(s0, s1));
            tm2 = fmaxf(tm2, fmaxf(s2, s3));
        }
        tm1 = fmaxf(tm1, __shfl_xor_sync(0xffffffff, tm1, 1));
        tm1 = fmaxf(tm1, __shfl_xor_sync(0xffffffff, tm1, 2));
        tm2 = fmaxf(tm2, __shfl_xor_sync(0xffffffff, tm2, 1));
        tm2 = fmaxf(tm2, __shfl_xor_sync(0xffffffff, tm2, 2));

        float mn1 = fmaxf(m1, tm1), mn2 = fmaxf(m2, tm2);
        float a1 = exp2f(m1 - mn1), a2 = exp2f(m2 - mn2);
        m1 = mn1; m2 = mn2;
        lacc[0] *= a1; lacc[1] *= a1; lacc[2] *= a2; lacc[3] *= a2;
#pragma unroll
        for (int nt = 0; nt < 8; nt++) {
            oacc[nt][0] *= a1; oacc[nt][1] *= a1;
            oacc[nt][2] *= a2; oacc[nt][3] *= a2;
        }

        uint32_t pah[4][4];
#pragma unroll
        for (int nt = 0; nt < 8; nt++) {
            int s = nt >> 1, base = (nt & 1) * 2;
            pah[s][base]     = h2exp2_u(pack_h2(sacc[nt][0] - m1, sacc[nt][1] - m1));
            pah[s][base + 1] = h2exp2_u(pack_h2(sacc[nt][2] - m2, sacc[nt][3] - m2));
        }

#pragma unroll
        for (int s = 0; s < 4; s++)
            MMA16816(lacc, pah[s][0], pah[s][1], pah[s][2], pah[s][3], ONES_H2, ONES_H2);

#pragma unroll
        for (int s = 0; s < 4; s++) {
            uint32_t bt[8][2];
#pragma unroll
            for (int p = 0; p < 4; p++) {
                uint32_t off = (uint32_t)(((s * 16 + vrow) * 72 + p * 16 + vcol) * 2);
                LDSM4T(bt[2 * p][0], bt[2 * p][1], bt[2 * p + 1][0], bt[2 * p + 1][1], vb + off);
            }
#pragma unroll
            for (int dt = 0; dt < 8; dt++)
                MMA16816(oacc[dt], pah[s][0], pah[s][1], pah[s][2], pah[s][3], bt[dt][0], bt[dt][1]);
        }
        if (++stg >= 3) stg = 0;
    }

    float inv1 = 1.0f / lacc[0], inv2 = 1.0f / lacc[2];

    size_t row1 = qrow0 + warp * 16 + r1;
#pragma unroll
    for (int nt = 0; nt < 8; nt++) {
        int col = h * 64 + nt * 8 + (lane & 3) * 2;
        *(uint32_t*)&Oh[row1 * Dd + col] =
            pack_h2(oacc[nt][0] * inv1, oacc[nt][1] * inv1);
        *(uint32_t*)&Oh[(row1 + 8) * Dd + col] =
            pack_h2(oacc[nt][2] * inv2, oacc[nt][3] * inv2);
    }
}

// ---------------------------------------------------------------------------
extern "C" void kernel_launch(void* const* d_in, const int* in_sizes, int n_in,
                              void* d_out, int out_size) {
    (void)in_sizes; (void)n_in; (void)out_size;

    const float* q    = (const float*)d_in[0];
    const float* k    = (const float*)d_in[1];
    const float* v    = (const float*)d_in[2];
    const int*   mask = (const int*)d_in[3];
    const float* WQw  = (const float*)d_in[4];
    const float* WQb  = (const float*)d_in[5];
    const float* WKw  = (const float*)d_in[6];
    const float* WKb  = (const float*)d_in[7];
    const float* WVw  = (const float*)d_in[8];
    const float* WVb  = (const float*)d_in[9];
    const float* WOw  = (const float*)d_in[10];
    const float* WOb  = (const float*)d_in[11];
    float* out = (float*)d_out;

    __half *qh, *kh, *vh, *Qh, *Kh, *Vh, *AOh;
    __half *WQh, *WKh, *WVh, *WOh;
    uint32_t* Mb;
    cudaGetSymbolAddress((void**)&qh, g_qh);
    cudaGetSymbolAddress((void**)&kh, g_kh);
    cudaGetSymbolAddress((void**)&vh, g_vh);
    cudaGetSymbolAddress((void**)&Qh, g_Qh);
    cudaGetSymbolAddress((void**)&Kh, g_Kh);
    cudaGetSymbolAddress((void**)&Vh, g_Vh);
    cudaGetSymbolAddress((void**)&AOh, g_AOh);
    cudaGetSymbolAddress((void**)&WQh, g_WQh);
    cudaGetSymbolAddress((void**)&WKh, g_WKh);
    cudaGetSymbolAddress((void**)&WVh, g_WVh);
    cudaGetSymbolAddress((void**)&WOh, g_WOh);
    cudaGetSymbolAddress((void**)&Mb, g_mbits);

    cudaFuncSetAttribute((const void*)gemm_sp<0, 0>,
                         cudaFuncAttributeMaxDynamicSharedMemorySize, GSMEM);
    cudaFuncSetAttribute((const void*)gemm_sp<2, 1>,
                         cudaFuncAttributeMaxDynamicSharedMemorySize, GSMEM);
    cudaFuncSetAttribute((const void*)attn_tc,
                         cudaFuncAttributeMaxDynamicSharedMemorySize, ASMEM);

    prep_all<<<dim3(4096, 8), 256>>>(q, k, v, WQw, WKw, WVw, WOw, mask,
                                     qh, kh, vh, WQh, WKh, WVh, WOh, Mb);

    const float QSCALE = 0.125f * 1.44269504f;  // 1/sqrt(64) * log2(e)
    dim3 gqkv(Dd / 128, (Bb * Ss) / 128, 3);  // (8, 64, 3)
    gemm_sp<2, 1><<<gqkv, 256, GSMEM>>>(qh, kh, vh, WQh, WKh, WVh,
                                        WQb, WKb, WVb, nullptr,
                                        Qh, Kh, Vh, QSCALE);

    attn_tc<<<dim3(Ss / 64, Hh, Bb), 128, ASMEM>>>(Qh, Kh, Vh, Mb, AOh);

    dim3 gg(Dd / 128, (Bb * Ss) / 128);
    gemm_sp<0, 0><<<gg, 256, GSMEM>>>(AOh, nullptr, nullptr, WOh, nullptr, nullptr,
                                      WOb, nullptr, nullptr, out,
                                      nullptr, nullptr, nullptr, 1.0f);
}